// round 9
// baseline (speedup 1.0000x reference)
#include <cuda_runtime.h>
#include <math.h>
#include <stdint.h>

typedef unsigned long long ull;

// ---------------- scratch (device globals; no allocations allowed) ----------------
__device__ float g_qT  [1024 * 256];      // [b*128+r][e]   e = h*16+d
__device__ float g_kTT [8 * 256 * 128];   // [b][e][c]
__device__ float g_v1  [1024 * 256];      // [b][h][s][d]
__device__ float g_v2  [1024 * 256];      // [b][h][s][d]
__device__ float g_ms1 [2097152];         // [b][h][r][c]
__device__ float g_ms2 [2097152];         // [b][h][r][c]
__device__ float g_attn1[1024 * 256];     // [b*128+r][h*16+d]
__device__ float g_attn2[1024 * 256];     // [b*128+c][h*16+d]
__device__ float g_part[1024 * 4];        // per-block {s1,q1,s2,q2}
__device__ float g_stats[2];              // inv_std1, inv_std2
// frag-packed split weights: per fragment+lane: {bhi0, bhi1, blo0, blo1}
__device__ float4 gW1p[256 * 32];         // frag = nf*4+ks  (nf 0..63, ks 0..3)
__device__ float4 gW2p[256 * 32];         // frag = ks*4+nf  (ks 0..63, nf 0..3)

// ---------------- helpers ----------------
__device__ __forceinline__ float fast_tanh(float x) {
    return 1.f - 2.f / (__expf(2.f * x) + 1.f);
}
__device__ __forceinline__ float tf32f(float x) {
    uint32_t u; asm("cvt.rna.tf32.f32 %0, %1;" : "=r"(u) : "f"(x));
    return __uint_as_float(u);
}
__device__ __forceinline__ void mma_tf32(float* c,
                                         uint32_t a0, uint32_t a1, uint32_t a2, uint32_t a3,
                                         uint32_t b0, uint32_t b1) {
    asm volatile(
        "mma.sync.aligned.m16n8k8.row.col.f32.tf32.tf32.f32 "
        "{%0,%1,%2,%3}, {%4,%5,%6,%7}, {%8,%9}, {%0,%1,%2,%3};"
        : "+f"(c[0]), "+f"(c[1]), "+f"(c[2]), "+f"(c[3])
        : "r"(a0), "r"(a1), "r"(a2), "r"(a3), "r"(b0), "r"(b1));
}

__global__ void k_nop() {}

// ---------------- K0: pack W1/W2 into per-fragment hi/lo float4s ----------------
__global__ void k_prep(const float* __restrict__ w1, const float* __restrict__ w2) {
    int idx = blockIdx.x * 256 + threadIdx.x;   // 0..16383
    if (idx >= 16384) return;
    int sel  = idx >> 13;
    int f    = idx & 8191;
    int lane = f & 31;
    int frag = f >> 5;            // 0..255
    int g = lane >> 2, tig = lane & 3;
    float b0, b1;
    if (sel == 0) {
        int nf = frag >> 2, ks = frag & 3;
        b0 = w1[(ks * 8 + tig) * 512 + nf * 8 + g];
        b1 = w1[(ks * 8 + tig + 4) * 512 + nf * 8 + g];
    } else {
        int ks = frag >> 2, nf = frag & 3;
        b0 = w2[(ks * 8 + tig) * 32 + nf * 8 + g];
        b1 = w2[(ks * 8 + tig + 4) * 32 + nf * 8 + g];
    }
    float h0 = tf32f(b0), h1 = tf32f(b1);
    float l0 = tf32f(b0 - h0), l1 = tf32f(b1 - h1);
    float4 v = make_float4(h0, h1, l0, l1);
    if (sel == 0) gW1p[frag * 32 + lane] = v;
    else          gW2p[frag * 32 + lane] = v;
}

// ---------------- K1: qkv projection GEMM ----------------
#define SM_QKV ((32 * 260 + 256 * 64) * 4)
__global__ void k_qkv(const float* __restrict__ x1, const float* __restrict__ x2,
                      const float* __restrict__ W) {
    extern __shared__ float smq[];
    float* sA = smq;             // 32 x 260 (padded)
    float* sB = smq + 32 * 260;  // 256 x 64
    const int m0 = blockIdx.x * 32, n0 = blockIdx.y * 64;
    const bool isX1 = (m0 < 1024);
    const float* src = isX1 ? x1 : x2;
    const int mm = m0 & 1023;
    const int b = mm >> 7, s0 = mm & 127;
    const int tid = threadIdx.x;

    for (int idx = tid; idx < 2048; idx += 256) {
        int row = idx >> 6, kk = (idx & 63) << 2;
        float4 v = *(const float4*)(src + (b * 128 + s0 + row) * 256 + kk);
        *(float4*)(sA + row * 260 + kk) = v;
    }
    for (int idx = tid; idx < 4096; idx += 256) {
        int row = idx >> 4, c4 = (idx & 15) << 2;
        float4 v = *(const float4*)(W + row * 512 + n0 + c4);
        *(float4*)(sB + row * 64 + c4) = v;
    }
    __syncthreads();

    const int r = tid >> 3, cg = tid & 7;
    float acc[8];
#pragma unroll
    for (int j = 0; j < 8; j++) acc[j] = 0.f;
    const float4* sB4 = (const float4*)sB;
#pragma unroll 4
    for (int k = 0; k < 256; k++) {
        float a = sA[r * 260 + k];
        float4 b0 = sB4[k * 16 + cg * 2];
        float4 b1 = sB4[k * 16 + cg * 2 + 1];
        acc[0] += a * b0.x; acc[1] += a * b0.y; acc[2] += a * b0.z; acc[3] += a * b0.w;
        acc[4] += a * b1.x; acc[5] += a * b1.y; acc[6] += a * b1.z; acc[7] += a * b1.w;
    }

    const int s = s0 + r;
#pragma unroll
    for (int j = 0; j < 8; j++) {
        int n = n0 + cg * 8 + j;
        float v = acc[j];
        if (n < 256) {
            if (isX1) g_qT[(b * 128 + s) * 256 + n] = v;
            else      g_kTT[(b * 256 + n) * 128 + s] = v;
        } else {
            int h = (n - 256) >> 4, d = n & 15;
            float* dst = isX1 ? g_v1 : g_v2;
            dst[((b * 16 + h) * 128 + s) * 16 + d] = v;
        }
    }
}

// ---------------- K3: tensor-core fused dot + MixedScoreFF MLP ----------------
// grid 1024 = (b,r). 256 threads = 8 warps, warp w owns rows (c) [16w,16w+16).
// Layer 1: full tf32x2 split (3 MMAs). Layer 2: main + W2-lo correction only
// (2 MMAs; H-lo rounding term dropped — expected final rel_err ~1e-4 vs 1e-3 tol).
// smem used 54272 B, PADDED to 81920 B -> 2 CTA/SM, ~64 KB L1D keeps the 32 KB
// active weight chunk L1-resident (validated in R8: DRAM 0.2%).
#define SM_MLP 81920
__global__ void __launch_bounds__(256, 2)
k_mlp(const float* __restrict__ cost) {
    extern __shared__ float smf[];
    float* sH = smf;                      // pitch 68
    float* sA = smf + 8704;               // pitch 36
    float* sq = smf + 8704 + 4608;

    const int blk = blockIdx.x;           // b*128 + r
    const int b = blk >> 7;
    const int tid = threadIdx.x;
    const int warp = tid >> 5, lane = tid & 31;
    const int g = lane >> 2, tig = lane & 3;

    // ---- phase 0: q row to smem; compute din; build A (fp32) ----
    sq[tid] = g_qT[(blk << 8) + tid];
    __syncthreads();

    {
        const int c = tid & 127, half = tid >> 7;   // half: h 0..7 vs 8..15
        float cv = cost[blk * 128 + c];
        const float* kb = g_kTT + b * 32768 + c;
#pragma unroll
        for (int hh = 0; hh < 8; hh++) {
            int h = half * 8 + hh;
            float a = 0.f;
#pragma unroll
            for (int d = 0; d < 16; d++)
                a += sq[h * 16 + d] * kb[(h * 16 + d) * 128];
            sA[c * 36 + 2 * h] = a * 0.25f;
            sA[c * 36 + 2 * h + 1] = cv;
        }
    }
    __syncthreads();

    // ---- load A fragments, split hi/lo in registers ----
    const int arow0 = warp * 16 + g, arow1 = arow0 + 8;
    uint32_t Ahi[4][4], Alo[4][4];
#pragma unroll
    for (int ks = 0; ks < 4; ks++) {
        float a0 = sA[arow0 * 36 + ks * 8 + tig];
        float a1 = sA[arow1 * 36 + ks * 8 + tig];
        float a2 = sA[arow0 * 36 + ks * 8 + tig + 4];
        float a3 = sA[arow1 * 36 + ks * 8 + tig + 4];
        float h0 = tf32f(a0), h1 = tf32f(a1), h2 = tf32f(a2), h3 = tf32f(a3);
        Ahi[ks][0] = __float_as_uint(h0); Alo[ks][0] = __float_as_uint(tf32f(a0 - h0));
        Ahi[ks][1] = __float_as_uint(h1); Alo[ks][1] = __float_as_uint(tf32f(a1 - h1));
        Ahi[ks][2] = __float_as_uint(h2); Alo[ks][2] = __float_as_uint(tf32f(a2 - h2));
        Ahi[ks][3] = __float_as_uint(h3); Alo[ks][3] = __float_as_uint(tf32f(a3 - h3));
    }

    float OUThh[4][4], OUTc[4][4];
#pragma unroll
    for (int i = 0; i < 4; i++)
#pragma unroll
        for (int j = 0; j < 4; j++) { OUThh[i][j] = 0.f; OUTc[i][j] = 0.f; }

    // per-chunk weight base pointers (unrolled offsets become immediates)
    const float4* w1c = gW1p + lane;
    const float4* w2c = gW2p + lane;

    // ---- 8 chunks of 64 hidden units ----
    for (int chunk = 0; chunk < 8; chunk++) {
        // layer 1: H[16x64]; 3 independent chains of depth 4
#pragma unroll
        for (int nfp = 0; nfp < 8; nfp++) {
            float hh[4] = {0.f, 0.f, 0.f, 0.f};
            float lh[4] = {0.f, 0.f, 0.f, 0.f};
            float hl[4] = {0.f, 0.f, 0.f, 0.f};
#pragma unroll
            for (int ks = 0; ks < 4; ks++) {
                float4 bw = w1c[(nfp * 4 + ks) << 5];
                uint32_t bh0 = __float_as_uint(bw.x), bh1 = __float_as_uint(bw.y);
                uint32_t bl0 = __float_as_uint(bw.z), bl1 = __float_as_uint(bw.w);
                mma_tf32(hh, Ahi[ks][0], Ahi[ks][1], Ahi[ks][2], Ahi[ks][3], bh0, bh1);
                mma_tf32(lh, Alo[ks][0], Alo[ks][1], Alo[ks][2], Alo[ks][3], bh0, bh1);
                mma_tf32(hl, Ahi[ks][0], Ahi[ks][1], Ahi[ks][2], Ahi[ks][3], bl0, bl1);
            }
            float h0 = fmaxf(hh[0] + lh[0] + hl[0], 0.f);
            float h1 = fmaxf(hh[1] + lh[1] + hl[1], 0.f);
            float h2 = fmaxf(hh[2] + lh[2] + hl[2], 0.f);
            float h3 = fmaxf(hh[3] + lh[3] + hl[3], 0.f);
            int col = nfp * 8 + 2 * tig;
            sH[arow0 * 68 + col]     = h0;
            sH[arow0 * 68 + col + 1] = h1;
            sH[arow1 * 68 + col]     = h2;
            sH[arow1 * 68 + col + 1] = h3;
        }
        __syncwarp();
        // layer 2: OUT[16x32] += H[16x64] @ W2[64x32]; H used as plain tf32 (hi)
        // plus the W2-lo correction (H-lo term dropped).
#pragma unroll
        for (int ksp = 0; ksp < 8; ksp++) {
            float f0 = sH[arow0 * 68 + ksp * 8 + tig];
            float f1 = sH[arow1 * 68 + ksp * 8 + tig];
            float f2 = sH[arow0 * 68 + ksp * 8 + tig + 4];
            float f3 = sH[arow1 * 68 + ksp * 8 + tig + 4];
            uint32_t ah0 = __float_as_uint(tf32f(f0)), ah1 = __float_as_uint(tf32f(f1));
            uint32_t ah2 = __float_as_uint(tf32f(f2)), ah3 = __float_as_uint(tf32f(f3));
#pragma unroll
            for (int nf = 0; nf < 4; nf++) {
                float4 bw = w2c[(ksp * 4 + nf) << 5];
                uint32_t bh0 = __float_as_uint(bw.x), bh1 = __float_as_uint(bw.y);
                uint32_t bl0 = __float_as_uint(bw.z), bl1 = __float_as_uint(bw.w);
                mma_tf32(OUThh[nf], ah0, ah1, ah2, ah3, bh0, bh1);
                mma_tf32(OUTc[nf],  ah0, ah1, ah2, ah3, bl0, bl1);
            }
        }
        __syncwarp();
        w1c += 1024;
        w2c += 1024;
    }

    // ---- write OUT to smem (reuse sH as [128][33]) then coalesced global write ----
    float* sO = sH;
    __syncthreads();   // everyone done with H before repurposing
#pragma unroll
    for (int nf = 0; nf < 4; nf++) {
        int col = nf * 8 + 2 * tig;
        sO[arow0 * 33 + col]     = OUThh[nf][0] + OUTc[nf][0];
        sO[arow0 * 33 + col + 1] = OUThh[nf][1] + OUTc[nf][1];
        sO[arow1 * 33 + col]     = OUThh[nf][2] + OUTc[nf][2];
        sO[arow1 * 33 + col + 1] = OUThh[nf][3] + OUTc[nf][3];
    }
    __syncthreads();

    const int r = blk & 127;
    float s1 = 0.f, q1 = 0.f, s2 = 0.f, q2 = 0.f;
    for (int i = tid; i < 2048; i += 256) {
        int h = i >> 7, cc = i & 127;
        float m1 = sO[cc * 33 + 2 * h];
        float m2 = sO[cc * 33 + 2 * h + 1];
        g_ms1[((b * 16 + h) * 128 + r) * 128 + cc] = m1;
        g_ms2[((b * 16 + h) * 128 + r) * 128 + cc] = m2;
        s1 += m1; q1 += m1 * m1; s2 += m2; q2 += m2 * m2;
    }

    float v[4] = {s1, q1, s2, q2};
#pragma unroll
    for (int i = 0; i < 4; i++)
        for (int off = 16; off; off >>= 1) v[i] += __shfl_xor_sync(0xffffffffu, v[i], off);
    __shared__ float red[4][8];
    if (lane == 0) { red[0][warp] = v[0]; red[1][warp] = v[1]; red[2][warp] = v[2]; red[3][warp] = v[3]; }
    __syncthreads();
    if (tid == 0) {
#pragma unroll
        for (int i = 0; i < 4; i++) {
            float s = 0.f;
#pragma unroll
            for (int j = 0; j < 8; j++) s += red[i][j];
            g_part[blk * 4 + i] = s;
        }
    }
}

// ---------------- K4: std reduction (ddof=1) ----------------
__global__ void k_std() {
    __shared__ double sh[4][128];
    const int tid = threadIdx.x;  // 128
    double a0 = 0, a1 = 0, a2 = 0, a3 = 0;
    for (int i = tid; i < 1024; i += 128) {
        const float* p = g_part + i * 4;
        a0 += p[0]; a1 += p[1]; a2 += p[2]; a3 += p[3];
    }
    sh[0][tid] = a0; sh[1][tid] = a1; sh[2][tid] = a2; sh[3][tid] = a3;
    __syncthreads();
    for (int o = 64; o; o >>= 1) {
        if (tid < o) {
#pragma unroll
            for (int i = 0; i < 4; i++) sh[i][tid] += sh[i][tid + o];
        }
        __syncthreads();
    }
    if (tid == 0) {
        const double N = 2097152.0;
        double v1 = (sh[1][0] - sh[0][0] * sh[0][0] / N) / (N - 1.0);
        double v2 = (sh[3][0] - sh[2][0] * sh[2][0] / N) / (N - 1.0);
        g_stats[0] = (float)(1.0 / sqrt(v1));
        g_stats[1] = (float)(1.0 / sqrt(v2));
    }
}

// ---------------- K5: merged attention (blocks 0..255 = h1 path, 256..511 = h2 path) ----------------
#define SM_ATT (14848 * 4)
__global__ void k_attn() {
    extern __shared__ float sm[];
    const int tid = threadIdx.x;     // 256

    if (blockIdx.x < 256) {
        // ---- h1: softmax over c ----
        float* sl = sm;            // [64 r][128 c]
        float* sv = sm + 8192;     // v2 plane [128 c][16 d]
        const int blk = blockIdx.x;
        const int p = blk >> 1, rh = blk & 1;
        const float inv = g_stats[0];
        const float* mp = g_ms1 + p * 16384 + rh * 8192;
        for (int idx = tid; idx < 8192; idx += 256) sl[idx] = 10.f * fast_tanh(mp[idx] * inv);
        const float* vp = g_v2 + p * 2048;
        for (int idx = tid; idx < 2048; idx += 256) sv[idx] = vp[idx];
        __syncthreads();

        const int w = tid >> 5, lane = tid & 31;
#pragma unroll
        for (int i = 0; i < 8; i++) {
            int r = w * 8 + i;
            float* row = sl + r * 128;
            float m = fmaxf(fmaxf(row[lane], row[lane + 32]), fmaxf(row[lane + 64], row[lane + 96]));
#pragma unroll
            for (int off = 16; off; off >>= 1) m = fmaxf(m, __shfl_xor_sync(0xffffffffu, m, off));
            float s = 0.f;
#pragma unroll
            for (int t = 0; t < 4; t++) {
                int cc = lane + t * 32;
                float e = __expf(row[cc] - m);
                row[cc] = e; s += e;
            }
#pragma unroll
            for (int off = 16; off; off >>= 1) s += __shfl_xor_sync(0xffffffffu, s, off);
            float is = 1.f / s;
#pragma unroll
            for (int t = 0; t < 4; t++) row[lane + t * 32] *= is;
        }
        __syncthreads();

        const int r = tid >> 2, d0 = (tid & 3) << 2;
        float a0 = 0.f, a1 = 0.f, a2 = 0.f, a3 = 0.f;
#pragma unroll 4
        for (int cc = 0; cc < 128; cc++) {
            float wgt = sl[r * 128 + cc];
            float4 v = *(const float4*)(sv + cc * 16 + d0);
            a0 += wgt * v.x; a1 += wgt * v.y; a2 += wgt * v.z; a3 += wgt * v.w;
        }
        const int b = p >> 4, h = p & 15;
        float* out = g_attn1 + (b * 128 + rh * 64 + r) * 256 + h * 16 + d0;
        *(float4*)out = make_float4(a0, a1, a2, a3);
    } else {
        // ---- h2: softmax over r, logits transposed ----
        float* sl   = sm;               // [128 r][64 c]
        float* sv   = sm + 8192;        // v1 plane [128 r][16 d]
        float* pr   = sm + 10240;       // [4 seg][64 c][16 d]
        float* redm = sm + 14336;       // [4 seg][64 c]
        float* reds = sm + 14592;       // [4 seg][64 c]
        const int blk = blockIdx.x - 256;
        const int p = blk >> 1, ch = blk & 1;
        const float inv = g_stats[1];
        const float* mp = g_ms2 + p * 16384 + ch * 64;
        for (int idx = tid; idx < 8192; idx += 256)
            sl[idx] = 10.f * fast_tanh(mp[(idx >> 6) * 128 + (idx & 63)] * inv);
        const float* vp = g_v1 + p * 2048;
        for (int idx = tid; idx < 2048; idx += 256) sv[idx] = vp[idx];
        __syncthreads();

        const int c = tid & 63, seg = tid >> 6;   // seg owns rows [seg*32, seg*32+32)
        float m = -1e30f;
#pragma unroll 4
        for (int i = 0; i < 32; i++) m = fmaxf(m, sl[(seg * 32 + i) * 64 + c]);
        redm[seg * 64 + c] = m;
        __syncthreads();
        m = fmaxf(fmaxf(redm[c], redm[64 + c]), fmaxf(redm[128 + c], redm[192 + c]));
        float s = 0.f;
#pragma unroll 4
        for (int i = 0; i < 32; i++) {
            int rr = seg * 32 + i;
            float e = __expf(sl[rr * 64 + c] - m);
            sl[rr * 64 + c] = e; s += e;
        }
        reds[seg * 64 + c] = s;

        float acc[16];
#pragma unroll
        for (int j = 0; j < 16; j++) acc[j] = 0.f;
#pragma unroll 2
        for (int i = 0; i < 32; i++) {
            int rr = seg * 32 + i;
            float wgt = sl[rr * 64 + c];
            const float4* v = (const float4*)(sv + rr * 16);
            float4 v0 = v[0], v1 = v[1], v2 = v[2], v3 = v[3];
            acc[0] += wgt * v0.x; acc[1] += wgt * v0.y; acc[2] += wgt * v0.z; acc[3] += wgt * v0.w;
            acc[4] += wgt * v1.x; acc[5] += wgt * v1.y; acc[6] += wgt * v1.z; acc[7] += wgt * v1.w;
            acc[8] += wgt * v2.x; acc[9] += wgt * v2.y; acc[10] += wgt * v2.z; acc[11] += wgt * v2.w;
            acc[12] += wgt * v3.x; acc[13] += wgt * v3.y; acc[14] += wgt * v3.z; acc[15] += wgt * v3.w;
        }
        float* prp = pr + (seg * 64 + c) * 16;
#pragma unroll
        for (int j = 0; j < 4; j++)
            *(float4*)(prp + j * 4) = make_float4(acc[j * 4], acc[j * 4 + 1], acc[j * 4 + 2], acc[j * 4 + 3]);
        __syncthreads();

        const int b = p >> 4, h = p & 15;
        for (int o = tid; o < 1024; o += 256) {
            int cc = o >> 4, d = o & 15;
            float v = pr[(cc) * 16 + d] + pr[(64 + cc) * 16 + d]
                    + pr[(128 + cc) * 16 + d] + pr[(192 + cc) * 16 + d];
            float stot = reds[cc] + reds[64 + cc] + reds[128 + cc] + reds[192 + cc];
            g_attn2[(b * 128 + ch * 64 + cc) * 256 + h * 16 + d] = v / stot;
        }
    }
}

// ---------------- K6: output projections ----------------
#define SM_OUT ((32 * 260 + 256 * 64) * 4)
__global__ void k_out(const float* __restrict__ o1w, const float* __restrict__ o2w,
                      float* __restrict__ out) {
    extern __shared__ float smo[];
    float* sA = smo;
    float* sB = smo + 32 * 260;
    const int m0 = blockIdx.x * 32, n0 = blockIdx.y * 64;
    const bool first = (m0 < 1024);
    const float* A = first ? g_attn1 : g_attn2;
    const float* W = first ? o1w : o2w;
    float* dst = out + (first ? 0 : 262144);
    const int mm = m0 & 1023;
    const int tid = threadIdx.x;

    for (int idx = tid; idx < 2048; idx += 256) {
        int row = idx >> 6, kk = (idx & 63) << 2;
        float4 v = *(const float4*)(A + (mm + row) * 256 + kk);
        *(float4*)(sA + row * 260 + kk) = v;
    }
    for (int idx = tid; idx < 4096; idx += 256) {
        int row = idx >> 4, c4 = (idx & 15) << 2;
        float4 v = *(const float4*)(W + row * 256 + n0 + c4);
        *(float4*)(sB + row * 64 + c4) = v;
    }
    __syncthreads();

    const int r = tid >> 3, cg = tid & 7;
    float acc[8];
#pragma unroll
    for (int j = 0; j < 8; j++) acc[j] = 0.f;
    const float4* sB4 = (const float4*)sB;
#pragma unroll 4
    for (int k = 0; k < 256; k++) {
        float a = sA[r * 260 + k];
        float4 b0 = sB4[k * 16 + cg * 2];
        float4 b1 = sB4[k * 16 + cg * 2 + 1];
        acc[0] += a * b0.x; acc[1] += a * b0.y; acc[2] += a * b0.z; acc[3] += a * b0.w;
        acc[4] += a * b1.x; acc[5] += a * b1.y; acc[6] += a * b1.z; acc[7] += a * b1.w;
    }
    float* o = dst + (mm + r) * 256 + n0 + cg * 8;
    *(float4*)(o) = make_float4(acc[0], acc[1], acc[2], acc[3]);
    *(float4*)(o + 4) = make_float4(acc[4], acc[5], acc[6], acc[7]);
}

// ---------------- launch ----------------
extern "C" void kernel_launch(void* const* d_in, const int* in_sizes, int n_in,
                              void* d_out, int out_size) {
    const float* x1   = (const float*)d_in[0];
    const float* x2   = (const float*)d_in[1];
    const float* cost = (const float*)d_in[2];
    const float* Wqv1 = (const float*)d_in[3];
    const float* lin1 = (const float*)d_in[4];
    const float* lin2 = (const float*)d_in[5];
    const float* o1w  = (const float*)d_in[6];
    const float* o2w  = (const float*)d_in[7];
    float* out = (float*)d_out;

    cudaFuncSetAttribute(k_qkv,  cudaFuncAttributeMaxDynamicSharedMemorySize, SM_QKV);
    cudaFuncSetAttribute(k_mlp,  cudaFuncAttributeMaxDynamicSharedMemorySize, SM_MLP);
    cudaFuncSetAttribute(k_attn, cudaFuncAttributeMaxDynamicSharedMemorySize, SM_ATT);
    cudaFuncSetAttribute(k_out,  cudaFuncAttributeMaxDynamicSharedMemorySize, SM_OUT);

    // keep k_mlp in the profiler's capture slot (4th launch)
    k_qkv<<<dim3(64, 8), 256, SM_QKV>>>(x1, x2, Wqv1);   // 1
    k_prep<<<64, 256>>>(lin1, lin2);                      // 2
    k_nop<<<1, 32>>>();                                   // 3
    k_mlp<<<1024, 256, SM_MLP>>>(cost);                   // 4  <- profiled
    k_std<<<1, 128>>>();                                  // 5
    k_attn<<<512, 256, SM_ATT>>>();                       // 6
    k_out<<<dim3(64, 4), 256, SM_OUT>>>(o1w, o2w, out);   // 7

    (void)in_sizes; (void)n_in; (void)out_size;
}

// round 10
// speedup vs baseline: 1.0206x; 1.0206x over previous
#include <cuda_runtime.h>
#include <math.h>
#include <stdint.h>

typedef unsigned long long ull;

// ---------------- scratch (device globals; no allocations allowed) ----------------
__device__ float g_qT  [1024 * 256];      // [b*128+r][e]   e = h*16+d
__device__ float g_kTT [8 * 256 * 128];   // [b][e][c]
__device__ float g_v1  [1024 * 256];      // [b][h][s][d]
__device__ float g_v2  [1024 * 256];      // [b][h][s][d]
__device__ float g_ms1 [2097152];         // [b][h][r][c]
__device__ float g_ms2 [2097152];         // [b][h][r][c]
__device__ float g_attn1[1024 * 256];     // [b*128+r][h*16+d]
__device__ float g_attn2[1024 * 256];     // [b*128+c][h*16+d]
__device__ float g_part[1024 * 4];        // per-block {s1,q1,s2,q2}
__device__ float g_stats[2];              // inv_std1, inv_std2
// frag-packed split weights: per fragment+lane: {bhi0, bhi1, blo0, blo1}
__device__ float4 gW1p[256 * 32];         // frag = nf*4+ks  (nf 0..63, ks 0..3)
__device__ float4 gW2p[256 * 32];         // frag = ks*4+nf  (ks 0..63, nf 0..3)

// ---------------- helpers ----------------
__device__ __forceinline__ float fast_tanh(float x) {
    return 1.f - 2.f / (__expf(2.f * x) + 1.f);
}
__device__ __forceinline__ float tf32f(float x) {
    uint32_t u; asm("cvt.rna.tf32.f32 %0, %1;" : "=r"(u) : "f"(x));
    return __uint_as_float(u);
}
__device__ __forceinline__ void mma_tf32(float* c,
                                         uint32_t a0, uint32_t a1, uint32_t a2, uint32_t a3,
                                         uint32_t b0, uint32_t b1) {
    asm volatile(
        "mma.sync.aligned.m16n8k8.row.col.f32.tf32.tf32.f32 "
        "{%0,%1,%2,%3}, {%4,%5,%6,%7}, {%8,%9}, {%0,%1,%2,%3};"
        : "+f"(c[0]), "+f"(c[1]), "+f"(c[2]), "+f"(c[3])
        : "r"(a0), "r"(a1), "r"(a2), "r"(a3), "r"(b0), "r"(b1));
}

__global__ void k_nop() {}

// ---------------- K0: pack W1/W2 into per-fragment hi/lo float4s ----------------
__global__ void k_prep(const float* __restrict__ w1, const float* __restrict__ w2) {
    int idx = blockIdx.x * 256 + threadIdx.x;   // 0..16383
    if (idx >= 16384) return;
    int sel  = idx >> 13;
    int f    = idx & 8191;
    int lane = f & 31;
    int frag = f >> 5;            // 0..255
    int g = lane >> 2, tig = lane & 3;
    float b0, b1;
    if (sel == 0) {
        int nf = frag >> 2, ks = frag & 3;
        b0 = w1[(ks * 8 + tig) * 512 + nf * 8 + g];
        b1 = w1[(ks * 8 + tig + 4) * 512 + nf * 8 + g];
    } else {
        int ks = frag >> 2, nf = frag & 3;
        b0 = w2[(ks * 8 + tig) * 32 + nf * 8 + g];
        b1 = w2[(ks * 8 + tig + 4) * 32 + nf * 8 + g];
    }
    float h0 = tf32f(b0), h1 = tf32f(b1);
    float l0 = tf32f(b0 - h0), l1 = tf32f(b1 - h1);
    float4 v = make_float4(h0, h1, l0, l1);
    if (sel == 0) gW1p[frag * 32 + lane] = v;
    else          gW2p[frag * 32 + lane] = v;
}

// ---------------- K1: qkv projection GEMM ----------------
#define SM_QKV ((32 * 260 + 256 * 64) * 4)
__global__ void k_qkv(const float* __restrict__ x1, const float* __restrict__ x2,
                      const float* __restrict__ W) {
    extern __shared__ float smq[];
    float* sA = smq;             // 32 x 260 (padded)
    float* sB = smq + 32 * 260;  // 256 x 64
    const int m0 = blockIdx.x * 32, n0 = blockIdx.y * 64;
    const bool isX1 = (m0 < 1024);
    const float* src = isX1 ? x1 : x2;
    const int mm = m0 & 1023;
    const int b = mm >> 7, s0 = mm & 127;
    const int tid = threadIdx.x;

    for (int idx = tid; idx < 2048; idx += 256) {
        int row = idx >> 6, kk = (idx & 63) << 2;
        float4 v = *(const float4*)(src + (b * 128 + s0 + row) * 256 + kk);
        *(float4*)(sA + row * 260 + kk) = v;
    }
    for (int idx = tid; idx < 4096; idx += 256) {
        int row = idx >> 4, c4 = (idx & 15) << 2;
        float4 v = *(const float4*)(W + row * 512 + n0 + c4);
        *(float4*)(sB + row * 64 + c4) = v;
    }
    __syncthreads();

    const int r = tid >> 3, cg = tid & 7;
    float acc[8];
#pragma unroll
    for (int j = 0; j < 8; j++) acc[j] = 0.f;
    const float4* sB4 = (const float4*)sB;
#pragma unroll 4
    for (int k = 0; k < 256; k++) {
        float a = sA[r * 260 + k];
        float4 b0 = sB4[k * 16 + cg * 2];
        float4 b1 = sB4[k * 16 + cg * 2 + 1];
        acc[0] += a * b0.x; acc[1] += a * b0.y; acc[2] += a * b0.z; acc[3] += a * b0.w;
        acc[4] += a * b1.x; acc[5] += a * b1.y; acc[6] += a * b1.z; acc[7] += a * b1.w;
    }

    const int s = s0 + r;
#pragma unroll
    for (int j = 0; j < 8; j++) {
        int n = n0 + cg * 8 + j;
        float v = acc[j];
        if (n < 256) {
            if (isX1) g_qT[(b * 128 + s) * 256 + n] = v;
            else      g_kTT[(b * 256 + n) * 128 + s] = v;
        } else {
            int h = (n - 256) >> 4, d = n & 15;
            float* dst = isX1 ? g_v1 : g_v2;
            dst[((b * 16 + h) * 128 + s) * 16 + d] = v;
        }
    }
}

// ---------------- K3: tensor-core fused dot + MixedScoreFF MLP (R8-exact) ----------------
// grid 1024 = (b,r). 256 threads = 8 warps, warp w owns rows (c) [16w,16w+16).
// tf32x2 split: every product = Ahi*Bhi + Alo*Bhi + Ahi*Blo.
// Independent accumulators break MMA dependency chains.
// smem used 54272 B, PADDED to 81920 B -> 2 CTA/SM, ~64 KB L1D keeps the 32 KB
// active weight chunk L1-resident (validated in R8: DRAM 0.2%, 165.7 us).
#define SM_MLP 81920
__global__ void __launch_bounds__(256, 2)
k_mlp(const float* __restrict__ cost) {
    extern __shared__ float smf[];
    float* sH = smf;                      // pitch 68
    float* sA = smf + 8704;               // pitch 36
    float* sq = smf + 8704 + 4608;

    const int blk = blockIdx.x;           // b*128 + r
    const int b = blk >> 7;
    const int tid = threadIdx.x;
    const int warp = tid >> 5, lane = tid & 31;
    const int g = lane >> 2, tig = lane & 3;

    // ---- phase 0: q row to smem; compute din; build A (fp32) ----
    sq[tid] = g_qT[(blk << 8) + tid];
    __syncthreads();

    {
        const int c = tid & 127, half = tid >> 7;   // half: h 0..7 vs 8..15
        float cv = cost[blk * 128 + c];
        const float* kb = g_kTT + b * 32768 + c;
#pragma unroll
        for (int hh = 0; hh < 8; hh++) {
            int h = half * 8 + hh;
            float a = 0.f;
#pragma unroll
            for (int d = 0; d < 16; d++)
                a += sq[h * 16 + d] * kb[(h * 16 + d) * 128];
            sA[c * 36 + 2 * h] = a * 0.25f;
            sA[c * 36 + 2 * h + 1] = cv;
        }
    }
    __syncthreads();

    // ---- load A fragments, split hi/lo in registers ----
    const int arow0 = warp * 16 + g, arow1 = arow0 + 8;
    uint32_t Ahi[4][4], Alo[4][4];
#pragma unroll
    for (int ks = 0; ks < 4; ks++) {
        float a0 = sA[arow0 * 36 + ks * 8 + tig];
        float a1 = sA[arow1 * 36 + ks * 8 + tig];
        float a2 = sA[arow0 * 36 + ks * 8 + tig + 4];
        float a3 = sA[arow1 * 36 + ks * 8 + tig + 4];
        float h0 = tf32f(a0), h1 = tf32f(a1), h2 = tf32f(a2), h3 = tf32f(a3);
        Ahi[ks][0] = __float_as_uint(h0); Alo[ks][0] = __float_as_uint(tf32f(a0 - h0));
        Ahi[ks][1] = __float_as_uint(h1); Alo[ks][1] = __float_as_uint(tf32f(a1 - h1));
        Ahi[ks][2] = __float_as_uint(h2); Alo[ks][2] = __float_as_uint(tf32f(a2 - h2));
        Ahi[ks][3] = __float_as_uint(h3); Alo[ks][3] = __float_as_uint(tf32f(a3 - h3));
    }

    float OUThh[4][4], OUTc[4][4];
#pragma unroll
    for (int i = 0; i < 4; i++)
#pragma unroll
        for (int j = 0; j < 4; j++) { OUThh[i][j] = 0.f; OUTc[i][j] = 0.f; }

    // ---- 8 chunks of 64 hidden units ----
    for (int chunk = 0; chunk < 8; chunk++) {
        // layer 1: H[16x64] for this warp's rows; 3 independent chains of depth 4
#pragma unroll
        for (int nfp = 0; nfp < 8; nfp++) {
            float hh[4] = {0.f, 0.f, 0.f, 0.f};
            float lh[4] = {0.f, 0.f, 0.f, 0.f};
            float hl[4] = {0.f, 0.f, 0.f, 0.f};
#pragma unroll
            for (int ks = 0; ks < 4; ks++) {
                float4 bw = gW1p[(((chunk * 8 + nfp) * 4 + ks) << 5) + lane];
                uint32_t bh0 = __float_as_uint(bw.x), bh1 = __float_as_uint(bw.y);
                uint32_t bl0 = __float_as_uint(bw.z), bl1 = __float_as_uint(bw.w);
                mma_tf32(hh, Ahi[ks][0], Ahi[ks][1], Ahi[ks][2], Ahi[ks][3], bh0, bh1);
                mma_tf32(lh, Alo[ks][0], Alo[ks][1], Alo[ks][2], Alo[ks][3], bh0, bh1);
                mma_tf32(hl, Ahi[ks][0], Ahi[ks][1], Ahi[ks][2], Ahi[ks][3], bl0, bl1);
            }
            float h0 = fmaxf(hh[0] + lh[0] + hl[0], 0.f);
            float h1 = fmaxf(hh[1] + lh[1] + hl[1], 0.f);
            float h2 = fmaxf(hh[2] + lh[2] + hl[2], 0.f);
            float h3 = fmaxf(hh[3] + lh[3] + hl[3], 0.f);
            int col = nfp * 8 + 2 * tig;
            sH[arow0 * 68 + col]     = h0;
            sH[arow0 * 68 + col + 1] = h1;
            sH[arow1 * 68 + col]     = h2;
            sH[arow1 * 68 + col + 1] = h3;
        }
        __syncwarp();
        // layer 2: OUT[16x32] += H[16x64] @ W2[64x32]; split H in registers
#pragma unroll
        for (int ksp = 0; ksp < 8; ksp++) {
            float f0 = sH[arow0 * 68 + ksp * 8 + tig];
            float f1 = sH[arow1 * 68 + ksp * 8 + tig];
            float f2 = sH[arow0 * 68 + ksp * 8 + tig + 4];
            float f3 = sH[arow1 * 68 + ksp * 8 + tig + 4];
            float t0 = tf32f(f0), t1 = tf32f(f1), t2 = tf32f(f2), t3 = tf32f(f3);
            uint32_t ah0 = __float_as_uint(t0), ah1 = __float_as_uint(t1);
            uint32_t ah2 = __float_as_uint(t2), ah3 = __float_as_uint(t3);
            uint32_t al0 = __float_as_uint(tf32f(f0 - t0)), al1 = __float_as_uint(tf32f(f1 - t1));
            uint32_t al2 = __float_as_uint(tf32f(f2 - t2)), al3 = __float_as_uint(tf32f(f3 - t3));
#pragma unroll
            for (int nf = 0; nf < 4; nf++) {
                float4 bw = gW2p[(((chunk * 8 + ksp) * 4 + nf) << 5) + lane];
                uint32_t bh0 = __float_as_uint(bw.x), bh1 = __float_as_uint(bw.y);
                uint32_t bl0 = __float_as_uint(bw.z), bl1 = __float_as_uint(bw.w);
                mma_tf32(OUThh[nf], ah0, ah1, ah2, ah3, bh0, bh1);
                mma_tf32(OUTc[nf],  al0, al1, al2, al3, bh0, bh1);
                mma_tf32(OUTc[nf],  ah0, ah1, ah2, ah3, bl0, bl1);
            }
        }
        __syncwarp();
    }

    // ---- write OUT to smem (reuse sH as [128][33]) then coalesced global write ----
    float* sO = sH;
    __syncthreads();   // everyone done with H before repurposing
#pragma unroll
    for (int nf = 0; nf < 4; nf++) {
        int col = nf * 8 + 2 * tig;
        sO[arow0 * 33 + col]     = OUThh[nf][0] + OUTc[nf][0];
        sO[arow0 * 33 + col + 1] = OUThh[nf][1] + OUTc[nf][1];
        sO[arow1 * 33 + col]     = OUThh[nf][2] + OUTc[nf][2];
        sO[arow1 * 33 + col + 1] = OUThh[nf][3] + OUTc[nf][3];
    }
    __syncthreads();

    const int r = blk & 127;
    float s1 = 0.f, q1 = 0.f, s2 = 0.f, q2 = 0.f;
    for (int i = tid; i < 2048; i += 256) {
        int h = i >> 7, cc = i & 127;
        float m1 = sO[cc * 33 + 2 * h];
        float m2 = sO[cc * 33 + 2 * h + 1];
        g_ms1[((b * 16 + h) * 128 + r) * 128 + cc] = m1;
        g_ms2[((b * 16 + h) * 128 + r) * 128 + cc] = m2;
        s1 += m1; q1 += m1 * m1; s2 += m2; q2 += m2 * m2;
    }

    float v[4] = {s1, q1, s2, q2};
#pragma unroll
    for (int i = 0; i < 4; i++)
        for (int off = 16; off; off >>= 1) v[i] += __shfl_xor_sync(0xffffffffu, v[i], off);
    __shared__ float red[4][8];
    if (lane == 0) { red[0][warp] = v[0]; red[1][warp] = v[1]; red[2][warp] = v[2]; red[3][warp] = v[3]; }
    __syncthreads();
    if (tid == 0) {
#pragma unroll
        for (int i = 0; i < 4; i++) {
            float s = 0.f;
#pragma unroll
            for (int j = 0; j < 8; j++) s += red[i][j];
            g_part[blk * 4 + i] = s;
        }
    }
}

// ---------------- K4: std reduction (ddof=1) ----------------
__global__ void k_std() {
    __shared__ double sh[4][128];
    const int tid = threadIdx.x;  // 128
    double a0 = 0, a1 = 0, a2 = 0, a3 = 0;
    for (int i = tid; i < 1024; i += 128) {
        const float* p = g_part + i * 4;
        a0 += p[0]; a1 += p[1]; a2 += p[2]; a3 += p[3];
    }
    sh[0][tid] = a0; sh[1][tid] = a1; sh[2][tid] = a2; sh[3][tid] = a3;
    __syncthreads();
    for (int o = 64; o; o >>= 1) {
        if (tid < o) {
#pragma unroll
            for (int i = 0; i < 4; i++) sh[i][tid] += sh[i][tid + o];
        }
        __syncthreads();
    }
    if (tid == 0) {
        const double N = 2097152.0;
        double v1 = (sh[1][0] - sh[0][0] * sh[0][0] / N) / (N - 1.0);
        double v2 = (sh[3][0] - sh[2][0] * sh[2][0] / N) / (N - 1.0);
        g_stats[0] = (float)(1.0 / sqrt(v1));
        g_stats[1] = (float)(1.0 / sqrt(v2));
    }
}

// ---------------- K5: merged attention (blocks 0..255 = h1 path, 256..511 = h2 path) ----------------
#define SM_ATT (14848 * 4)
__global__ void k_attn() {
    extern __shared__ float sm[];
    const int tid = threadIdx.x;     // 256

    if (blockIdx.x < 256) {
        // ---- h1: softmax over c ----
        float* sl = sm;            // [64 r][128 c]
        float* sv = sm + 8192;     // v2 plane [128 c][16 d]
        const int blk = blockIdx.x;
        const int p = blk >> 1, rh = blk & 1;
        const float inv = g_stats[0];
        const float* mp = g_ms1 + p * 16384 + rh * 8192;
        for (int idx = tid; idx < 8192; idx += 256) sl[idx] = 10.f * fast_tanh(mp[idx] * inv);
        const float* vp = g_v2 + p * 2048;
        for (int idx = tid; idx < 2048; idx += 256) sv[idx] = vp[idx];
        __syncthreads();

        const int w = tid >> 5, lane = tid & 31;
#pragma unroll
        for (int i = 0; i < 8; i++) {
            int r = w * 8 + i;
            float* row = sl + r * 128;
            float m = fmaxf(fmaxf(row[lane], row[lane + 32]), fmaxf(row[lane + 64], row[lane + 96]));
#pragma unroll
            for (int off = 16; off; off >>= 1) m = fmaxf(m, __shfl_xor_sync(0xffffffffu, m, off));
            float s = 0.f;
#pragma unroll
            for (int t = 0; t < 4; t++) {
                int cc = lane + t * 32;
                float e = __expf(row[cc] - m);
                row[cc] = e; s += e;
            }
#pragma unroll
            for (int off = 16; off; off >>= 1) s += __shfl_xor_sync(0xffffffffu, s, off);
            float is = 1.f / s;
#pragma unroll
            for (int t = 0; t < 4; t++) row[lane + t * 32] *= is;
        }
        __syncthreads();

        const int r = tid >> 2, d0 = (tid & 3) << 2;
        float a0 = 0.f, a1 = 0.f, a2 = 0.f, a3 = 0.f;
#pragma unroll 4
        for (int cc = 0; cc < 128; cc++) {
            float wgt = sl[r * 128 + cc];
            float4 v = *(const float4*)(sv + cc * 16 + d0);
            a0 += wgt * v.x; a1 += wgt * v.y; a2 += wgt * v.z; a3 += wgt * v.w;
        }
        const int b = p >> 4, h = p & 15;
        float* out = g_attn1 + (b * 128 + rh * 64 + r) * 256 + h * 16 + d0;
        *(float4*)out = make_float4(a0, a1, a2, a3);
    } else {
        // ---- h2: softmax over r, logits transposed ----
        float* sl   = sm;               // [128 r][64 c]
        float* sv   = sm + 8192;        // v1 plane [128 r][16 d]
        float* pr   = sm + 10240;       // [4 seg][64 c][16 d]
        float* redm = sm + 14336;       // [4 seg][64 c]
        float* reds = sm + 14592;       // [4 seg][64 c]
        const int blk = blockIdx.x - 256;
        const int p = blk >> 1, ch = blk & 1;
        const float inv = g_stats[1];
        const float* mp = g_ms2 + p * 16384 + ch * 64;
        for (int idx = tid; idx < 8192; idx += 256)
            sl[idx] = 10.f * fast_tanh(mp[(idx >> 6) * 128 + (idx & 63)] * inv);
        const float* vp = g_v1 + p * 2048;
        for (int idx = tid; idx < 2048; idx += 256) sv[idx] = vp[idx];
        __syncthreads();

        const int c = tid & 63, seg = tid >> 6;   // seg owns rows [seg*32, seg*32+32)
        float m = -1e30f;
#pragma unroll 4
        for (int i = 0; i < 32; i++) m = fmaxf(m, sl[(seg * 32 + i) * 64 + c]);
        redm[seg * 64 + c] = m;
        __syncthreads();
        m = fmaxf(fmaxf(redm[c], redm[64 + c]), fmaxf(redm[128 + c], redm[192 + c]));
        float s = 0.f;
#pragma unroll 4
        for (int i = 0; i < 32; i++) {
            int rr = seg * 32 + i;
            float e = __expf(sl[rr * 64 + c] - m);
            sl[rr * 64 + c] = e; s += e;
        }
        reds[seg * 64 + c] = s;

        float acc[16];
#pragma unroll
        for (int j = 0; j < 16; j++) acc[j] = 0.f;
#pragma unroll 2
        for (int i = 0; i < 32; i++) {
            int rr = seg * 32 + i;
            float wgt = sl[rr * 64 + c];
            const float4* v = (const float4*)(sv + rr * 16);
            float4 v0 = v[0], v1 = v[1], v2 = v[2], v3 = v[3];
            acc[0] += wgt * v0.x; acc[1] += wgt * v0.y; acc[2] += wgt * v0.z; acc[3] += wgt * v0.w;
            acc[4] += wgt * v1.x; acc[5] += wgt * v1.y; acc[6] += wgt * v1.z; acc[7] += wgt * v1.w;
            acc[8] += wgt * v2.x; acc[9] += wgt * v2.y; acc[10] += wgt * v2.z; acc[11] += wgt * v2.w;
            acc[12] += wgt * v3.x; acc[13] += wgt * v3.y; acc[14] += wgt * v3.z; acc[15] += wgt * v3.w;
        }
        float* prp = pr + (seg * 64 + c) * 16;
#pragma unroll
        for (int j = 0; j < 4; j++)
            *(float4*)(prp + j * 4) = make_float4(acc[j * 4], acc[j * 4 + 1], acc[j * 4 + 2], acc[j * 4 + 3]);
        __syncthreads();

        const int b = p >> 4, h = p & 15;
        for (int o = tid; o < 1024; o += 256) {
            int cc = o >> 4, d = o & 15;
            float v = pr[(cc) * 16 + d] + pr[(64 + cc) * 16 + d]
                    + pr[(128 + cc) * 16 + d] + pr[(192 + cc) * 16 + d];
            float stot = reds[cc] + reds[64 + cc] + reds[128 + cc] + reds[192 + cc];
            g_attn2[(b * 128 + ch * 64 + cc) * 256 + h * 16 + d] = v / stot;
        }
    }
}

// ---------------- K6: output projections ----------------
#define SM_OUT ((32 * 260 + 256 * 64) * 4)
__global__ void k_out(const float* __restrict__ o1w, const float* __restrict__ o2w,
                      float* __restrict__ out) {
    extern __shared__ float smo[];
    float* sA = smo;
    float* sB = smo + 32 * 260;
    const int m0 = blockIdx.x * 32, n0 = blockIdx.y * 64;
    const bool first = (m0 < 1024);
    const float* A = first ? g_attn1 : g_attn2;
    const float* W = first ? o1w : o2w;
    float* dst = out + (first ? 0 : 262144);
    const int mm = m0 & 1023;
    const int tid = threadIdx.x;

    for (int idx = tid; idx < 2048; idx += 256) {
        int row = idx >> 6, kk = (idx & 63) << 2;
        float4 v = *(const float4*)(A + (mm + row) * 256 + kk);
        *(float4*)(sA + row * 260 + kk) = v;
    }
    for (int idx = tid; idx < 4096; idx += 256) {
        int row = idx >> 4, c4 = (idx & 15) << 2;
        float4 v = *(const float4*)(W + row * 256 + n0 + c4);
        *(float4*)(sB + row * 64 + c4) = v;
    }
    __syncthreads();

    const int r = tid >> 3, cg = tid & 7;
    float acc[8];
#pragma unroll
    for (int j = 0; j < 8; j++) acc[j] = 0.f;
    const float4* sB4 = (const float4*)sB;
#pragma unroll 4
    for (int k = 0; k < 256; k++) {
        float a = sA[r * 260 + k];
        float4 b0 = sB4[k * 16 + cg * 2];
        float4 b1 = sB4[k * 16 + cg * 2 + 1];
        acc[0] += a * b0.x; acc[1] += a * b0.y; acc[2] += a * b0.z; acc[3] += a * b0.w;
        acc[4] += a * b1.x; acc[5] += a * b1.y; acc[6] += a * b1.z; acc[7] += a * b1.w;
    }
    float* o = dst + (mm + r) * 256 + n0 + cg * 8;
    *(float4*)(o) = make_float4(acc[0], acc[1], acc[2], acc[3]);
    *(float4*)(o + 4) = make_float4(acc[4], acc[5], acc[6], acc[7]);
}

// ---------------- launch ----------------
extern "C" void kernel_launch(void* const* d_in, const int* in_sizes, int n_in,
                              void* d_out, int out_size) {
    const float* x1   = (const float*)d_in[0];
    const float* x2   = (const float*)d_in[1];
    const float* cost = (const float*)d_in[2];
    const float* Wqv1 = (const float*)d_in[3];
    const float* lin1 = (const float*)d_in[4];
    const float* lin2 = (const float*)d_in[5];
    const float* o1w  = (const float*)d_in[6];
    const float* o2w  = (const float*)d_in[7];
    float* out = (float*)d_out;

    cudaFuncSetAttribute(k_qkv,  cudaFuncAttributeMaxDynamicSharedMemorySize, SM_QKV);
    cudaFuncSetAttribute(k_mlp,  cudaFuncAttributeMaxDynamicSharedMemorySize, SM_MLP);
    cudaFuncSetAttribute(k_attn, cudaFuncAttributeMaxDynamicSharedMemorySize, SM_ATT);
    cudaFuncSetAttribute(k_out,  cudaFuncAttributeMaxDynamicSharedMemorySize, SM_OUT);

    // keep k_mlp in the profiler's capture slot (4th launch)
    k_qkv<<<dim3(64, 8), 256, SM_QKV>>>(x1, x2, Wqv1);   // 1
    k_prep<<<64, 256>>>(lin1, lin2);                      // 2
    k_nop<<<1, 32>>>();                                   // 3
    k_mlp<<<1024, 256, SM_MLP>>>(cost);                   // 4  <- profiled
    k_std<<<1, 128>>>();                                  // 5
    k_attn<<<512, 256, SM_ATT>>>();                       // 6
    k_out<<<dim3(64, 4), 256, SM_OUT>>>(o1w, o2w, out);   // 7

    (void)in_sizes; (void)n_in; (void)out_size;
}

// round 11
// speedup vs baseline: 1.2199x; 1.1953x over previous
#include <cuda_runtime.h>
#include <math.h>
#include <stdint.h>

typedef unsigned long long ull;

// ---------------- scratch (device globals; no allocations allowed) ----------------
__device__ float g_qT  [1024 * 256];      // [b*128+r][e]   e = h*16+d
__device__ float g_kTT [8 * 256 * 128];   // [b][e][c]
__device__ float g_v1  [1024 * 256];      // [b][h][s][d]
__device__ float g_v2  [1024 * 256];      // [b][h][s][d]
__device__ float g_ms1 [2097152];         // [b][h][r][c]
__device__ float g_ms2 [2097152];         // [b][h][r][c]
__device__ float g_attn1[1024 * 256];     // [b*128+r][h*16+d]
__device__ float g_attn2[1024 * 256];     // [b*128+c][h*16+d]
__device__ float g_part[1024 * 4];        // per-block {s1,q1,s2,q2}
__device__ float g_stats[2];              // inv_std1, inv_std2
// bf16 hi/lo frag-packed weights: per fragment+lane uint4 {b0hi, b1hi, b0lo, b1lo}
// W1 frag = (chunk*8+nfp)*2 + ks2   (128 frags)
// W2 frag = (chunk*4+ksp)*4 + nf    (128 frags)
__device__ uint4 gW1p[128 * 32];
__device__ uint4 gW2p[128 * 32];

// ---------------- helpers ----------------
__device__ __forceinline__ float fast_tanh(float x) {
    return 1.f - 2.f / (__expf(2.f * x) + 1.f);
}
// pack two fp32 -> bf16x2 (upper = fu, lower = fl)
__device__ __forceinline__ uint32_t packbf(float fu, float fl) {
    uint32_t r; asm("cvt.rn.bf16x2.f32 %0, %1, %2;" : "=r"(r) : "f"(fu), "f"(fl));
    return r;
}
// hi/lo bf16 split of a pair (x0 -> lower half, x1 -> upper half)
__device__ __forceinline__ void split2(float x0, float x1, uint32_t& hi, uint32_t& lo) {
    hi = packbf(x1, x0);
    float h0 = __uint_as_float(hi << 16);
    float h1 = __uint_as_float(hi & 0xffff0000u);
    lo = packbf(x1 - h1, x0 - h0);
}
__device__ __forceinline__ void mma_bf16(float* c,
                                         uint32_t a0, uint32_t a1, uint32_t a2, uint32_t a3,
                                         uint32_t b0, uint32_t b1) {
    asm volatile(
        "mma.sync.aligned.m16n8k16.row.col.f32.bf16.bf16.f32 "
        "{%0,%1,%2,%3}, {%4,%5,%6,%7}, {%8,%9}, {%0,%1,%2,%3};"
        : "+f"(c[0]), "+f"(c[1]), "+f"(c[2]), "+f"(c[3])
        : "r"(a0), "r"(a1), "r"(a2), "r"(a3), "r"(b0), "r"(b1));
}

__global__ void k_nop() {}

// ---------------- K0: pack W1/W2 into bf16 hi/lo fragment uint4s ----------------
// m16n8k16 B frag: b0 = {B[2tig][n], B[2tig+1][n]}, b1 = {B[2tig+8][n], B[2tig+9][n]}
__global__ void k_prep(const float* __restrict__ w1, const float* __restrict__ w2) {
    int idx = blockIdx.x * 256 + threadIdx.x;   // 0..8191
    if (idx >= 8192) return;
    int sel  = idx >> 12;
    int f    = idx & 4095;
    int lane = f & 31;
    int frag = f >> 5;            // 0..127
    int g = lane >> 2, tig = lane & 3;
    float k0, k1, k8, k9;
    if (sel == 0) {
        // W1 [32][512]: frag = cn*2 + ks2, n = cn*8+g, kb = ks2*16+2tig
        int ks2 = frag & 1, cn = frag >> 1;
        int n = cn * 8 + g;
        int kb = ks2 * 16 + 2 * tig;
        k0 = w1[kb * 512 + n];       k1 = w1[(kb + 1) * 512 + n];
        k8 = w1[(kb + 8) * 512 + n]; k9 = w1[(kb + 9) * 512 + n];
    } else {
        // W2 [512][32]: frag = ck*4 + nf, n = nf*8+g, kb = ck*16+2tig
        int nf = frag & 3, ck = frag >> 2;
        int n = nf * 8 + g;
        int kb = ck * 16 + 2 * tig;
        k0 = w2[kb * 32 + n];        k1 = w2[(kb + 1) * 32 + n];
        k8 = w2[(kb + 8) * 32 + n];  k9 = w2[(kb + 9) * 32 + n];
    }
    uint32_t h0, l0, h1, l1;
    split2(k0, k1, h0, l0);
    split2(k8, k9, h1, l1);
    uint4 v = make_uint4(h0, h1, l0, l1);
    if (sel == 0) gW1p[frag * 32 + lane] = v;
    else          gW2p[frag * 32 + lane] = v;
}

// ---------------- K1: qkv projection GEMM ----------------
#define SM_QKV ((32 * 260 + 256 * 64) * 4)
__global__ void k_qkv(const float* __restrict__ x1, const float* __restrict__ x2,
                      const float* __restrict__ W) {
    extern __shared__ float smq[];
    float* sA = smq;             // 32 x 260 (padded)
    float* sB = smq + 32 * 260;  // 256 x 64
    const int m0 = blockIdx.x * 32, n0 = blockIdx.y * 64;
    const bool isX1 = (m0 < 1024);
    const float* src = isX1 ? x1 : x2;
    const int mm = m0 & 1023;
    const int b = mm >> 7, s0 = mm & 127;
    const int tid = threadIdx.x;

    for (int idx = tid; idx < 2048; idx += 256) {
        int row = idx >> 6, kk = (idx & 63) << 2;
        float4 v = *(const float4*)(src + (b * 128 + s0 + row) * 256 + kk);
        *(float4*)(sA + row * 260 + kk) = v;
    }
    for (int idx = tid; idx < 4096; idx += 256) {
        int row = idx >> 4, c4 = (idx & 15) << 2;
        float4 v = *(const float4*)(W + row * 512 + n0 + c4);
        *(float4*)(sB + row * 64 + c4) = v;
    }
    __syncthreads();

    const int r = tid >> 3, cg = tid & 7;
    float acc[8];
#pragma unroll
    for (int j = 0; j < 8; j++) acc[j] = 0.f;
    const float4* sB4 = (const float4*)sB;
#pragma unroll 4
    for (int k = 0; k < 256; k++) {
        float a = sA[r * 260 + k];
        float4 b0 = sB4[k * 16 + cg * 2];
        float4 b1 = sB4[k * 16 + cg * 2 + 1];
        acc[0] += a * b0.x; acc[1] += a * b0.y; acc[2] += a * b0.z; acc[3] += a * b0.w;
        acc[4] += a * b1.x; acc[5] += a * b1.y; acc[6] += a * b1.z; acc[7] += a * b1.w;
    }

    const int s = s0 + r;
#pragma unroll
    for (int j = 0; j < 8; j++) {
        int n = n0 + cg * 8 + j;
        float v = acc[j];
        if (n < 256) {
            if (isX1) g_qT[(b * 128 + s) * 256 + n] = v;
            else      g_kTT[(b * 256 + n) * 128 + s] = v;
        } else {
            int h = (n - 256) >> 4, d = n & 15;
            float* dst = isX1 ? g_v1 : g_v2;
            dst[((b * 16 + h) * 128 + s) * 16 + d] = v;
        }
    }
}

// ---------------- K3: bf16-split tensor-core fused dot + MixedScoreFF MLP ----------------
// grid 1024 = (b,r). 256 threads = 8 warps, warp w owns rows (c) [16w,16w+16).
// bf16 hi/lo 3-term split per product (Ah*Bh + Al*Bh + Ah*Bl), m16n8k16 (K=16/MMA):
// MMA count halved vs tf32 k8 split. C layout identical -> epilogue unchanged.
// smem used 54272 B, PADDED to 81920 B -> 2 CTA/SM, ~64 KB L1D (validated R8).
#define SM_MLP 81920
__global__ void __launch_bounds__(256, 2)
k_mlp(const float* __restrict__ cost) {
    extern __shared__ float smf[];
    float* sH = smf;                      // pitch 68
    float* sA = smf + 8704;               // pitch 36
    float* sq = smf + 8704 + 4608;

    const int blk = blockIdx.x;           // b*128 + r
    const int b = blk >> 7;
    const int tid = threadIdx.x;
    const int warp = tid >> 5, lane = tid & 31;
    const int g = lane >> 2, tig = lane & 3;

    // ---- phase 0: q row to smem; compute din; build A (fp32) ----
    sq[tid] = g_qT[(blk << 8) + tid];
    __syncthreads();

    {
        const int c = tid & 127, half = tid >> 7;   // half: h 0..7 vs 8..15
        float cv = cost[blk * 128 + c];
        const float* kb = g_kTT + b * 32768 + c;
#pragma unroll
        for (int hh = 0; hh < 8; hh++) {
            int h = half * 8 + hh;
            float a = 0.f;
#pragma unroll
            for (int d = 0; d < 16; d++)
                a += sq[h * 16 + d] * kb[(h * 16 + d) * 128];
            sA[c * 36 + 2 * h] = a * 0.25f;
            sA[c * 36 + 2 * h + 1] = cv;
        }
    }
    __syncthreads();

    // ---- A fragments (bf16 hi/lo), held for all chunks ----
    // m16n8k16 A frag: a0={A[r0][2tig],A[r0][2tig+1]}, a1=row r0+8, a2=cols+8 r0, a3=cols+8 r0+8
    const int arow0 = warp * 16 + g, arow1 = arow0 + 8;
    uint32_t Ahi[2][4], Alo[2][4];
#pragma unroll
    for (int ks2 = 0; ks2 < 2; ks2++) {
        int cb = ks2 * 16 + 2 * tig;
        split2(sA[arow0 * 36 + cb],     sA[arow0 * 36 + cb + 1], Ahi[ks2][0], Alo[ks2][0]);
        split2(sA[arow1 * 36 + cb],     sA[arow1 * 36 + cb + 1], Ahi[ks2][1], Alo[ks2][1]);
        split2(sA[arow0 * 36 + cb + 8], sA[arow0 * 36 + cb + 9], Ahi[ks2][2], Alo[ks2][2]);
        split2(sA[arow1 * 36 + cb + 8], sA[arow1 * 36 + cb + 9], Ahi[ks2][3], Alo[ks2][3]);
    }

    float OUThh[4][4], OUTc[4][4];
#pragma unroll
    for (int i = 0; i < 4; i++)
#pragma unroll
        for (int j = 0; j < 4; j++) { OUThh[i][j] = 0.f; OUTc[i][j] = 0.f; }

    // ---- 8 chunks of 64 hidden units ----
    for (int chunk = 0; chunk < 8; chunk++) {
        // layer 1: H[16x64]; per nfp: 2 k16-steps x 3 split terms = 6 MMAs
#pragma unroll
        for (int nfp = 0; nfp < 8; nfp++) {
            float hh[4] = {0.f, 0.f, 0.f, 0.f};
            float lh[4] = {0.f, 0.f, 0.f, 0.f};
            float hl[4] = {0.f, 0.f, 0.f, 0.f};
#pragma unroll
            for (int ks2 = 0; ks2 < 2; ks2++) {
                uint4 bw = gW1p[((((chunk * 8 + nfp) * 2 + ks2)) << 5) + lane];
                mma_bf16(hh, Ahi[ks2][0], Ahi[ks2][1], Ahi[ks2][2], Ahi[ks2][3], bw.x, bw.y);
                mma_bf16(lh, Alo[ks2][0], Alo[ks2][1], Alo[ks2][2], Alo[ks2][3], bw.x, bw.y);
                mma_bf16(hl, Ahi[ks2][0], Ahi[ks2][1], Ahi[ks2][2], Ahi[ks2][3], bw.z, bw.w);
            }
            float h0 = fmaxf(hh[0] + lh[0] + hl[0], 0.f);
            float h1 = fmaxf(hh[1] + lh[1] + hl[1], 0.f);
            float h2 = fmaxf(hh[2] + lh[2] + hl[2], 0.f);
            float h3 = fmaxf(hh[3] + lh[3] + hl[3], 0.f);
            int col = nfp * 8 + 2 * tig;
            sH[arow0 * 68 + col]     = h0;
            sH[arow0 * 68 + col + 1] = h1;
            sH[arow1 * 68 + col]     = h2;
            sH[arow1 * 68 + col + 1] = h3;
        }
        __syncwarp();
        // layer 2: OUT[16x32] += H[16x64] @ W2[64x32]; 4 k16-steps x 4 nf x 3 = 48 MMAs
#pragma unroll
        for (int ksp = 0; ksp < 4; ksp++) {
            int cb = ksp * 16 + 2 * tig;
            float2 f0 = *(const float2*)(sH + arow0 * 68 + cb);
            float2 f1 = *(const float2*)(sH + arow1 * 68 + cb);
            float2 f2 = *(const float2*)(sH + arow0 * 68 + cb + 8);
            float2 f3 = *(const float2*)(sH + arow1 * 68 + cb + 8);
            uint32_t ah[4], al[4];
            split2(f0.x, f0.y, ah[0], al[0]);
            split2(f1.x, f1.y, ah[1], al[1]);
            split2(f2.x, f2.y, ah[2], al[2]);
            split2(f3.x, f3.y, ah[3], al[3]);
#pragma unroll
            for (int nf = 0; nf < 4; nf++) {
                uint4 bw = gW2p[((((chunk * 4 + ksp) * 4 + nf)) << 5) + lane];
                mma_bf16(OUThh[nf], ah[0], ah[1], ah[2], ah[3], bw.x, bw.y);
                mma_bf16(OUTc[nf],  al[0], al[1], al[2], al[3], bw.x, bw.y);
                mma_bf16(OUTc[nf],  ah[0], ah[1], ah[2], ah[3], bw.z, bw.w);
            }
        }
        __syncwarp();
    }

    // ---- write OUT to smem (reuse sH as [128][33]) then coalesced global write ----
    float* sO = sH;
    __syncthreads();   // everyone done with H before repurposing
#pragma unroll
    for (int nf = 0; nf < 4; nf++) {
        int col = nf * 8 + 2 * tig;
        sO[arow0 * 33 + col]     = OUThh[nf][0] + OUTc[nf][0];
        sO[arow0 * 33 + col + 1] = OUThh[nf][1] + OUTc[nf][1];
        sO[arow1 * 33 + col]     = OUThh[nf][2] + OUTc[nf][2];
        sO[arow1 * 33 + col + 1] = OUThh[nf][3] + OUTc[nf][3];
    }
    __syncthreads();

    const int r = blk & 127;
    float s1 = 0.f, q1 = 0.f, s2 = 0.f, q2 = 0.f;
    for (int i = tid; i < 2048; i += 256) {
        int h = i >> 7, cc = i & 127;
        float m1 = sO[cc * 33 + 2 * h];
        float m2 = sO[cc * 33 + 2 * h + 1];
        g_ms1[((b * 16 + h) * 128 + r) * 128 + cc] = m1;
        g_ms2[((b * 16 + h) * 128 + r) * 128 + cc] = m2;
        s1 += m1; q1 += m1 * m1; s2 += m2; q2 += m2 * m2;
    }

    float v[4] = {s1, q1, s2, q2};
#pragma unroll
    for (int i = 0; i < 4; i++)
        for (int off = 16; off; off >>= 1) v[i] += __shfl_xor_sync(0xffffffffu, v[i], off);
    __shared__ float red[4][8];
    if (lane == 0) { red[0][warp] = v[0]; red[1][warp] = v[1]; red[2][warp] = v[2]; red[3][warp] = v[3]; }
    __syncthreads();
    if (tid == 0) {
#pragma unroll
        for (int i = 0; i < 4; i++) {
            float s = 0.f;
#pragma unroll
            for (int j = 0; j < 8; j++) s += red[i][j];
            g_part[blk * 4 + i] = s;
        }
    }
}

// ---------------- K4: std reduction (ddof=1) ----------------
__global__ void k_std() {
    __shared__ double sh[4][128];
    const int tid = threadIdx.x;  // 128
    double a0 = 0, a1 = 0, a2 = 0, a3 = 0;
    for (int i = tid; i < 1024; i += 128) {
        const float* p = g_part + i * 4;
        a0 += p[0]; a1 += p[1]; a2 += p[2]; a3 += p[3];
    }
    sh[0][tid] = a0; sh[1][tid] = a1; sh[2][tid] = a2; sh[3][tid] = a3;
    __syncthreads();
    for (int o = 64; o; o >>= 1) {
        if (tid < o) {
#pragma unroll
            for (int i = 0; i < 4; i++) sh[i][tid] += sh[i][tid + o];
        }
        __syncthreads();
    }
    if (tid == 0) {
        const double N = 2097152.0;
        double v1 = (sh[1][0] - sh[0][0] * sh[0][0] / N) / (N - 1.0);
        double v2 = (sh[3][0] - sh[2][0] * sh[2][0] / N) / (N - 1.0);
        g_stats[0] = (float)(1.0 / sqrt(v1));
        g_stats[1] = (float)(1.0 / sqrt(v2));
    }
}

// ---------------- K5: merged attention (blocks 0..255 = h1 path, 256..511 = h2 path) ----------------
#define SM_ATT (14848 * 4)
__global__ void k_attn() {
    extern __shared__ float sm[];
    const int tid = threadIdx.x;     // 256

    if (blockIdx.x < 256) {
        // ---- h1: softmax over c ----
        float* sl = sm;            // [64 r][128 c]
        float* sv = sm + 8192;     // v2 plane [128 c][16 d]
        const int blk = blockIdx.x;
        const int p = blk >> 1, rh = blk & 1;
        const float inv = g_stats[0];
        const float* mp = g_ms1 + p * 16384 + rh * 8192;
        for (int idx = tid; idx < 8192; idx += 256) sl[idx] = 10.f * fast_tanh(mp[idx] * inv);
        const float* vp = g_v2 + p * 2048;
        for (int idx = tid; idx < 2048; idx += 256) sv[idx] = vp[idx];
        __syncthreads();

        const int w = tid >> 5, lane = tid & 31;
#pragma unroll
        for (int i = 0; i < 8; i++) {
            int r = w * 8 + i;
            float* row = sl + r * 128;
            float m = fmaxf(fmaxf(row[lane], row[lane + 32]), fmaxf(row[lane + 64], row[lane + 96]));
#pragma unroll
            for (int off = 16; off; off >>= 1) m = fmaxf(m, __shfl_xor_sync(0xffffffffu, m, off));
            float s = 0.f;
#pragma unroll
            for (int t = 0; t < 4; t++) {
                int cc = lane + t * 32;
                float e = __expf(row[cc] - m);
                row[cc] = e; s += e;
            }
#pragma unroll
            for (int off = 16; off; off >>= 1) s += __shfl_xor_sync(0xffffffffu, s, off);
            float is = 1.f / s;
#pragma unroll
            for (int t = 0; t < 4; t++) row[lane + t * 32] *= is;
        }
        __syncthreads();

        const int r = tid >> 2, d0 = (tid & 3) << 2;
        float a0 = 0.f, a1 = 0.f, a2 = 0.f, a3 = 0.f;
#pragma unroll 4
        for (int cc = 0; cc < 128; cc++) {
            float wgt = sl[r * 128 + cc];
            float4 v = *(const float4*)(sv + cc * 16 + d0);
            a0 += wgt * v.x; a1 += wgt * v.y; a2 += wgt * v.z; a3 += wgt * v.w;
        }
        const int b = p >> 4, h = p & 15;
        float* out = g_attn1 + (b * 128 + rh * 64 + r) * 256 + h * 16 + d0;
        *(float4*)out = make_float4(a0, a1, a2, a3);
    } else {
        // ---- h2: softmax over r, logits transposed ----
        float* sl   = sm;               // [128 r][64 c]
        float* sv   = sm + 8192;        // v1 plane [128 r][16 d]
        float* pr   = sm + 10240;       // [4 seg][64 c][16 d]
        float* redm = sm + 14336;       // [4 seg][64 c]
        float* reds = sm + 14592;       // [4 seg][64 c]
        const int blk = blockIdx.x - 256;
        const int p = blk >> 1, ch = blk & 1;
        const float inv = g_stats[1];
        const float* mp = g_ms2 + p * 16384 + ch * 64;
        for (int idx = tid; idx < 8192; idx += 256)
            sl[idx] = 10.f * fast_tanh(mp[(idx >> 6) * 128 + (idx & 63)] * inv);
        const float* vp = g_v1 + p * 2048;
        for (int idx = tid; idx < 2048; idx += 256) sv[idx] = vp[idx];
        __syncthreads();

        const int c = tid & 63, seg = tid >> 6;   // seg owns rows [seg*32, seg*32+32)
        float m = -1e30f;
#pragma unroll 4
        for (int i = 0; i < 32; i++) m = fmaxf(m, sl[(seg * 32 + i) * 64 + c]);
        redm[seg * 64 + c] = m;
        __syncthreads();
        m = fmaxf(fmaxf(redm[c], redm[64 + c]), fmaxf(redm[128 + c], redm[192 + c]));
        float s = 0.f;
#pragma unroll 4
        for (int i = 0; i < 32; i++) {
            int rr = seg * 32 + i;
            float e = __expf(sl[rr * 64 + c] - m);
            sl[rr * 64 + c] = e; s += e;
        }
        reds[seg * 64 + c] = s;

        float acc[16];
#pragma unroll
        for (int j = 0; j < 16; j++) acc[j] = 0.f;
#pragma unroll 2
        for (int i = 0; i < 32; i++) {
            int rr = seg * 32 + i;
            float wgt = sl[rr * 64 + c];
            const float4* v = (const float4*)(sv + rr * 16);
            float4 v0 = v[0], v1 = v[1], v2 = v[2], v3 = v[3];
            acc[0] += wgt * v0.x; acc[1] += wgt * v0.y; acc[2] += wgt * v0.z; acc[3] += wgt * v0.w;
            acc[4] += wgt * v1.x; acc[5] += wgt * v1.y; acc[6] += wgt * v1.z; acc[7] += wgt * v1.w;
            acc[8] += wgt * v2.x; acc[9] += wgt * v2.y; acc[10] += wgt * v2.z; acc[11] += wgt * v2.w;
            acc[12] += wgt * v3.x; acc[13] += wgt * v3.y; acc[14] += wgt * v3.z; acc[15] += wgt * v3.w;
        }
        float* prp = pr + (seg * 64 + c) * 16;
#pragma unroll
        for (int j = 0; j < 4; j++)
            *(float4*)(prp + j * 4) = make_float4(acc[j * 4], acc[j * 4 + 1], acc[j * 4 + 2], acc[j * 4 + 3]);
        __syncthreads();

        const int b = p >> 4, h = p & 15;
        for (int o = tid; o < 1024; o += 256) {
            int cc = o >> 4, d = o & 15;
            float v = pr[(cc) * 16 + d] + pr[(64 + cc) * 16 + d]
                    + pr[(128 + cc) * 16 + d] + pr[(192 + cc) * 16 + d];
            float stot = reds[cc] + reds[64 + cc] + reds[128 + cc] + reds[192 + cc];
            g_attn2[(b * 128 + ch * 64 + cc) * 256 + h * 16 + d] = v / stot;
        }
    }
}

// ---------------- K6: output projections ----------------
#define SM_OUT ((32 * 260 + 256 * 64) * 4)
__global__ void k_out(const float* __restrict__ o1w, const float* __restrict__ o2w,
                      float* __restrict__ out) {
    extern __shared__ float smo[];
    float* sA = smo;
    float* sB = smo + 32 * 260;
    const int m0 = blockIdx.x * 32, n0 = blockIdx.y * 64;
    const bool first = (m0 < 1024);
    const float* A = first ? g_attn1 : g_attn2;
    const float* W = first ? o1w : o2w;
    float* dst = out + (first ? 0 : 262144);
    const int mm = m0 & 1023;
    const int tid = threadIdx.x;

    for (int idx = tid; idx < 2048; idx += 256) {
        int row = idx >> 6, kk = (idx & 63) << 2;
        float4 v = *(const float4*)(A + (mm + row) * 256 + kk);
        *(float4*)(sA + row * 260 + kk) = v;
    }
    for (int idx = tid; idx < 4096; idx += 256) {
        int row = idx >> 4, c4 = (idx & 15) << 2;
        float4 v = *(const float4*)(W + row * 256 + n0 + c4);
        *(float4*)(sB + row * 64 + c4) = v;
    }
    __syncthreads();

    const int r = tid >> 3, cg = tid & 7;
    float acc[8];
#pragma unroll
    for (int j = 0; j < 8; j++) acc[j] = 0.f;
    const float4* sB4 = (const float4*)sB;
#pragma unroll 4
    for (int k = 0; k < 256; k++) {
        float a = sA[r * 260 + k];
        float4 b0 = sB4[k * 16 + cg * 2];
        float4 b1 = sB4[k * 16 + cg * 2 + 1];
        acc[0] += a * b0.x; acc[1] += a * b0.y; acc[2] += a * b0.z; acc[3] += a * b0.w;
        acc[4] += a * b1.x; acc[5] += a * b1.y; acc[6] += a * b1.z; acc[7] += a * b1.w;
    }
    float* o = dst + (mm + r) * 256 + n0 + cg * 8;
    *(float4*)(o) = make_float4(acc[0], acc[1], acc[2], acc[3]);
    *(float4*)(o + 4) = make_float4(acc[4], acc[5], acc[6], acc[7]);
}

// ---------------- launch ----------------
extern "C" void kernel_launch(void* const* d_in, const int* in_sizes, int n_in,
                              void* d_out, int out_size) {
    const float* x1   = (const float*)d_in[0];
    const float* x2   = (const float*)d_in[1];
    const float* cost = (const float*)d_in[2];
    const float* Wqv1 = (const float*)d_in[3];
    const float* lin1 = (const float*)d_in[4];
    const float* lin2 = (const float*)d_in[5];
    const float* o1w  = (const float*)d_in[6];
    const float* o2w  = (const float*)d_in[7];
    float* out = (float*)d_out;

    cudaFuncSetAttribute(k_qkv,  cudaFuncAttributeMaxDynamicSharedMemorySize, SM_QKV);
    cudaFuncSetAttribute(k_mlp,  cudaFuncAttributeMaxDynamicSharedMemorySize, SM_MLP);
    cudaFuncSetAttribute(k_attn, cudaFuncAttributeMaxDynamicSharedMemorySize, SM_ATT);
    cudaFuncSetAttribute(k_out,  cudaFuncAttributeMaxDynamicSharedMemorySize, SM_OUT);

    // keep k_mlp in the profiler's capture slot (4th launch)
    k_qkv<<<dim3(64, 8), 256, SM_QKV>>>(x1, x2, Wqv1);   // 1
    k_prep<<<32, 256>>>(lin1, lin2);                      // 2
    k_nop<<<1, 32>>>();                                   // 3
    k_mlp<<<1024, 256, SM_MLP>>>(cost);                   // 4  <- profiled
    k_std<<<1, 128>>>();                                  // 5
    k_attn<<<512, 256, SM_ATT>>>();                       // 6
    k_out<<<dim3(64, 4), 256, SM_OUT>>>(o1w, o2w, out);   // 7

    (void)in_sizes; (void)n_in; (void)out_size;
}

// round 12
// speedup vs baseline: 1.3013x; 1.0667x over previous
#include <cuda_runtime.h>
#include <math.h>
#include <stdint.h>

typedef unsigned long long ull;

// ---------------- scratch (device globals; no allocations allowed) ----------------
__device__ float g_qT  [1024 * 256];      // [b*128+r][e]   e = h*16+d
__device__ float g_kTT [8 * 256 * 128];   // [b][e][c]
__device__ float g_v1  [1024 * 256];      // [b][h][s][d]
__device__ float g_v2  [1024 * 256];      // [b][h][s][d]
__device__ float g_ms1 [2097152];         // [b][h][r][c]
__device__ float g_ms2 [2097152];         // [b][h][r][c]
__device__ float g_attn1[1024 * 256];     // [b*128+r][h*16+d]
__device__ float g_attn2[1024 * 256];     // [b*128+c][h*16+d]
__device__ float g_part[1024 * 4];        // per-block {s1,q1,s2,q2}
__device__ float g_stats[2];              // inv_std1, inv_std2
// bf16 hi/lo frag-packed weights: per fragment+lane uint4 {b0hi, b1hi, b0lo, b1lo}
// W1 frag = (chunk*8+nfp)*2 + ks2   (128 frags)
// W2 frag = (chunk*4+ksp)*4 + nf    (128 frags)
__device__ uint4 gW1p[128 * 32];
__device__ uint4 gW2p[128 * 32];

// ---------------- helpers ----------------
__device__ __forceinline__ float fast_tanh(float x) {
    return 1.f - 2.f / (__expf(2.f * x) + 1.f);
}
// pack two fp32 -> bf16x2 (upper = fu, lower = fl)
__device__ __forceinline__ uint32_t packbf(float fu, float fl) {
    uint32_t r; asm("cvt.rn.bf16x2.f32 %0, %1, %2;" : "=r"(r) : "f"(fu), "f"(fl));
    return r;
}
// hi/lo bf16 split of a pair (x0 -> lower half, x1 -> upper half)
__device__ __forceinline__ void split2(float x0, float x1, uint32_t& hi, uint32_t& lo) {
    hi = packbf(x1, x0);
    float h0 = __uint_as_float(hi << 16);
    float h1 = __uint_as_float(hi & 0xffff0000u);
    lo = packbf(x1 - h1, x0 - h0);
}
__device__ __forceinline__ void mma_bf16(float* c,
                                         uint32_t a0, uint32_t a1, uint32_t a2, uint32_t a3,
                                         uint32_t b0, uint32_t b1) {
    asm volatile(
        "mma.sync.aligned.m16n8k16.row.col.f32.bf16.bf16.f32 "
        "{%0,%1,%2,%3}, {%4,%5,%6,%7}, {%8,%9}, {%0,%1,%2,%3};"
        : "+f"(c[0]), "+f"(c[1]), "+f"(c[2]), "+f"(c[3])
        : "r"(a0), "r"(a1), "r"(a2), "r"(a3), "r"(b0), "r"(b1));
}

__global__ void k_nop() {}

// ---------------- K0: pack W1/W2 into bf16 hi/lo fragment uint4s ----------------
// m16n8k16 B frag: b0 = {B[2tig][n], B[2tig+1][n]}, b1 = {B[2tig+8][n], B[2tig+9][n]}
__global__ void k_prep(const float* __restrict__ w1, const float* __restrict__ w2) {
    int idx = blockIdx.x * 256 + threadIdx.x;   // 0..8191
    if (idx >= 8192) return;
    int sel  = idx >> 12;
    int f    = idx & 4095;
    int lane = f & 31;
    int frag = f >> 5;            // 0..127
    int g = lane >> 2, tig = lane & 3;
    float k0, k1, k8, k9;
    if (sel == 0) {
        // W1 [32][512]: frag = cn*2 + ks2, n = cn*8+g, kb = ks2*16+2tig
        int ks2 = frag & 1, cn = frag >> 1;
        int n = cn * 8 + g;
        int kb = ks2 * 16 + 2 * tig;
        k0 = w1[kb * 512 + n];       k1 = w1[(kb + 1) * 512 + n];
        k8 = w1[(kb + 8) * 512 + n]; k9 = w1[(kb + 9) * 512 + n];
    } else {
        // W2 [512][32]: frag = ck*4 + nf, n = nf*8+g, kb = ck*16+2tig
        int nf = frag & 3, ck = frag >> 2;
        int n = nf * 8 + g;
        int kb = ck * 16 + 2 * tig;
        k0 = w2[kb * 32 + n];        k1 = w2[(kb + 1) * 32 + n];
        k8 = w2[(kb + 8) * 32 + n];  k9 = w2[(kb + 9) * 32 + n];
    }
    uint32_t h0, l0, h1, l1;
    split2(k0, k1, h0, l0);
    split2(k8, k9, h1, l1);
    uint4 v = make_uint4(h0, h1, l0, l1);
    if (sel == 0) gW1p[frag * 32 + lane] = v;
    else          gW2p[frag * 32 + lane] = v;
}

// ---------------- K1: qkv projection GEMM ----------------
#define SM_QKV ((32 * 260 + 256 * 64) * 4)
__global__ void k_qkv(const float* __restrict__ x1, const float* __restrict__ x2,
                      const float* __restrict__ W) {
    extern __shared__ float smq[];
    float* sA = smq;             // 32 x 260 (padded)
    float* sB = smq + 32 * 260;  // 256 x 64
    const int m0 = blockIdx.x * 32, n0 = blockIdx.y * 64;
    const bool isX1 = (m0 < 1024);
    const float* src = isX1 ? x1 : x2;
    const int mm = m0 & 1023;
    const int b = mm >> 7, s0 = mm & 127;
    const int tid = threadIdx.x;

    for (int idx = tid; idx < 2048; idx += 256) {
        int row = idx >> 6, kk = (idx & 63) << 2;
        float4 v = *(const float4*)(src + (b * 128 + s0 + row) * 256 + kk);
        *(float4*)(sA + row * 260 + kk) = v;
    }
    for (int idx = tid; idx < 4096; idx += 256) {
        int row = idx >> 4, c4 = (idx & 15) << 2;
        float4 v = *(const float4*)(W + row * 512 + n0 + c4);
        *(float4*)(sB + row * 64 + c4) = v;
    }
    __syncthreads();

    const int r = tid >> 3, cg = tid & 7;
    float acc[8];
#pragma unroll
    for (int j = 0; j < 8; j++) acc[j] = 0.f;
    const float4* sB4 = (const float4*)sB;
#pragma unroll 4
    for (int k = 0; k < 256; k++) {
        float a = sA[r * 260 + k];
        float4 b0 = sB4[k * 16 + cg * 2];
        float4 b1 = sB4[k * 16 + cg * 2 + 1];
        acc[0] += a * b0.x; acc[1] += a * b0.y; acc[2] += a * b0.z; acc[3] += a * b0.w;
        acc[4] += a * b1.x; acc[5] += a * b1.y; acc[6] += a * b1.z; acc[7] += a * b1.w;
    }

    const int s = s0 + r;
#pragma unroll
    for (int j = 0; j < 8; j++) {
        int n = n0 + cg * 8 + j;
        float v = acc[j];
        if (n < 256) {
            if (isX1) g_qT[(b * 128 + s) * 256 + n] = v;
            else      g_kTT[(b * 256 + n) * 128 + s] = v;
        } else {
            int h = (n - 256) >> 4, d = n & 15;
            float* dst = isX1 ? g_v1 : g_v2;
            dst[((b * 16 + h) * 128 + s) * 16 + d] = v;
        }
    }
}

// ---------------- K3: bf16-split tensor-core fused dot + MixedScoreFF MLP ----------------
// grid 1024 = (b,r). 256 threads = 8 warps, warp w owns rows (c) [16w,16w+16).
// bf16 hi/lo 3-term split per product; m16n8k16.
// KEY: layer-1 C-fragment layout == layer-2 A-fragment layout (same thread), so
// H never touches smem — relu'd accumulators are split2'ed straight into layer-2
// A-frags in registers. smem only for A staging (reused as output buffer).
// Padded to 81920 B to pin residency at 2 CTA/SM (L1 weight-resident model, R8).
#define SM_MLP 81920
__global__ void __launch_bounds__(256, 2)
k_mlp(const float* __restrict__ cost) {
    extern __shared__ float smf[];
    float* sA = smf;                      // [128][36] staging; reused as sO [128][33]
    float* sq = smf + 4608;               // [256]

    const int blk = blockIdx.x;           // b*128 + r
    const int b = blk >> 7;
    const int tid = threadIdx.x;
    const int warp = tid >> 5, lane = tid & 31;
    const int g = lane >> 2, tig = lane & 3;

    // ---- phase 0: q row to smem; compute din; build A (fp32) ----
    sq[tid] = g_qT[(blk << 8) + tid];
    __syncthreads();

    {
        const int c = tid & 127, half = tid >> 7;   // half: h 0..7 vs 8..15
        float cv = cost[blk * 128 + c];
        const float* kb = g_kTT + b * 32768 + c;
#pragma unroll
        for (int hh = 0; hh < 8; hh++) {
            int h = half * 8 + hh;
            float a = 0.f;
#pragma unroll
            for (int d = 0; d < 16; d++)
                a += sq[h * 16 + d] * kb[(h * 16 + d) * 128];
            sA[c * 36 + 2 * h] = a * 0.25f;
            sA[c * 36 + 2 * h + 1] = cv;
        }
    }
    __syncthreads();

    // ---- A fragments (bf16 hi/lo), held for all chunks ----
    const int arow0 = warp * 16 + g, arow1 = arow0 + 8;
    uint32_t Ahi[2][4], Alo[2][4];
#pragma unroll
    for (int ks2 = 0; ks2 < 2; ks2++) {
        int cb = ks2 * 16 + 2 * tig;
        split2(sA[arow0 * 36 + cb],     sA[arow0 * 36 + cb + 1], Ahi[ks2][0], Alo[ks2][0]);
        split2(sA[arow1 * 36 + cb],     sA[arow1 * 36 + cb + 1], Ahi[ks2][1], Alo[ks2][1]);
        split2(sA[arow0 * 36 + cb + 8], sA[arow0 * 36 + cb + 9], Ahi[ks2][2], Alo[ks2][2]);
        split2(sA[arow1 * 36 + cb + 8], sA[arow1 * 36 + cb + 9], Ahi[ks2][3], Alo[ks2][3]);
    }
    __syncthreads();   // sA reads done; safe to reuse as sO later

    float OUThh[4][4], OUTc[4][4];
#pragma unroll
    for (int i = 0; i < 4; i++)
#pragma unroll
        for (int j = 0; j < 4; j++) { OUThh[i][j] = 0.f; OUTc[i][j] = 0.f; }

    // ---- 8 chunks of 64 hidden units; H stays in registers ----
    for (int chunk = 0; chunk < 8; chunk++) {
#pragma unroll
        for (int ksp = 0; ksp < 4; ksp++) {
            // layer 1 for nfp = 2*ksp (-> a0/a1) and nfp = 2*ksp+1 (-> a2/a3)
            uint32_t ah[4], al[4];
#pragma unroll
            for (int halfn = 0; halfn < 2; halfn++) {
                int nfp = 2 * ksp + halfn;
                float hh[4] = {0.f, 0.f, 0.f, 0.f};
                float lh[4] = {0.f, 0.f, 0.f, 0.f};
                float hl[4] = {0.f, 0.f, 0.f, 0.f};
#pragma unroll
                for (int ks2 = 0; ks2 < 2; ks2++) {
                    uint4 bw = gW1p[((((chunk * 8 + nfp) * 2 + ks2)) << 5) + lane];
                    mma_bf16(hh, Ahi[ks2][0], Ahi[ks2][1], Ahi[ks2][2], Ahi[ks2][3], bw.x, bw.y);
                    mma_bf16(lh, Alo[ks2][0], Alo[ks2][1], Alo[ks2][2], Alo[ks2][3], bw.x, bw.y);
                    mma_bf16(hl, Ahi[ks2][0], Ahi[ks2][1], Ahi[ks2][2], Ahi[ks2][3], bw.z, bw.w);
                }
                float h0 = fmaxf(hh[0] + lh[0] + hl[0], 0.f);
                float h1 = fmaxf(hh[1] + lh[1] + hl[1], 0.f);
                float h2 = fmaxf(hh[2] + lh[2] + hl[2], 0.f);
                float h3 = fmaxf(hh[3] + lh[3] + hl[3], 0.f);
                // C-frag -> layer-2 A-frag (identity mapping within the thread)
                split2(h0, h1, ah[2 * halfn],     al[2 * halfn]);
                split2(h2, h3, ah[2 * halfn + 1], al[2 * halfn + 1]);
            }
            // layer 2: 4 nf x 3 split terms
#pragma unroll
            for (int nf = 0; nf < 4; nf++) {
                uint4 bw = gW2p[((((chunk * 4 + ksp) * 4 + nf)) << 5) + lane];
                mma_bf16(OUThh[nf], ah[0], ah[1], ah[2], ah[3], bw.x, bw.y);
                mma_bf16(OUTc[nf],  al[0], al[1], al[2], al[3], bw.x, bw.y);
                mma_bf16(OUTc[nf],  ah[0], ah[1], ah[2], ah[3], bw.z, bw.w);
            }
        }
    }

    // ---- write OUT to smem (sO reuses sA space, pitch 33) then coalesced global write ----
    float* sO = smf;
#pragma unroll
    for (int nf = 0; nf < 4; nf++) {
        int col = nf * 8 + 2 * tig;
        sO[arow0 * 33 + col]     = OUThh[nf][0] + OUTc[nf][0];
        sO[arow0 * 33 + col + 1] = OUThh[nf][1] + OUTc[nf][1];
        sO[arow1 * 33 + col]     = OUThh[nf][2] + OUTc[nf][2];
        sO[arow1 * 33 + col + 1] = OUThh[nf][3] + OUTc[nf][3];
    }
    __syncthreads();

    const int r = blk & 127;
    float s1 = 0.f, q1 = 0.f, s2 = 0.f, q2 = 0.f;
    for (int i = tid; i < 2048; i += 256) {
        int h = i >> 7, cc = i & 127;
        float m1 = sO[cc * 33 + 2 * h];
        float m2 = sO[cc * 33 + 2 * h + 1];
        g_ms1[((b * 16 + h) * 128 + r) * 128 + cc] = m1;
        g_ms2[((b * 16 + h) * 128 + r) * 128 + cc] = m2;
        s1 += m1; q1 += m1 * m1; s2 += m2; q2 += m2 * m2;
    }

    float v[4] = {s1, q1, s2, q2};
#pragma unroll
    for (int i = 0; i < 4; i++)
        for (int off = 16; off; off >>= 1) v[i] += __shfl_xor_sync(0xffffffffu, v[i], off);
    __shared__ float red[4][8];
    if (lane == 0) { red[0][warp] = v[0]; red[1][warp] = v[1]; red[2][warp] = v[2]; red[3][warp] = v[3]; }
    __syncthreads();
    if (tid == 0) {
#pragma unroll
        for (int i = 0; i < 4; i++) {
            float s = 0.f;
#pragma unroll
            for (int j = 0; j < 8; j++) s += red[i][j];
            g_part[blk * 4 + i] = s;
        }
    }
}

// ---------------- K4: std reduction (ddof=1) ----------------
__global__ void k_std() {
    __shared__ double sh[4][128];
    const int tid = threadIdx.x;  // 128
    double a0 = 0, a1 = 0, a2 = 0, a3 = 0;
    for (int i = tid; i < 1024; i += 128) {
        const float* p = g_part + i * 4;
        a0 += p[0]; a1 += p[1]; a2 += p[2]; a3 += p[3];
    }
    sh[0][tid] = a0; sh[1][tid] = a1; sh[2][tid] = a2; sh[3][tid] = a3;
    __syncthreads();
    for (int o = 64; o; o >>= 1) {
        if (tid < o) {
#pragma unroll
            for (int i = 0; i < 4; i++) sh[i][tid] += sh[i][tid + o];
        }
        __syncthreads();
    }
    if (tid == 0) {
        const double N = 2097152.0;
        double v1 = (sh[1][0] - sh[0][0] * sh[0][0] / N) / (N - 1.0);
        double v2 = (sh[3][0] - sh[2][0] * sh[2][0] / N) / (N - 1.0);
        g_stats[0] = (float)(1.0 / sqrt(v1));
        g_stats[1] = (float)(1.0 / sqrt(v2));
    }
}

// ---------------- K5: merged attention (blocks 0..255 = h1 path, 256..511 = h2 path) ----------------
#define SM_ATT (14848 * 4)
__global__ void k_attn() {
    extern __shared__ float sm[];
    const int tid = threadIdx.x;     // 256

    if (blockIdx.x < 256) {
        // ---- h1: softmax over c ----
        float* sl = sm;            // [64 r][128 c]
        float* sv = sm + 8192;     // v2 plane [128 c][16 d]
        const int blk = blockIdx.x;
        const int p = blk >> 1, rh = blk & 1;
        const float inv = g_stats[0];
        const float* mp = g_ms1 + p * 16384 + rh * 8192;
        for (int idx = tid; idx < 8192; idx += 256) sl[idx] = 10.f * fast_tanh(mp[idx] * inv);
        const float* vp = g_v2 + p * 2048;
        for (int idx = tid; idx < 2048; idx += 256) sv[idx] = vp[idx];
        __syncthreads();

        const int w = tid >> 5, lane = tid & 31;
#pragma unroll
        for (int i = 0; i < 8; i++) {
            int r = w * 8 + i;
            float* row = sl + r * 128;
            float m = fmaxf(fmaxf(row[lane], row[lane + 32]), fmaxf(row[lane + 64], row[lane + 96]));
#pragma unroll
            for (int off = 16; off; off >>= 1) m = fmaxf(m, __shfl_xor_sync(0xffffffffu, m, off));
            float s = 0.f;
#pragma unroll
            for (int t = 0; t < 4; t++) {
                int cc = lane + t * 32;
                float e = __expf(row[cc] - m);
                row[cc] = e; s += e;
            }
#pragma unroll
            for (int off = 16; off; off >>= 1) s += __shfl_xor_sync(0xffffffffu, s, off);
            float is = 1.f / s;
#pragma unroll
            for (int t = 0; t < 4; t++) row[lane + t * 32] *= is;
        }
        __syncthreads();

        const int r = tid >> 2, d0 = (tid & 3) << 2;
        float a0 = 0.f, a1 = 0.f, a2 = 0.f, a3 = 0.f;
#pragma unroll 4
        for (int cc = 0; cc < 128; cc++) {
            float wgt = sl[r * 128 + cc];
            float4 v = *(const float4*)(sv + cc * 16 + d0);
            a0 += wgt * v.x; a1 += wgt * v.y; a2 += wgt * v.z; a3 += wgt * v.w;
        }
        const int b = p >> 4, h = p & 15;
        float* out = g_attn1 + (b * 128 + rh * 64 + r) * 256 + h * 16 + d0;
        *(float4*)out = make_float4(a0, a1, a2, a3);
    } else {
        // ---- h2: softmax over r, logits transposed ----
        float* sl   = sm;               // [128 r][64 c]
        float* sv   = sm + 8192;        // v1 plane [128 r][16 d]
        float* pr   = sm + 10240;       // [4 seg][64 c][16 d]
        float* redm = sm + 14336;       // [4 seg][64 c]
        float* reds = sm + 14592;       // [4 seg][64 c]
        const int blk = blockIdx.x - 256;
        const int p = blk >> 1, ch = blk & 1;
        const float inv = g_stats[1];
        const float* mp = g_ms2 + p * 16384 + ch * 64;
        for (int idx = tid; idx < 8192; idx += 256)
            sl[idx] = 10.f * fast_tanh(mp[(idx >> 6) * 128 + (idx & 63)] * inv);
        const float* vp = g_v1 + p * 2048;
        for (int idx = tid; idx < 2048; idx += 256) sv[idx] = vp[idx];
        __syncthreads();

        const int c = tid & 63, seg = tid >> 6;   // seg owns rows [seg*32, seg*32+32)
        float m = -1e30f;
#pragma unroll 4
        for (int i = 0; i < 32; i++) m = fmaxf(m, sl[(seg * 32 + i) * 64 + c]);
        redm[seg * 64 + c] = m;
        __syncthreads();
        m = fmaxf(fmaxf(redm[c], redm[64 + c]), fmaxf(redm[128 + c], redm[192 + c]));
        float s = 0.f;
#pragma unroll 4
        for (int i = 0; i < 32; i++) {
            int rr = seg * 32 + i;
            float e = __expf(sl[rr * 64 + c] - m);
            sl[rr * 64 + c] = e; s += e;
        }
        reds[seg * 64 + c] = s;

        float acc[16];
#pragma unroll
        for (int j = 0; j < 16; j++) acc[j] = 0.f;
#pragma unroll 2
        for (int i = 0; i < 32; i++) {
            int rr = seg * 32 + i;
            float wgt = sl[rr * 64 + c];
            const float4* v = (const float4*)(sv + rr * 16);
            float4 v0 = v[0], v1 = v[1], v2 = v[2], v3 = v[3];
            acc[0] += wgt * v0.x; acc[1] += wgt * v0.y; acc[2] += wgt * v0.z; acc[3] += wgt * v0.w;
            acc[4] += wgt * v1.x; acc[5] += wgt * v1.y; acc[6] += wgt * v1.z; acc[7] += wgt * v1.w;
            acc[8] += wgt * v2.x; acc[9] += wgt * v2.y; acc[10] += wgt * v2.z; acc[11] += wgt * v2.w;
            acc[12] += wgt * v3.x; acc[13] += wgt * v3.y; acc[14] += wgt * v3.z; acc[15] += wgt * v3.w;
        }
        float* prp = pr + (seg * 64 + c) * 16;
#pragma unroll
        for (int j = 0; j < 4; j++)
            *(float4*)(prp + j * 4) = make_float4(acc[j * 4], acc[j * 4 + 1], acc[j * 4 + 2], acc[j * 4 + 3]);
        __syncthreads();

        const int b = p >> 4, h = p & 15;
        for (int o = tid; o < 1024; o += 256) {
            int cc = o >> 4, d = o & 15;
            float v = pr[(cc) * 16 + d] + pr[(64 + cc) * 16 + d]
                    + pr[(128 + cc) * 16 + d] + pr[(192 + cc) * 16 + d];
            float stot = reds[cc] + reds[64 + cc] + reds[128 + cc] + reds[192 + cc];
            g_attn2[(b * 128 + ch * 64 + cc) * 256 + h * 16 + d] = v / stot;
        }
    }
}

// ---------------- K6: output projections ----------------
#define SM_OUT ((32 * 260 + 256 * 64) * 4)
__global__ void k_out(const float* __restrict__ o1w, const float* __restrict__ o2w,
                      float* __restrict__ out) {
    extern __shared__ float smo[];
    float* sA = smo;
    float* sB = smo + 32 * 260;
    const int m0 = blockIdx.x * 32, n0 = blockIdx.y * 64;
    const bool first = (m0 < 1024);
    const float* A = first ? g_attn1 : g_attn2;
    const float* W = first ? o1w : o2w;
    float* dst = out + (first ? 0 : 262144);
    const int mm = m0 & 1023;
    const int tid = threadIdx.x;

    for (int idx = tid; idx < 2048; idx += 256) {
        int row = idx >> 6, kk = (idx & 63) << 2;
        float4 v = *(const float4*)(A + (mm + row) * 256 + kk);
        *(float4*)(sA + row * 260 + kk) = v;
    }
    for (int idx = tid; idx < 4096; idx += 256) {
        int row = idx >> 4, c4 = (idx & 15) << 2;
        float4 v = *(const float4*)(W + row * 256 + n0 + c4);
        *(float4*)(sB + row * 64 + c4) = v;
    }
    __syncthreads();

    const int r = tid >> 3, cg = tid & 7;
    float acc[8];
#pragma unroll
    for (int j = 0; j < 8; j++) acc[j] = 0.f;
    const float4* sB4 = (const float4*)sB;
#pragma unroll 4
    for (int k = 0; k < 256; k++) {
        float a = sA[r * 260 + k];
        float4 b0 = sB4[k * 16 + cg * 2];
        float4 b1 = sB4[k * 16 + cg * 2 + 1];
        acc[0] += a * b0.x; acc[1] += a * b0.y; acc[2] += a * b0.z; acc[3] += a * b0.w;
        acc[4] += a * b1.x; acc[5] += a * b1.y; acc[6] += a * b1.z; acc[7] += a * b1.w;
    }
    float* o = dst + (mm + r) * 256 + n0 + cg * 8;
    *(float4*)(o) = make_float4(acc[0], acc[1], acc[2], acc[3]);
    *(float4*)(o + 4) = make_float4(acc[4], acc[5], acc[6], acc[7]);
}

// ---------------- launch ----------------
extern "C" void kernel_launch(void* const* d_in, const int* in_sizes, int n_in,
                              void* d_out, int out_size) {
    const float* x1   = (const float*)d_in[0];
    const float* x2   = (const float*)d_in[1];
    const float* cost = (const float*)d_in[2];
    const float* Wqv1 = (const float*)d_in[3];
    const float* lin1 = (const float*)d_in[4];
    const float* lin2 = (const float*)d_in[5];
    const float* o1w  = (const float*)d_in[6];
    const float* o2w  = (const float*)d_in[7];
    float* out = (float*)d_out;

    cudaFuncSetAttribute(k_qkv,  cudaFuncAttributeMaxDynamicSharedMemorySize, SM_QKV);
    cudaFuncSetAttribute(k_mlp,  cudaFuncAttributeMaxDynamicSharedMemorySize, SM_MLP);
    cudaFuncSetAttribute(k_attn, cudaFuncAttributeMaxDynamicSharedMemorySize, SM_ATT);
    cudaFuncSetAttribute(k_out,  cudaFuncAttributeMaxDynamicSharedMemorySize, SM_OUT);

    // keep k_mlp in the profiler's capture slot (4th launch)
    k_qkv<<<dim3(64, 8), 256, SM_QKV>>>(x1, x2, Wqv1);   // 1
    k_prep<<<32, 256>>>(lin1, lin2);                      // 2
    k_nop<<<1, 32>>>();                                   // 3
    k_mlp<<<1024, 256, SM_MLP>>>(cost);                   // 4  <- profiled
    k_std<<<1, 128>>>();                                  // 5
    k_attn<<<512, 256, SM_ATT>>>();                       // 6
    k_out<<<dim3(64, 4), 256, SM_OUT>>>(o1w, o2w, out);   // 7

    (void)in_sizes; (void)n_in; (void)out_size;
}

// round 13
// speedup vs baseline: 1.6975x; 1.3045x over previous
#include <cuda_runtime.h>
#include <math.h>
#include <stdint.h>

typedef unsigned long long ull;

// ---------------- scratch (device globals; no allocations allowed) ----------------
__device__ float g_qT  [1024 * 256];      // [b*128+r][e]   e = h*16+d
__device__ float g_kTT [8 * 256 * 128];   // [b][e][c]
__device__ float g_v1  [1024 * 256];      // [b][h][s][d]
__device__ float g_v2  [1024 * 256];      // [b][h][s][d]
__device__ float g_ms1 [2097152];         // [b][h][r][c]
__device__ float g_ms2 [2097152];         // [b][h][r][c]
__device__ float g_attn1[1024 * 256];     // [b*128+r][h*16+d]
__device__ float g_attn2[1024 * 256];     // [b*128+c][h*16+d]
__device__ float g_part[1024 * 4];        // per-block {s1,q1,s2,q2}
__device__ float g_stats[2];              // inv_std1, inv_std2
// bf16 hi/lo frag-packed weights: per fragment+lane uint4 {b0hi, b1hi, b0lo, b1lo}
__device__ uint4 gW1p[128 * 32];
__device__ uint4 gW2p[128 * 32];

// ---------------- helpers ----------------
__device__ __forceinline__ float fast_tanh(float x) {
    return 1.f - 2.f / (__expf(2.f * x) + 1.f);
}
__device__ __forceinline__ uint32_t packbf(float fu, float fl) {
    uint32_t r; asm("cvt.rn.bf16x2.f32 %0, %1, %2;" : "=r"(r) : "f"(fu), "f"(fl));
    return r;
}
__device__ __forceinline__ void split2(float x0, float x1, uint32_t& hi, uint32_t& lo) {
    hi = packbf(x1, x0);
    float h0 = __uint_as_float(hi << 16);
    float h1 = __uint_as_float(hi & 0xffff0000u);
    lo = packbf(x1 - h1, x0 - h0);
}
__device__ __forceinline__ void mma_bf16(float* c,
                                         uint32_t a0, uint32_t a1, uint32_t a2, uint32_t a3,
                                         uint32_t b0, uint32_t b1) {
    asm volatile(
        "mma.sync.aligned.m16n8k16.row.col.f32.bf16.bf16.f32 "
        "{%0,%1,%2,%3}, {%4,%5,%6,%7}, {%8,%9}, {%0,%1,%2,%3};"
        : "+f"(c[0]), "+f"(c[1]), "+f"(c[2]), "+f"(c[3])
        : "r"(a0), "r"(a1), "r"(a2), "r"(a3), "r"(b0), "r"(b1));
}

__global__ void k_nop() {}

// ---------------- K0: pack W1/W2 into bf16 hi/lo fragment uint4s ----------------
__global__ void k_prep(const float* __restrict__ w1, const float* __restrict__ w2) {
    int idx = blockIdx.x * 256 + threadIdx.x;   // 0..8191
    if (idx >= 8192) return;
    int sel  = idx >> 12;
    int f    = idx & 4095;
    int lane = f & 31;
    int frag = f >> 5;            // 0..127
    int g = lane >> 2, tig = lane & 3;
    float k0, k1, k8, k9;
    if (sel == 0) {
        int ks2 = frag & 1, cn = frag >> 1;
        int n = cn * 8 + g;
        int kb = ks2 * 16 + 2 * tig;
        k0 = w1[kb * 512 + n];       k1 = w1[(kb + 1) * 512 + n];
        k8 = w1[(kb + 8) * 512 + n]; k9 = w1[(kb + 9) * 512 + n];
    } else {
        int nf = frag & 3, ck = frag >> 2;
        int n = nf * 8 + g;
        int kb = ck * 16 + 2 * tig;
        k0 = w2[kb * 32 + n];        k1 = w2[(kb + 1) * 32 + n];
        k8 = w2[(kb + 8) * 32 + n];  k9 = w2[(kb + 9) * 32 + n];
    }
    uint32_t h0, l0, h1, l1;
    split2(k0, k1, h0, l0);
    split2(k8, k9, h1, l1);
    uint4 v = make_uint4(h0, h1, l0, l1);
    if (sel == 0) gW1p[frag * 32 + lane] = v;
    else          gW2p[frag * 32 + lane] = v;
}

// ---------------- K1: qkv projection GEMM ----------------
// M=2048, N=512, K=256. 64x64 tiles, K chunked x128, 16 outputs/thread.
#define SM_QKV ((64 * 132 + 128 * 64) * 4)
__global__ void k_qkv(const float* __restrict__ x1, const float* __restrict__ x2,
                      const float* __restrict__ W) {
    extern __shared__ float smq[];
    float* sA = smq;               // [64][132]
    float* sB = smq + 64 * 132;    // [128][64]
    const int m0 = blockIdx.x * 64, n0 = blockIdx.y * 64;
    const bool isX1 = (m0 < 1024);
    const float* src = isX1 ? x1 : x2;
    const int mm = m0 & 1023;
    const int b = mm >> 7, s0 = mm & 127;
    const int tid = threadIdx.x;
    const int r = tid >> 3, cg = tid & 7;

    float acc[16];
#pragma unroll
    for (int j = 0; j < 16; j++) acc[j] = 0.f;

    for (int kc = 0; kc < 256; kc += 128) {
        for (int idx = tid; idx < 2048; idx += 256) {
            int row = idx >> 5, k4 = (idx & 31) << 2;
            float4 v = *(const float4*)(src + (b * 128 + s0 + row) * 256 + kc + k4);
            *(float4*)(sA + row * 132 + k4) = v;
        }
        for (int idx = tid; idx < 2048; idx += 256) {
            int row = idx >> 4, c4 = (idx & 15) << 2;
            float4 v = *(const float4*)(W + (kc + row) * 512 + n0 + c4);
            *(float4*)(sB + row * 64 + c4) = v;
        }
        __syncthreads();

        const float4* sB4 = (const float4*)sB;
#pragma unroll 4
        for (int k = 0; k < 128; k++) {
            float a0 = sA[r * 132 + k];
            float a1 = sA[(r + 32) * 132 + k];
            float4 b0 = sB4[k * 16 + cg * 2];
            float4 b1 = sB4[k * 16 + cg * 2 + 1];
            acc[0] += a0 * b0.x; acc[1] += a0 * b0.y; acc[2] += a0 * b0.z; acc[3] += a0 * b0.w;
            acc[4] += a0 * b1.x; acc[5] += a0 * b1.y; acc[6] += a0 * b1.z; acc[7] += a0 * b1.w;
            acc[8]  += a1 * b0.x; acc[9]  += a1 * b0.y; acc[10] += a1 * b0.z; acc[11] += a1 * b0.w;
            acc[12] += a1 * b1.x; acc[13] += a1 * b1.y; acc[14] += a1 * b1.z; acc[15] += a1 * b1.w;
        }
        __syncthreads();
    }

#pragma unroll
    for (int rr = 0; rr < 2; rr++) {
        int s = s0 + r + rr * 32;
#pragma unroll
        for (int j = 0; j < 8; j++) {
            int n = n0 + cg * 8 + j;
            float v = acc[rr * 8 + j];
            if (n < 256) {
                if (isX1) g_qT[(b * 128 + s) * 256 + n] = v;
                else      g_kTT[(b * 256 + n) * 128 + s] = v;
            } else {
                int h = (n - 256) >> 4, d = n & 15;
                float* dst = isX1 ? g_v1 : g_v2;
                dst[((b * 16 + h) * 128 + s) * 16 + d] = v;
            }
        }
    }
}

// ---------------- K3: bf16-split tensor-core fused dot + MixedScoreFF MLP ----------------
// (validated R12: 82.7 us, rel_err 1.565e-5 — unchanged)
#define SM_MLP 81920
__global__ void __launch_bounds__(256, 2)
k_mlp(const float* __restrict__ cost) {
    extern __shared__ float smf[];
    float* sA = smf;                      // [128][36] staging; reused as sO [128][33]
    float* sq = smf + 4608;               // [256]

    const int blk = blockIdx.x;           // b*128 + r
    const int b = blk >> 7;
    const int tid = threadIdx.x;
    const int warp = tid >> 5, lane = tid & 31;
    const int g = lane >> 2, tig = lane & 3;

    sq[tid] = g_qT[(blk << 8) + tid];
    __syncthreads();

    {
        const int c = tid & 127, half = tid >> 7;
        float cv = cost[blk * 128 + c];
        const float* kb = g_kTT + b * 32768 + c;
#pragma unroll
        for (int hh = 0; hh < 8; hh++) {
            int h = half * 8 + hh;
            float a = 0.f;
#pragma unroll
            for (int d = 0; d < 16; d++)
                a += sq[h * 16 + d] * kb[(h * 16 + d) * 128];
            sA[c * 36 + 2 * h] = a * 0.25f;
            sA[c * 36 + 2 * h + 1] = cv;
        }
    }
    __syncthreads();

    const int arow0 = warp * 16 + g, arow1 = arow0 + 8;
    uint32_t Ahi[2][4], Alo[2][4];
#pragma unroll
    for (int ks2 = 0; ks2 < 2; ks2++) {
        int cb = ks2 * 16 + 2 * tig;
        split2(sA[arow0 * 36 + cb],     sA[arow0 * 36 + cb + 1], Ahi[ks2][0], Alo[ks2][0]);
        split2(sA[arow1 * 36 + cb],     sA[arow1 * 36 + cb + 1], Ahi[ks2][1], Alo[ks2][1]);
        split2(sA[arow0 * 36 + cb + 8], sA[arow0 * 36 + cb + 9], Ahi[ks2][2], Alo[ks2][2]);
        split2(sA[arow1 * 36 + cb + 8], sA[arow1 * 36 + cb + 9], Ahi[ks2][3], Alo[ks2][3]);
    }
    __syncthreads();

    float OUThh[4][4], OUTc[4][4];
#pragma unroll
    for (int i = 0; i < 4; i++)
#pragma unroll
        for (int j = 0; j < 4; j++) { OUThh[i][j] = 0.f; OUTc[i][j] = 0.f; }

    for (int chunk = 0; chunk < 8; chunk++) {
#pragma unroll
        for (int ksp = 0; ksp < 4; ksp++) {
            uint32_t ah[4], al[4];
#pragma unroll
            for (int halfn = 0; halfn < 2; halfn++) {
                int nfp = 2 * ksp + halfn;
                float hh[4] = {0.f, 0.f, 0.f, 0.f};
                float lh[4] = {0.f, 0.f, 0.f, 0.f};
                float hl[4] = {0.f, 0.f, 0.f, 0.f};
#pragma unroll
                for (int ks2 = 0; ks2 < 2; ks2++) {
                    uint4 bw = gW1p[((((chunk * 8 + nfp) * 2 + ks2)) << 5) + lane];
                    mma_bf16(hh, Ahi[ks2][0], Ahi[ks2][1], Ahi[ks2][2], Ahi[ks2][3], bw.x, bw.y);
                    mma_bf16(lh, Alo[ks2][0], Alo[ks2][1], Alo[ks2][2], Alo[ks2][3], bw.x, bw.y);
                    mma_bf16(hl, Ahi[ks2][0], Ahi[ks2][1], Ahi[ks2][2], Ahi[ks2][3], bw.z, bw.w);
                }
                float h0 = fmaxf(hh[0] + lh[0] + hl[0], 0.f);
                float h1 = fmaxf(hh[1] + lh[1] + hl[1], 0.f);
                float h2 = fmaxf(hh[2] + lh[2] + hl[2], 0.f);
                float h3 = fmaxf(hh[3] + lh[3] + hl[3], 0.f);
                split2(h0, h1, ah[2 * halfn],     al[2 * halfn]);
                split2(h2, h3, ah[2 * halfn + 1], al[2 * halfn + 1]);
            }
#pragma unroll
            for (int nf = 0; nf < 4; nf++) {
                uint4 bw = gW2p[((((chunk * 4 + ksp) * 4 + nf)) << 5) + lane];
                mma_bf16(OUThh[nf], ah[0], ah[1], ah[2], ah[3], bw.x, bw.y);
                mma_bf16(OUTc[nf],  al[0], al[1], al[2], al[3], bw.x, bw.y);
                mma_bf16(OUTc[nf],  ah[0], ah[1], ah[2], ah[3], bw.z, bw.w);
            }
        }
    }

    float* sO = smf;
#pragma unroll
    for (int nf = 0; nf < 4; nf++) {
        int col = nf * 8 + 2 * tig;
        sO[arow0 * 33 + col]     = OUThh[nf][0] + OUTc[nf][0];
        sO[arow0 * 33 + col + 1] = OUThh[nf][1] + OUTc[nf][1];
        sO[arow1 * 33 + col]     = OUThh[nf][2] + OUTc[nf][2];
        sO[arow1 * 33 + col + 1] = OUThh[nf][3] + OUTc[nf][3];
    }
    __syncthreads();

    const int r = blk & 127;
    float s1 = 0.f, q1 = 0.f, s2 = 0.f, q2 = 0.f;
    for (int i = tid; i < 2048; i += 256) {
        int h = i >> 7, cc = i & 127;
        float m1 = sO[cc * 33 + 2 * h];
        float m2 = sO[cc * 33 + 2 * h + 1];
        g_ms1[((b * 16 + h) * 128 + r) * 128 + cc] = m1;
        g_ms2[((b * 16 + h) * 128 + r) * 128 + cc] = m2;
        s1 += m1; q1 += m1 * m1; s2 += m2; q2 += m2 * m2;
    }

    float v[4] = {s1, q1, s2, q2};
#pragma unroll
    for (int i = 0; i < 4; i++)
        for (int off = 16; off; off >>= 1) v[i] += __shfl_xor_sync(0xffffffffu, v[i], off);
    __shared__ float red[4][8];
    if (lane == 0) { red[0][warp] = v[0]; red[1][warp] = v[1]; red[2][warp] = v[2]; red[3][warp] = v[3]; }
    __syncthreads();
    if (tid == 0) {
#pragma unroll
        for (int i = 0; i < 4; i++) {
            float s = 0.f;
#pragma unroll
            for (int j = 0; j < 8; j++) s += red[i][j];
            g_part[blk * 4 + i] = s;
        }
    }
}

// ---------------- K4: std reduction (ddof=1) ----------------
__global__ void k_std() {
    __shared__ double sh[4][128];
    const int tid = threadIdx.x;  // 128
    double a0 = 0, a1 = 0, a2 = 0, a3 = 0;
    for (int i = tid; i < 1024; i += 128) {
        const float* p = g_part + i * 4;
        a0 += p[0]; a1 += p[1]; a2 += p[2]; a3 += p[3];
    }
    sh[0][tid] = a0; sh[1][tid] = a1; sh[2][tid] = a2; sh[3][tid] = a3;
    __syncthreads();
    for (int o = 64; o; o >>= 1) {
        if (tid < o) {
#pragma unroll
            for (int i = 0; i < 4; i++) sh[i][tid] += sh[i][tid + o];
        }
        __syncthreads();
    }
    if (tid == 0) {
        const double N = 2097152.0;
        double v1 = (sh[1][0] - sh[0][0] * sh[0][0] / N) / (N - 1.0);
        double v2 = (sh[3][0] - sh[2][0] * sh[2][0] / N) / (N - 1.0);
        g_stats[0] = (float)(1.0 / sqrt(v1));
        g_stats[1] = (float)(1.0 / sqrt(v2));
    }
}

// ---------------- K5: merged attention (blocks 0..255 = h1 path, 256..511 = h2 path) ----------------
#define SM_ATT (14848 * 4)
__global__ void k_attn() {
    extern __shared__ float sm[];
    const int tid = threadIdx.x;     // 256

    if (blockIdx.x < 256) {
        float* sl = sm;            // [64 r][128 c]
        float* sv = sm + 8192;     // v2 plane [128 c][16 d]
        const int blk = blockIdx.x;
        const int p = blk >> 1, rh = blk & 1;
        const float inv = g_stats[0];
        const float* mp = g_ms1 + p * 16384 + rh * 8192;
        for (int idx = tid; idx < 8192; idx += 256) sl[idx] = 10.f * fast_tanh(mp[idx] * inv);
        const float* vp = g_v2 + p * 2048;
        for (int idx = tid; idx < 2048; idx += 256) sv[idx] = vp[idx];
        __syncthreads();

        const int w = tid >> 5, lane = tid & 31;
#pragma unroll
        for (int i = 0; i < 8; i++) {
            int r = w * 8 + i;
            float* row = sl + r * 128;
            float m = fmaxf(fmaxf(row[lane], row[lane + 32]), fmaxf(row[lane + 64], row[lane + 96]));
#pragma unroll
            for (int off = 16; off; off >>= 1) m = fmaxf(m, __shfl_xor_sync(0xffffffffu, m, off));
            float s = 0.f;
#pragma unroll
            for (int t = 0; t < 4; t++) {
                int cc = lane + t * 32;
                float e = __expf(row[cc] - m);
                row[cc] = e; s += e;
            }
#pragma unroll
            for (int off = 16; off; off >>= 1) s += __shfl_xor_sync(0xffffffffu, s, off);
            float is = 1.f / s;
#pragma unroll
            for (int t = 0; t < 4; t++) row[lane + t * 32] *= is;
        }
        __syncthreads();

        const int r = tid >> 2, d0 = (tid & 3) << 2;
        float a0 = 0.f, a1 = 0.f, a2 = 0.f, a3 = 0.f;
#pragma unroll 4
        for (int cc = 0; cc < 128; cc++) {
            float wgt = sl[r * 128 + cc];
            float4 v = *(const float4*)(sv + cc * 16 + d0);
            a0 += wgt * v.x; a1 += wgt * v.y; a2 += wgt * v.z; a3 += wgt * v.w;
        }
        const int b = p >> 4, h = p & 15;
        float* out = g_attn1 + (b * 128 + rh * 64 + r) * 256 + h * 16 + d0;
        *(float4*)out = make_float4(a0, a1, a2, a3);
    } else {
        float* sl   = sm;               // [128 r][64 c]
        float* sv   = sm + 8192;        // v1 plane [128 r][16 d]
        float* pr   = sm + 10240;       // [4 seg][64 c][16 d]
        float* redm = sm + 14336;       // [4 seg][64 c]
        float* reds = sm + 14592;       // [4 seg][64 c]
        const int blk = blockIdx.x - 256;
        const int p = blk >> 1, ch = blk & 1;
        const float inv = g_stats[1];
        const float* mp = g_ms2 + p * 16384 + ch * 64;
        for (int idx = tid; idx < 8192; idx += 256)
            sl[idx] = 10.f * fast_tanh(mp[(idx >> 6) * 128 + (idx & 63)] * inv);
        const float* vp = g_v1 + p * 2048;
        for (int idx = tid; idx < 2048; idx += 256) sv[idx] = vp[idx];
        __syncthreads();

        const int c = tid & 63, seg = tid >> 6;
        float m = -1e30f;
#pragma unroll 4
        for (int i = 0; i < 32; i++) m = fmaxf(m, sl[(seg * 32 + i) * 64 + c]);
        redm[seg * 64 + c] = m;
        __syncthreads();
        m = fmaxf(fmaxf(redm[c], redm[64 + c]), fmaxf(redm[128 + c], redm[192 + c]));
        float s = 0.f;
#pragma unroll 4
        for (int i = 0; i < 32; i++) {
            int rr = seg * 32 + i;
            float e = __expf(sl[rr * 64 + c] - m);
            sl[rr * 64 + c] = e; s += e;
        }
        reds[seg * 64 + c] = s;

        float acc[16];
#pragma unroll
        for (int j = 0; j < 16; j++) acc[j] = 0.f;
#pragma unroll 2
        for (int i = 0; i < 32; i++) {
            int rr = seg * 32 + i;
            float wgt = sl[rr * 64 + c];
            const float4* v = (const float4*)(sv + rr * 16);
            float4 v0 = v[0], v1 = v[1], v2 = v[2], v3 = v[3];
            acc[0] += wgt * v0.x; acc[1] += wgt * v0.y; acc[2] += wgt * v0.z; acc[3] += wgt * v0.w;
            acc[4] += wgt * v1.x; acc[5] += wgt * v1.y; acc[6] += wgt * v1.z; acc[7] += wgt * v1.w;
            acc[8] += wgt * v2.x; acc[9] += wgt * v2.y; acc[10] += wgt * v2.z; acc[11] += wgt * v2.w;
            acc[12] += wgt * v3.x; acc[13] += wgt * v3.y; acc[14] += wgt * v3.z; acc[15] += wgt * v3.w;
        }
        float* prp = pr + (seg * 64 + c) * 16;
#pragma unroll
        for (int j = 0; j < 4; j++)
            *(float4*)(prp + j * 4) = make_float4(acc[j * 4], acc[j * 4 + 1], acc[j * 4 + 2], acc[j * 4 + 3]);
        __syncthreads();

        const int b = p >> 4, h = p & 15;
        for (int o = tid; o < 1024; o += 256) {
            int cc = o >> 4, d = o & 15;
            float v = pr[(cc) * 16 + d] + pr[(64 + cc) * 16 + d]
                    + pr[(128 + cc) * 16 + d] + pr[(192 + cc) * 16 + d];
            float stot = reds[cc] + reds[64 + cc] + reds[128 + cc] + reds[192 + cc];
            g_attn2[(b * 128 + ch * 64 + cc) * 256 + h * 16 + d] = v / stot;
        }
    }
}

// ---------------- K6: output projections ----------------
// M=2048, N=256, K=256. 64x64 tiles, K chunked x128, 16 outputs/thread.
#define SM_OUT ((64 * 132 + 128 * 64) * 4)
__global__ void k_out(const float* __restrict__ o1w, const float* __restrict__ o2w,
                      float* __restrict__ out) {
    extern __shared__ float smo[];
    float* sA = smo;               // [64][132]
    float* sB = smo + 64 * 132;    // [128][64]
    const int m0 = blockIdx.x * 64, n0 = blockIdx.y * 64;
    const bool first = (m0 < 1024);
    const float* A = first ? g_attn1 : g_attn2;
    const float* W = first ? o1w : o2w;
    float* dst = out + (first ? 0 : 262144);
    const int mm = m0 & 1023;
    const int tid = threadIdx.x;
    const int r = tid >> 3, cg = tid & 7;

    float acc[16];
#pragma unroll
    for (int j = 0; j < 16; j++) acc[j] = 0.f;

    for (int kc = 0; kc < 256; kc += 128) {
        for (int idx = tid; idx < 2048; idx += 256) {
            int row = idx >> 5, k4 = (idx & 31) << 2;
            float4 v = *(const float4*)(A + (mm + row) * 256 + kc + k4);
            *(float4*)(sA + row * 132 + k4) = v;
        }
        for (int idx = tid; idx < 2048; idx += 256) {
            int row = idx >> 4, c4 = (idx & 15) << 2;
            float4 v = *(const float4*)(W + (kc + row) * 256 + n0 + c4);
            *(float4*)(sB + row * 64 + c4) = v;
        }
        __syncthreads();

        const float4* sB4 = (const float4*)sB;
#pragma unroll 4
        for (int k = 0; k < 128; k++) {
            float a0 = sA[r * 132 + k];
            float a1 = sA[(r + 32) * 132 + k];
            float4 b0 = sB4[k * 16 + cg * 2];
            float4 b1 = sB4[k * 16 + cg * 2 + 1];
            acc[0] += a0 * b0.x; acc[1] += a0 * b0.y; acc[2] += a0 * b0.z; acc[3] += a0 * b0.w;
            acc[4] += a0 * b1.x; acc[5] += a0 * b1.y; acc[6] += a0 * b1.z; acc[7] += a0 * b1.w;
            acc[8]  += a1 * b0.x; acc[9]  += a1 * b0.y; acc[10] += a1 * b0.z; acc[11] += a1 * b0.w;
            acc[12] += a1 * b1.x; acc[13] += a1 * b1.y; acc[14] += a1 * b1.z; acc[15] += a1 * b1.w;
        }
        __syncthreads();
    }

#pragma unroll
    for (int rr = 0; rr < 2; rr++) {
        float* o = dst + (mm + r + rr * 32) * 256 + n0 + cg * 8;
        *(float4*)(o)     = make_float4(acc[rr * 8],     acc[rr * 8 + 1], acc[rr * 8 + 2], acc[rr * 8 + 3]);
        *(float4*)(o + 4) = make_float4(acc[rr * 8 + 4], acc[rr * 8 + 5], acc[rr * 8 + 6], acc[rr * 8 + 7]);
    }
}

// ---------------- launch ----------------
extern "C" void kernel_launch(void* const* d_in, const int* in_sizes, int n_in,
                              void* d_out, int out_size) {
    const float* x1   = (const float*)d_in[0];
    const float* x2   = (const float*)d_in[1];
    const float* cost = (const float*)d_in[2];
    const float* Wqv1 = (const float*)d_in[3];
    const float* lin1 = (const float*)d_in[4];
    const float* lin2 = (const float*)d_in[5];
    const float* o1w  = (const float*)d_in[6];
    const float* o2w  = (const float*)d_in[7];
    float* out = (float*)d_out;

    cudaFuncSetAttribute(k_qkv,  cudaFuncAttributeMaxDynamicSharedMemorySize, SM_QKV);
    cudaFuncSetAttribute(k_mlp,  cudaFuncAttributeMaxDynamicSharedMemorySize, SM_MLP);
    cudaFuncSetAttribute(k_attn, cudaFuncAttributeMaxDynamicSharedMemorySize, SM_ATT);
    cudaFuncSetAttribute(k_out,  cudaFuncAttributeMaxDynamicSharedMemorySize, SM_OUT);

    // profiler slot 4 now captures the NEW k_qkv (k_mlp is stable/validated)
    k_prep<<<32, 256>>>(lin1, lin2);                      // 1
    k_nop<<<1, 32>>>();                                   // 2
    k_nop<<<1, 32>>>();                                   // 3
    k_qkv<<<dim3(32, 8), 256, SM_QKV>>>(x1, x2, Wqv1);    // 4  <- profiled
    k_mlp<<<1024, 256, SM_MLP>>>(cost);                   // 5
    k_std<<<1, 128>>>();                                  // 6
    k_attn<<<512, 256, SM_ATT>>>();                       // 7
    k_out<<<dim3(32, 4), 256, SM_OUT>>>(o1w, o2w, out);   // 8

    (void)in_sizes; (void)n_in; (void)out_size;
}

// round 14
// speedup vs baseline: 2.0241x; 1.1924x over previous
#include <cuda_runtime.h>
#include <math.h>
#include <stdint.h>

typedef unsigned long long ull;

// ---------------- scratch (device globals; no allocations allowed) ----------------
__device__ float g_qT  [1024 * 256];      // [b*128+r][e]   e = h*16+d
__device__ float g_kTT [8 * 256 * 128];   // [b][e][c]
__device__ float g_v1  [1024 * 256];      // [b][h][s][d]
__device__ float g_v2  [1024 * 256];      // [b][h][s][d]
__device__ float g_ms1 [2097152];         // [b][h][r][c]
__device__ float g_ms2 [2097152];         // [b][h][r][c]
__device__ float g_attn1[1024 * 256];     // [b*128+r][h*16+d]
__device__ float g_attn2[1024 * 256];     // [b*128+c][h*16+d]
__device__ float g_part[1024 * 4];        // per-block {s1,q1,s2,q2}
__device__ float g_stats[2];              // inv_std1, inv_std2
// bf16 hi/lo frag-packed weights: per fragment+lane uint4 {b0hi, b1hi, b0lo, b1lo}
__device__ uint4 gW1p[128 * 32];
__device__ uint4 gW2p[128 * 32];
__device__ uint4 gWqv[1024 * 32];         // Wqv1 [256][512]: frag = kstep*64 + nfr

// ---------------- helpers ----------------
__device__ __forceinline__ float fast_tanh(float x) {
    return 1.f - 2.f / (__expf(2.f * x) + 1.f);
}
__device__ __forceinline__ uint32_t packbf(float fu, float fl) {
    uint32_t r; asm("cvt.rn.bf16x2.f32 %0, %1, %2;" : "=r"(r) : "f"(fu), "f"(fl));
    return r;
}
__device__ __forceinline__ void split2(float x0, float x1, uint32_t& hi, uint32_t& lo) {
    hi = packbf(x1, x0);
    float h0 = __uint_as_float(hi << 16);
    float h1 = __uint_as_float(hi & 0xffff0000u);
    lo = packbf(x1 - h1, x0 - h0);
}
__device__ __forceinline__ void mma_bf16(float* c,
                                         uint32_t a0, uint32_t a1, uint32_t a2, uint32_t a3,
                                         uint32_t b0, uint32_t b1) {
    asm volatile(
        "mma.sync.aligned.m16n8k16.row.col.f32.bf16.bf16.f32 "
        "{%0,%1,%2,%3}, {%4,%5,%6,%7}, {%8,%9}, {%0,%1,%2,%3};"
        : "+f"(c[0]), "+f"(c[1]), "+f"(c[2]), "+f"(c[3])
        : "r"(a0), "r"(a1), "r"(a2), "r"(a3), "r"(b0), "r"(b1));
}

__global__ void k_nop() {}

// ---------------- K0: pack W1/W2/Wqv1 into bf16 hi/lo fragment uint4s ----------------
__global__ void k_prep(const float* __restrict__ w1, const float* __restrict__ w2,
                       const float* __restrict__ wqv) {
    int idx = blockIdx.x * 256 + threadIdx.x;   // 0..40959
    if (idx < 8192) {
        int sel  = idx >> 12;
        int f    = idx & 4095;
        int lane = f & 31;
        int frag = f >> 5;            // 0..127
        int g = lane >> 2, tig = lane & 3;
        float k0, k1, k8, k9;
        if (sel == 0) {
            int ks2 = frag & 1, cn = frag >> 1;
            int n = cn * 8 + g;
            int kb = ks2 * 16 + 2 * tig;
            k0 = w1[kb * 512 + n];       k1 = w1[(kb + 1) * 512 + n];
            k8 = w1[(kb + 8) * 512 + n]; k9 = w1[(kb + 9) * 512 + n];
        } else {
            int nf = frag & 3, ck = frag >> 2;
            int n = nf * 8 + g;
            int kb = ck * 16 + 2 * tig;
            k0 = w2[kb * 32 + n];        k1 = w2[(kb + 1) * 32 + n];
            k8 = w2[(kb + 8) * 32 + n];  k9 = w2[(kb + 9) * 32 + n];
        }
        uint32_t h0, l0, h1, l1;
        split2(k0, k1, h0, l0);
        split2(k8, k9, h1, l1);
        uint4 v = make_uint4(h0, h1, l0, l1);
        if (sel == 0) gW1p[frag * 32 + lane] = v;
        else          gW2p[frag * 32 + lane] = v;
    } else if (idx < 40960) {
        int f = idx - 8192;
        int lane = f & 31;
        int frag = f >> 5;            // 0..1023: kstep*64 + nfr
        int kstep = frag >> 6, nfr = frag & 63;
        int g = lane >> 2, tig = lane & 3;
        int n = nfr * 8 + g;
        int kb = kstep * 16 + 2 * tig;
        float k0 = wqv[kb * 512 + n],       k1 = wqv[(kb + 1) * 512 + n];
        float k8 = wqv[(kb + 8) * 512 + n], k9 = wqv[(kb + 9) * 512 + n];
        uint32_t h0, l0, h1, l1;
        split2(k0, k1, h0, l0);
        split2(k8, k9, h1, l1);
        gWqv[frag * 32 + lane] = make_uint4(h0, h1, l0, l1);
    }
}

// ---------------- K1: qkv projection GEMM (bf16-split tensor cores) ----------------
// M=2048 (x1 rows then x2 rows), N=512, K=256. CTA = 64 m-rows x 64 n-cols.
// 8 warps: warp = (msub 0..3) x (nhalf 0..1); each warp 16 rows x 32 cols.
// Full A slab (64x256 fp32) staged once in smem; split at consume.
#define SM_QKV (64 * 260 * 4)
__global__ void __launch_bounds__(256)
k_qkv(const float* __restrict__ x1, const float* __restrict__ x2) {
    extern __shared__ float smq[];
    float* sA = smq;   // [64][260]
    const int m0 = blockIdx.x * 64, n0 = blockIdx.y * 64;
    const bool isX1 = (m0 < 1024);
    const float* src = isX1 ? x1 : x2;
    const int mm = m0 & 1023;
    const int b = mm >> 7, s0 = mm & 127;
    const int tid = threadIdx.x;
    const int warp = tid >> 5, lane = tid & 31;
    const int g = lane >> 2, tig = lane & 3;
    const int msub = warp >> 1, nhalf = warp & 1;

    for (int idx = tid; idx < 4096; idx += 256) {
        int row = idx >> 6, k4 = (idx & 63) << 2;
        float4 v = *(const float4*)(src + (b * 128 + s0 + row) * 256 + k4);
        *(float4*)(sA + row * 260 + k4) = v;
    }
    __syncthreads();

    const int arow0 = msub * 16 + g, arow1 = arow0 + 8;
    float acc[4][4], accC[4][4];
#pragma unroll
    for (int i = 0; i < 4; i++)
#pragma unroll
        for (int j = 0; j < 4; j++) { acc[i][j] = 0.f; accC[i][j] = 0.f; }

    const int nfr0 = (n0 >> 3) + nhalf * 4;
#pragma unroll 4
    for (int kk = 0; kk < 16; kk++) {
        int cb = kk * 16 + 2 * tig;
        uint32_t ah[4], al[4];
        split2(sA[arow0 * 260 + cb],     sA[arow0 * 260 + cb + 1], ah[0], al[0]);
        split2(sA[arow1 * 260 + cb],     sA[arow1 * 260 + cb + 1], ah[1], al[1]);
        split2(sA[arow0 * 260 + cb + 8], sA[arow0 * 260 + cb + 9], ah[2], al[2]);
        split2(sA[arow1 * 260 + cb + 8], sA[arow1 * 260 + cb + 9], ah[3], al[3]);
#pragma unroll
        for (int nf = 0; nf < 4; nf++) {
            uint4 bw = gWqv[((kk << 6) + nfr0 + nf) * 32 + lane];
            mma_bf16(acc[nf],  ah[0], ah[1], ah[2], ah[3], bw.x, bw.y);
            mma_bf16(accC[nf], al[0], al[1], al[2], al[3], bw.x, bw.y);
            mma_bf16(accC[nf], ah[0], ah[1], ah[2], ah[3], bw.z, bw.w);
        }
    }

    // store: C-frag (c0,c1)=(arow0, col/col+1), (c2,c3)=(arow1, col/col+1)
#pragma unroll
    for (int nf = 0; nf < 4; nf++) {
        int n = n0 + nhalf * 32 + nf * 8 + 2 * tig;
        float v[4] = {acc[nf][0] + accC[nf][0], acc[nf][1] + accC[nf][1],
                      acc[nf][2] + accC[nf][2], acc[nf][3] + accC[nf][3]};
#pragma unroll
        for (int q = 0; q < 4; q++) {
            int s = s0 + ((q >> 1) ? arow1 : arow0);
            int nn = n + (q & 1);
            float val = v[q];
            if (nn < 256) {
                if (isX1) g_qT[(b * 128 + s) * 256 + nn] = val;
                else      g_kTT[(b * 256 + nn) * 128 + s] = val;
            } else {
                int h = (nn - 256) >> 4, d = nn & 15;
                float* dst = isX1 ? g_v1 : g_v2;
                dst[((b * 16 + h) * 128 + s) * 16 + d] = val;
            }
        }
    }
}

// ---------------- K3: bf16-split tensor-core fused dot + MixedScoreFF MLP ----------------
// (validated R12: 82.7 us, rel_err 1.565e-5 — unchanged)
#define SM_MLP 81920
__global__ void __launch_bounds__(256, 2)
k_mlp(const float* __restrict__ cost) {
    extern __shared__ float smf[];
    float* sA = smf;                      // [128][36] staging; reused as sO [128][33]
    float* sq = smf + 4608;               // [256]

    const int blk = blockIdx.x;           // b*128 + r
    const int b = blk >> 7;
    const int tid = threadIdx.x;
    const int warp = tid >> 5, lane = tid & 31;
    const int g = lane >> 2, tig = lane & 3;

    sq[tid] = g_qT[(blk << 8) + tid];
    __syncthreads();

    {
        const int c = tid & 127, half = tid >> 7;
        float cv = cost[blk * 128 + c];
        const float* kb = g_kTT + b * 32768 + c;
#pragma unroll
        for (int hh = 0; hh < 8; hh++) {
            int h = half * 8 + hh;
            float a = 0.f;
#pragma unroll
            for (int d = 0; d < 16; d++)
                a += sq[h * 16 + d] * kb[(h * 16 + d) * 128];
            sA[c * 36 + 2 * h] = a * 0.25f;
            sA[c * 36 + 2 * h + 1] = cv;
        }
    }
    __syncthreads();

    const int arow0 = warp * 16 + g, arow1 = arow0 + 8;
    uint32_t Ahi[2][4], Alo[2][4];
#pragma unroll
    for (int ks2 = 0; ks2 < 2; ks2++) {
        int cb = ks2 * 16 + 2 * tig;
        split2(sA[arow0 * 36 + cb],     sA[arow0 * 36 + cb + 1], Ahi[ks2][0], Alo[ks2][0]);
        split2(sA[arow1 * 36 + cb],     sA[arow1 * 36 + cb + 1], Ahi[ks2][1], Alo[ks2][1]);
        split2(sA[arow0 * 36 + cb + 8], sA[arow0 * 36 + cb + 9], Ahi[ks2][2], Alo[ks2][2]);
        split2(sA[arow1 * 36 + cb + 8], sA[arow1 * 36 + cb + 9], Ahi[ks2][3], Alo[ks2][3]);
    }
    __syncthreads();

    float OUThh[4][4], OUTc[4][4];
#pragma unroll
    for (int i = 0; i < 4; i++)
#pragma unroll
        for (int j = 0; j < 4; j++) { OUThh[i][j] = 0.f; OUTc[i][j] = 0.f; }

    for (int chunk = 0; chunk < 8; chunk++) {
#pragma unroll
        for (int ksp = 0; ksp < 4; ksp++) {
            uint32_t ah[4], al[4];
#pragma unroll
            for (int halfn = 0; halfn < 2; halfn++) {
                int nfp = 2 * ksp + halfn;
                float hh[4] = {0.f, 0.f, 0.f, 0.f};
                float lh[4] = {0.f, 0.f, 0.f, 0.f};
                float hl[4] = {0.f, 0.f, 0.f, 0.f};
#pragma unroll
                for (int ks2 = 0; ks2 < 2; ks2++) {
                    uint4 bw = gW1p[((((chunk * 8 + nfp) * 2 + ks2)) << 5) + lane];
                    mma_bf16(hh, Ahi[ks2][0], Ahi[ks2][1], Ahi[ks2][2], Ahi[ks2][3], bw.x, bw.y);
                    mma_bf16(lh, Alo[ks2][0], Alo[ks2][1], Alo[ks2][2], Alo[ks2][3], bw.x, bw.y);
                    mma_bf16(hl, Ahi[ks2][0], Ahi[ks2][1], Ahi[ks2][2], Ahi[ks2][3], bw.z, bw.w);
                }
                float h0 = fmaxf(hh[0] + lh[0] + hl[0], 0.f);
                float h1 = fmaxf(hh[1] + lh[1] + hl[1], 0.f);
                float h2 = fmaxf(hh[2] + lh[2] + hl[2], 0.f);
                float h3 = fmaxf(hh[3] + lh[3] + hl[3], 0.f);
                split2(h0, h1, ah[2 * halfn],     al[2 * halfn]);
                split2(h2, h3, ah[2 * halfn + 1], al[2 * halfn + 1]);
            }
#pragma unroll
            for (int nf = 0; nf < 4; nf++) {
                uint4 bw = gW2p[((((chunk * 4 + ksp) * 4 + nf)) << 5) + lane];
                mma_bf16(OUThh[nf], ah[0], ah[1], ah[2], ah[3], bw.x, bw.y);
                mma_bf16(OUTc[nf],  al[0], al[1], al[2], al[3], bw.x, bw.y);
                mma_bf16(OUTc[nf],  ah[0], ah[1], ah[2], ah[3], bw.z, bw.w);
            }
        }
    }

    float* sO = smf;
#pragma unroll
    for (int nf = 0; nf < 4; nf++) {
        int col = nf * 8 + 2 * tig;
        sO[arow0 * 33 + col]     = OUThh[nf][0] + OUTc[nf][0];
        sO[arow0 * 33 + col + 1] = OUThh[nf][1] + OUTc[nf][1];
        sO[arow1 * 33 + col]     = OUThh[nf][2] + OUTc[nf][2];
        sO[arow1 * 33 + col + 1] = OUThh[nf][3] + OUTc[nf][3];
    }
    __syncthreads();

    const int r = blk & 127;
    float s1 = 0.f, q1 = 0.f, s2 = 0.f, q2 = 0.f;
    for (int i = tid; i < 2048; i += 256) {
        int h = i >> 7, cc = i & 127;
        float m1 = sO[cc * 33 + 2 * h];
        float m2 = sO[cc * 33 + 2 * h + 1];
        g_ms1[((b * 16 + h) * 128 + r) * 128 + cc] = m1;
        g_ms2[((b * 16 + h) * 128 + r) * 128 + cc] = m2;
        s1 += m1; q1 += m1 * m1; s2 += m2; q2 += m2 * m2;
    }

    float v[4] = {s1, q1, s2, q2};
#pragma unroll
    for (int i = 0; i < 4; i++)
        for (int off = 16; off; off >>= 1) v[i] += __shfl_xor_sync(0xffffffffu, v[i], off);
    __shared__ float red[4][8];
    if (lane == 0) { red[0][warp] = v[0]; red[1][warp] = v[1]; red[2][warp] = v[2]; red[3][warp] = v[3]; }
    __syncthreads();
    if (tid == 0) {
#pragma unroll
        for (int i = 0; i < 4; i++) {
            float s = 0.f;
#pragma unroll
            for (int j = 0; j < 8; j++) s += red[i][j];
            g_part[blk * 4 + i] = s;
        }
    }
}

// ---------------- K4: std reduction (ddof=1) ----------------
__global__ void k_std() {
    __shared__ double sh[4][128];
    const int tid = threadIdx.x;  // 128
    double a0 = 0, a1 = 0, a2 = 0, a3 = 0;
    for (int i = tid; i < 1024; i += 128) {
        const float* p = g_part + i * 4;
        a0 += p[0]; a1 += p[1]; a2 += p[2]; a3 += p[3];
    }
    sh[0][tid] = a0; sh[1][tid] = a1; sh[2][tid] = a2; sh[3][tid] = a3;
    __syncthreads();
    for (int o = 64; o; o >>= 1) {
        if (tid < o) {
#pragma unroll
            for (int i = 0; i < 4; i++) sh[i][tid] += sh[i][tid + o];
        }
        __syncthreads();
    }
    if (tid == 0) {
        const double N = 2097152.0;
        double v1 = (sh[1][0] - sh[0][0] * sh[0][0] / N) / (N - 1.0);
        double v2 = (sh[3][0] - sh[2][0] * sh[2][0] / N) / (N - 1.0);
        g_stats[0] = (float)(1.0 / sqrt(v1));
        g_stats[1] = (float)(1.0 / sqrt(v2));
    }
}

// ---------------- K5: merged attention (blocks 0..255 = h1 path, 256..511 = h2 path) ----------------
#define SM_ATT (14848 * 4)
__global__ void k_attn() {
    extern __shared__ float sm[];
    const int tid = threadIdx.x;     // 256

    if (blockIdx.x < 256) {
        float* sl = sm;            // [64 r][128 c]
        float* sv = sm + 8192;     // v2 plane [128 c][16 d]
        const int blk = blockIdx.x;
        const int p = blk >> 1, rh = blk & 1;
        const float inv = g_stats[0];
        const float* mp = g_ms1 + p * 16384 + rh * 8192;
        for (int idx = tid; idx < 8192; idx += 256) sl[idx] = 10.f * fast_tanh(mp[idx] * inv);
        const float* vp = g_v2 + p * 2048;
        for (int idx = tid; idx < 2048; idx += 256) sv[idx] = vp[idx];
        __syncthreads();

        const int w = tid >> 5, lane = tid & 31;
#pragma unroll
        for (int i = 0; i < 8; i++) {
            int r = w * 8 + i;
            float* row = sl + r * 128;
            float m = fmaxf(fmaxf(row[lane], row[lane + 32]), fmaxf(row[lane + 64], row[lane + 96]));
#pragma unroll
            for (int off = 16; off; off >>= 1) m = fmaxf(m, __shfl_xor_sync(0xffffffffu, m, off));
            float s = 0.f;
#pragma unroll
            for (int t = 0; t < 4; t++) {
                int cc = lane + t * 32;
                float e = __expf(row[cc] - m);
                row[cc] = e; s += e;
            }
#pragma unroll
            for (int off = 16; off; off >>= 1) s += __shfl_xor_sync(0xffffffffu, s, off);
            float is = 1.f / s;
#pragma unroll
            for (int t = 0; t < 4; t++) row[lane + t * 32] *= is;
        }
        __syncthreads();

        const int r = tid >> 2, d0 = (tid & 3) << 2;
        float a0 = 0.f, a1 = 0.f, a2 = 0.f, a3 = 0.f;
#pragma unroll 4
        for (int cc = 0; cc < 128; cc++) {
            float wgt = sl[r * 128 + cc];
            float4 v = *(const float4*)(sv + cc * 16 + d0);
            a0 += wgt * v.x; a1 += wgt * v.y; a2 += wgt * v.z; a3 += wgt * v.w;
        }
        const int b = p >> 4, h = p & 15;
        float* out = g_attn1 + (b * 128 + rh * 64 + r) * 256 + h * 16 + d0;
        *(float4*)out = make_float4(a0, a1, a2, a3);
    } else {
        float* sl   = sm;               // [128 r][64 c]
        float* sv   = sm + 8192;        // v1 plane [128 r][16 d]
        float* pr   = sm + 10240;       // [4 seg][64 c][16 d]
        float* redm = sm + 14336;       // [4 seg][64 c]
        float* reds = sm + 14592;       // [4 seg][64 c]
        const int blk = blockIdx.x - 256;
        const int p = blk >> 1, ch = blk & 1;
        const float inv = g_stats[1];
        const float* mp = g_ms2 + p * 16384 + ch * 64;
        for (int idx = tid; idx < 8192; idx += 256)
            sl[idx] = 10.f * fast_tanh(mp[(idx >> 6) * 128 + (idx & 63)] * inv);
        const float* vp = g_v1 + p * 2048;
        for (int idx = tid; idx < 2048; idx += 256) sv[idx] = vp[idx];
        __syncthreads();

        const int c = tid & 63, seg = tid >> 6;
        float m = -1e30f;
#pragma unroll 4
        for (int i = 0; i < 32; i++) m = fmaxf(m, sl[(seg * 32 + i) * 64 + c]);
        redm[seg * 64 + c] = m;
        __syncthreads();
        m = fmaxf(fmaxf(redm[c], redm[64 + c]), fmaxf(redm[128 + c], redm[192 + c]));
        float s = 0.f;
#pragma unroll 4
        for (int i = 0; i < 32; i++) {
            int rr = seg * 32 + i;
            float e = __expf(sl[rr * 64 + c] - m);
            sl[rr * 64 + c] = e; s += e;
        }
        reds[seg * 64 + c] = s;

        float acc[16];
#pragma unroll
        for (int j = 0; j < 16; j++) acc[j] = 0.f;
#pragma unroll 2
        for (int i = 0; i < 32; i++) {
            int rr = seg * 32 + i;
            float wgt = sl[rr * 64 + c];
            const float4* v = (const float4*)(sv + rr * 16);
            float4 v0 = v[0], v1 = v[1], v2 = v[2], v3 = v[3];
            acc[0] += wgt * v0.x; acc[1] += wgt * v0.y; acc[2] += wgt * v0.z; acc[3] += wgt * v0.w;
            acc[4] += wgt * v1.x; acc[5] += wgt * v1.y; acc[6] += wgt * v1.z; acc[7] += wgt * v1.w;
            acc[8] += wgt * v2.x; acc[9] += wgt * v2.y; acc[10] += wgt * v2.z; acc[11] += wgt * v2.w;
            acc[12] += wgt * v3.x; acc[13] += wgt * v3.y; acc[14] += wgt * v3.z; acc[15] += wgt * v3.w;
        }
        float* prp = pr + (seg * 64 + c) * 16;
#pragma unroll
        for (int j = 0; j < 4; j++)
            *(float4*)(prp + j * 4) = make_float4(acc[j * 4], acc[j * 4 + 1], acc[j * 4 + 2], acc[j * 4 + 3]);
        __syncthreads();

        const int b = p >> 4, h = p & 15;
        for (int o = tid; o < 1024; o += 256) {
            int cc = o >> 4, d = o & 15;
            float v = pr[(cc) * 16 + d] + pr[(64 + cc) * 16 + d]
                    + pr[(128 + cc) * 16 + d] + pr[(192 + cc) * 16 + d];
            float stot = reds[cc] + reds[64 + cc] + reds[128 + cc] + reds[192 + cc];
            g_attn2[(b * 128 + ch * 64 + cc) * 256 + h * 16 + d] = v / stot;
        }
    }
}

// ---------------- K6: output projections ----------------
// M=2048, N=256, K=256. 64x64 tiles, K chunked x128, 16 outputs/thread.
#define SM_OUT ((64 * 132 + 128 * 64) * 4)
__global__ void k_out(const float* __restrict__ o1w, const float* __restrict__ o2w,
                      float* __restrict__ out) {
    extern __shared__ float smo[];
    float* sA = smo;               // [64][132]
    float* sB = smo + 64 * 132;    // [128][64]
    const int m0 = blockIdx.x * 64, n0 = blockIdx.y * 64;
    const bool first = (m0 < 1024);
    const float* A = first ? g_attn1 : g_attn2;
    const float* W = first ? o1w : o2w;
    float* dst = out + (first ? 0 : 262144);
    const int mm = m0 & 1023;
    const int tid = threadIdx.x;
    const int r = tid >> 3, cg = tid & 7;

    float acc[16];
#pragma unroll
    for (int j = 0; j < 16; j++) acc[j] = 0.f;

    for (int kc = 0; kc < 256; kc += 128) {
        for (int idx = tid; idx < 2048; idx += 256) {
            int row = idx >> 5, k4 = (idx & 31) << 2;
            float4 v = *(const float4*)(A + (mm + row) * 256 + kc + k4);
            *(float4*)(sA + row * 132 + k4) = v;
        }
        for (int idx = tid; idx < 2048; idx += 256) {
            int row = idx >> 4, c4 = (idx & 15) << 2;
            float4 v = *(const float4*)(W + (kc + row) * 256 + n0 + c4);
            *(float4*)(sB + row * 64 + c4) = v;
        }
        __syncthreads();

        const float4* sB4 = (const float4*)sB;
#pragma unroll 4
        for (int k = 0; k < 128; k++) {
            float a0 = sA[r * 132 + k];
            float a1 = sA[(r + 32) * 132 + k];
            float4 b0 = sB4[k * 16 + cg * 2];
            float4 b1 = sB4[k * 16 + cg * 2 + 1];
            acc[0] += a0 * b0.x; acc[1] += a0 * b0.y; acc[2] += a0 * b0.z; acc[3] += a0 * b0.w;
            acc[4] += a0 * b1.x; acc[5] += a0 * b1.y; acc[6] += a0 * b1.z; acc[7] += a0 * b1.w;
            acc[8]  += a1 * b0.x; acc[9]  += a1 * b0.y; acc[10] += a1 * b0.z; acc[11] += a1 * b0.w;
            acc[12] += a1 * b1.x; acc[13] += a1 * b1.y; acc[14] += a1 * b1.z; acc[15] += a1 * b1.w;
        }
        __syncthreads();
    }

#pragma unroll
    for (int rr = 0; rr < 2; rr++) {
        float* o = dst + (mm + r + rr * 32) * 256 + n0 + cg * 8;
        *(float4*)(o)     = make_float4(acc[rr * 8],     acc[rr * 8 + 1], acc[rr * 8 + 2], acc[rr * 8 + 3]);
        *(float4*)(o + 4) = make_float4(acc[rr * 8 + 4], acc[rr * 8 + 5], acc[rr * 8 + 6], acc[rr * 8 + 7]);
    }
}

// ---------------- launch ----------------
extern "C" void kernel_launch(void* const* d_in, const int* in_sizes, int n_in,
                              void* d_out, int out_size) {
    const float* x1   = (const float*)d_in[0];
    const float* x2   = (const float*)d_in[1];
    const float* cost = (const float*)d_in[2];
    const float* Wqv1 = (const float*)d_in[3];
    const float* lin1 = (const float*)d_in[4];
    const float* lin2 = (const float*)d_in[5];
    const float* o1w  = (const float*)d_in[6];
    const float* o2w  = (const float*)d_in[7];
    float* out = (float*)d_out;

    cudaFuncSetAttribute(k_qkv,  cudaFuncAttributeMaxDynamicSharedMemorySize, SM_QKV);
    cudaFuncSetAttribute(k_mlp,  cudaFuncAttributeMaxDynamicSharedMemorySize, SM_MLP);
    cudaFuncSetAttribute(k_attn, cudaFuncAttributeMaxDynamicSharedMemorySize, SM_ATT);
    cudaFuncSetAttribute(k_out,  cudaFuncAttributeMaxDynamicSharedMemorySize, SM_OUT);

    // profiler slot 4 captures the NEW tensor-core k_qkv
    k_prep<<<160, 256>>>(lin1, lin2, Wqv1);               // 1
    k_nop<<<1, 32>>>();                                   // 2
    k_nop<<<1, 32>>>();                                   // 3
    k_qkv<<<dim3(32, 8), 256, SM_QKV>>>(x1, x2);          // 4  <- profiled
    k_mlp<<<1024, 256, SM_MLP>>>(cost);                   // 5
    k_std<<<1, 128>>>();                                  // 6
    k_attn<<<512, 256, SM_ATT>>>();                       // 7
    k_out<<<dim3(32, 4), 256, SM_OUT>>>(o1w, o2w, out);   // 8

    (void)in_sizes; (void)n_in; (void)out_size;
}

// round 15
// speedup vs baseline: 2.2634x; 1.1182x over previous
#include <cuda_runtime.h>
#include <math.h>
#include <stdint.h>

typedef unsigned long long ull;

// ---------------- scratch (device globals; no allocations allowed) ----------------
__device__ float g_qT  [1024 * 256];      // [b*128+r][e]   e = h*16+d
__device__ float g_kTT [8 * 256 * 128];   // [b][e][c]
__device__ float g_v1  [1024 * 256];      // [b][h][s][d]
__device__ float g_v2  [1024 * 256];      // [b][h][s][d]
__device__ float g_ms1 [2097152];         // [b][h][r][c]
__device__ float g_ms2 [2097152];         // [b][h][r][c]
__device__ float g_attn1[1024 * 256];     // [b*128+r][h*16+d]
__device__ float g_attn2[1024 * 256];     // [b*128+c][h*16+d]
__device__ float g_part[1024 * 4];        // per-block {s1,q1,s2,q2}
__device__ float g_stats[2];              // inv_std1, inv_std2
// bf16 hi/lo frag-packed weights: per fragment+lane uint4 {b0hi, b1hi, b0lo, b1lo}
__device__ uint4 gW1p[128 * 32];
__device__ uint4 gW2p[128 * 32];
__device__ uint4 gWqv[1024 * 32];         // Wqv1 [256][512]: frag = kstep*64 + nfr
__device__ uint4 gWo[2][512 * 32];        // o1w/o2w [256][256]: frag = kstep*32 + nfr

// ---------------- helpers ----------------
__device__ __forceinline__ float fast_tanh(float x) {
    return 1.f - 2.f / (__expf(2.f * x) + 1.f);
}
__device__ __forceinline__ uint32_t packbf(float fu, float fl) {
    uint32_t r; asm("cvt.rn.bf16x2.f32 %0, %1, %2;" : "=r"(r) : "f"(fu), "f"(fl));
    return r;
}
__device__ __forceinline__ void split2(float x0, float x1, uint32_t& hi, uint32_t& lo) {
    hi = packbf(x1, x0);
    float h0 = __uint_as_float(hi << 16);
    float h1 = __uint_as_float(hi & 0xffff0000u);
    lo = packbf(x1 - h1, x0 - h0);
}
__device__ __forceinline__ void mma_bf16(float* c,
                                         uint32_t a0, uint32_t a1, uint32_t a2, uint32_t a3,
                                         uint32_t b0, uint32_t b1) {
    asm volatile(
        "mma.sync.aligned.m16n8k16.row.col.f32.bf16.bf16.f32 "
        "{%0,%1,%2,%3}, {%4,%5,%6,%7}, {%8,%9}, {%0,%1,%2,%3};"
        : "+f"(c[0]), "+f"(c[1]), "+f"(c[2]), "+f"(c[3])
        : "r"(a0), "r"(a1), "r"(a2), "r"(a3), "r"(b0), "r"(b1));
}

__global__ void k_nop() {}

// ---------------- K0: pack W1/W2/Wqv1/o1w/o2w into bf16 hi/lo fragment uint4s ----------------
__global__ void k_prep(const float* __restrict__ w1, const float* __restrict__ w2,
                       const float* __restrict__ wqv,
                       const float* __restrict__ o1w, const float* __restrict__ o2w) {
    int idx = blockIdx.x * 256 + threadIdx.x;   // 0..73727
    if (idx < 8192) {
        int sel  = idx >> 12;
        int f    = idx & 4095;
        int lane = f & 31;
        int frag = f >> 5;            // 0..127
        int g = lane >> 2, tig = lane & 3;
        float k0, k1, k8, k9;
        if (sel == 0) {
            int ks2 = frag & 1, cn = frag >> 1;
            int n = cn * 8 + g;
            int kb = ks2 * 16 + 2 * tig;
            k0 = w1[kb * 512 + n];       k1 = w1[(kb + 1) * 512 + n];
            k8 = w1[(kb + 8) * 512 + n]; k9 = w1[(kb + 9) * 512 + n];
        } else {
            int nf = frag & 3, ck = frag >> 2;
            int n = nf * 8 + g;
            int kb = ck * 16 + 2 * tig;
            k0 = w2[kb * 32 + n];        k1 = w2[(kb + 1) * 32 + n];
            k8 = w2[(kb + 8) * 32 + n];  k9 = w2[(kb + 9) * 32 + n];
        }
        uint32_t h0, l0, h1, l1;
        split2(k0, k1, h0, l0);
        split2(k8, k9, h1, l1);
        uint4 v = make_uint4(h0, h1, l0, l1);
        if (sel == 0) gW1p[frag * 32 + lane] = v;
        else          gW2p[frag * 32 + lane] = v;
    } else if (idx < 40960) {
        int f = idx - 8192;
        int lane = f & 31;
        int frag = f >> 5;            // 0..1023: kstep*64 + nfr
        int kstep = frag >> 6, nfr = frag & 63;
        int g = lane >> 2, tig = lane & 3;
        int n = nfr * 8 + g;
        int kb = kstep * 16 + 2 * tig;
        float k0 = wqv[kb * 512 + n],       k1 = wqv[(kb + 1) * 512 + n];
        float k8 = wqv[(kb + 8) * 512 + n], k9 = wqv[(kb + 9) * 512 + n];
        uint32_t h0, l0, h1, l1;
        split2(k0, k1, h0, l0);
        split2(k8, k9, h1, l1);
        gWqv[frag * 32 + lane] = make_uint4(h0, h1, l0, l1);
    } else if (idx < 73728) {
        int f = idx - 40960;          // 0..32767
        int wsel = f >> 14;           // 0 = o1w, 1 = o2w
        int ff = f & 16383;
        int lane = ff & 31;
        int frag = ff >> 5;           // 0..511: kstep*32 + nfr
        int kstep = frag >> 5, nfr = frag & 31;
        int g = lane >> 2, tig = lane & 3;
        const float* w = wsel ? o2w : o1w;
        int n = nfr * 8 + g;
        int kb = kstep * 16 + 2 * tig;
        float k0 = w[kb * 256 + n],       k1 = w[(kb + 1) * 256 + n];
        float k8 = w[(kb + 8) * 256 + n], k9 = w[(kb + 9) * 256 + n];
        uint32_t h0, l0, h1, l1;
        split2(k0, k1, h0, l0);
        split2(k8, k9, h1, l1);
        gWo[wsel][frag * 32 + lane] = make_uint4(h0, h1, l0, l1);
    }
}

// ---------------- K1: qkv projection GEMM (bf16-split tensor cores) ----------------
// M=2048 (x1 rows then x2 rows), N=512, K=256. CTA = 64 m-rows x 64 n-cols.
// 8 warps: warp = (msub 0..3) x (nhalf 0..1); each warp 16 rows x 32 cols.
// 3 independent accumulator sets per nf break the MMA chains (R6-validated).
#define SM_QKV (64 * 260 * 4)
__global__ void __launch_bounds__(256)
k_qkv(const float* __restrict__ x1, const float* __restrict__ x2) {
    extern __shared__ float smq[];
    float* sA = smq;   // [64][260]
    const int m0 = blockIdx.x * 64, n0 = blockIdx.y * 64;
    const bool isX1 = (m0 < 1024);
    const float* src = isX1 ? x1 : x2;
    const int mm = m0 & 1023;
    const int b = mm >> 7, s0 = mm & 127;
    const int tid = threadIdx.x;
    const int warp = tid >> 5, lane = tid & 31;
    const int g = lane >> 2, tig = lane & 3;
    const int msub = warp >> 1, nhalf = warp & 1;

    for (int idx = tid; idx < 4096; idx += 256) {
        int row = idx >> 6, k4 = (idx & 63) << 2;
        float4 v = *(const float4*)(src + (b * 128 + s0 + row) * 256 + k4);
        *(float4*)(sA + row * 260 + k4) = v;
    }
    __syncthreads();

    const int arow0 = msub * 16 + g, arow1 = arow0 + 8;
    float acc[4][4], accL[4][4], accX[4][4];
#pragma unroll
    for (int i = 0; i < 4; i++)
#pragma unroll
        for (int j = 0; j < 4; j++) { acc[i][j] = 0.f; accL[i][j] = 0.f; accX[i][j] = 0.f; }

    const int nfr0 = (n0 >> 3) + nhalf * 4;
#pragma unroll 4
    for (int kk = 0; kk < 16; kk++) {
        int cb = kk * 16 + 2 * tig;
        uint32_t ah[4], al[4];
        split2(sA[arow0 * 260 + cb],     sA[arow0 * 260 + cb + 1], ah[0], al[0]);
        split2(sA[arow1 * 260 + cb],     sA[arow1 * 260 + cb + 1], ah[1], al[1]);
        split2(sA[arow0 * 260 + cb + 8], sA[arow0 * 260 + cb + 9], ah[2], al[2]);
        split2(sA[arow1 * 260 + cb + 8], sA[arow1 * 260 + cb + 9], ah[3], al[3]);
#pragma unroll
        for (int nf = 0; nf < 4; nf++) {
            uint4 bw = gWqv[((kk << 6) + nfr0 + nf) * 32 + lane];
            mma_bf16(acc[nf],  ah[0], ah[1], ah[2], ah[3], bw.x, bw.y);
            mma_bf16(accL[nf], al[0], al[1], al[2], al[3], bw.x, bw.y);
            mma_bf16(accX[nf], ah[0], ah[1], ah[2], ah[3], bw.z, bw.w);
        }
    }

#pragma unroll
    for (int nf = 0; nf < 4; nf++) {
        int n = n0 + nhalf * 32 + nf * 8 + 2 * tig;
        float v[4];
#pragma unroll
        for (int j = 0; j < 4; j++) v[j] = acc[nf][j] + accL[nf][j] + accX[nf][j];
#pragma unroll
        for (int q = 0; q < 4; q++) {
            int s = s0 + ((q >> 1) ? arow1 : arow0);
            int nn = n + (q & 1);
            float val = v[q];
            if (nn < 256) {
                if (isX1) g_qT[(b * 128 + s) * 256 + nn] = val;
                else      g_kTT[(b * 256 + nn) * 128 + s] = val;
            } else {
                int h = (nn - 256) >> 4, d = nn & 15;
                float* dst = isX1 ? g_v1 : g_v2;
                dst[((b * 16 + h) * 128 + s) * 16 + d] = val;
            }
        }
    }
}

// ---------------- K3: bf16-split tensor-core fused dot + MixedScoreFF MLP ----------------
// (validated R12: 82.7 us, rel_err 1.565e-5 — unchanged)
#define SM_MLP 81920
__global__ void __launch_bounds__(256, 2)
k_mlp(const float* __restrict__ cost) {
    extern __shared__ float smf[];
    float* sA = smf;                      // [128][36] staging; reused as sO [128][33]
    float* sq = smf + 4608;               // [256]

    const int blk = blockIdx.x;           // b*128 + r
    const int b = blk >> 7;
    const int tid = threadIdx.x;
    const int warp = tid >> 5, lane = tid & 31;
    const int g = lane >> 2, tig = lane & 3;

    sq[tid] = g_qT[(blk << 8) + tid];
    __syncthreads();

    {
        const int c = tid & 127, half = tid >> 7;
        float cv = cost[blk * 128 + c];
        const float* kb = g_kTT + b * 32768 + c;
#pragma unroll
        for (int hh = 0; hh < 8; hh++) {
            int h = half * 8 + hh;
            float a = 0.f;
#pragma unroll
            for (int d = 0; d < 16; d++)
                a += sq[h * 16 + d] * kb[(h * 16 + d) * 128];
            sA[c * 36 + 2 * h] = a * 0.25f;
            sA[c * 36 + 2 * h + 1] = cv;
        }
    }
    __syncthreads();

    const int arow0 = warp * 16 + g, arow1 = arow0 + 8;
    uint32_t Ahi[2][4], Alo[2][4];
#pragma unroll
    for (int ks2 = 0; ks2 < 2; ks2++) {
        int cb = ks2 * 16 + 2 * tig;
        split2(sA[arow0 * 36 + cb],     sA[arow0 * 36 + cb + 1], Ahi[ks2][0], Alo[ks2][0]);
        split2(sA[arow1 * 36 + cb],     sA[arow1 * 36 + cb + 1], Ahi[ks2][1], Alo[ks2][1]);
        split2(sA[arow0 * 36 + cb + 8], sA[arow0 * 36 + cb + 9], Ahi[ks2][2], Alo[ks2][2]);
        split2(sA[arow1 * 36 + cb + 8], sA[arow1 * 36 + cb + 9], Ahi[ks2][3], Alo[ks2][3]);
    }
    __syncthreads();

    float OUThh[4][4], OUTc[4][4];
#pragma unroll
    for (int i = 0; i < 4; i++)
#pragma unroll
        for (int j = 0; j < 4; j++) { OUThh[i][j] = 0.f; OUTc[i][j] = 0.f; }

    for (int chunk = 0; chunk < 8; chunk++) {
#pragma unroll
        for (int ksp = 0; ksp < 4; ksp++) {
            uint32_t ah[4], al[4];
#pragma unroll
            for (int halfn = 0; halfn < 2; halfn++) {
                int nfp = 2 * ksp + halfn;
                float hh[4] = {0.f, 0.f, 0.f, 0.f};
                float lh[4] = {0.f, 0.f, 0.f, 0.f};
                float hl[4] = {0.f, 0.f, 0.f, 0.f};
#pragma unroll
                for (int ks2 = 0; ks2 < 2; ks2++) {
                    uint4 bw = gW1p[((((chunk * 8 + nfp) * 2 + ks2)) << 5) + lane];
                    mma_bf16(hh, Ahi[ks2][0], Ahi[ks2][1], Ahi[ks2][2], Ahi[ks2][3], bw.x, bw.y);
                    mma_bf16(lh, Alo[ks2][0], Alo[ks2][1], Alo[ks2][2], Alo[ks2][3], bw.x, bw.y);
                    mma_bf16(hl, Ahi[ks2][0], Ahi[ks2][1], Ahi[ks2][2], Ahi[ks2][3], bw.z, bw.w);
                }
                float h0 = fmaxf(hh[0] + lh[0] + hl[0], 0.f);
                float h1 = fmaxf(hh[1] + lh[1] + hl[1], 0.f);
                float h2 = fmaxf(hh[2] + lh[2] + hl[2], 0.f);
                float h3 = fmaxf(hh[3] + lh[3] + hl[3], 0.f);
                split2(h0, h1, ah[2 * halfn],     al[2 * halfn]);
                split2(h2, h3, ah[2 * halfn + 1], al[2 * halfn + 1]);
            }
#pragma unroll
            for (int nf = 0; nf < 4; nf++) {
                uint4 bw = gW2p[((((chunk * 4 + ksp) * 4 + nf)) << 5) + lane];
                mma_bf16(OUThh[nf], ah[0], ah[1], ah[2], ah[3], bw.x, bw.y);
                mma_bf16(OUTc[nf],  al[0], al[1], al[2], al[3], bw.x, bw.y);
                mma_bf16(OUTc[nf],  ah[0], ah[1], ah[2], ah[3], bw.z, bw.w);
            }
        }
    }

    float* sO = smf;
#pragma unroll
    for (int nf = 0; nf < 4; nf++) {
        int col = nf * 8 + 2 * tig;
        sO[arow0 * 33 + col]     = OUThh[nf][0] + OUTc[nf][0];
        sO[arow0 * 33 + col + 1] = OUThh[nf][1] + OUTc[nf][1];
        sO[arow1 * 33 + col]     = OUThh[nf][2] + OUTc[nf][2];
        sO[arow1 * 33 + col + 1] = OUThh[nf][3] + OUTc[nf][3];
    }
    __syncthreads();

    const int r = blk & 127;
    float s1 = 0.f, q1 = 0.f, s2 = 0.f, q2 = 0.f;
    for (int i = tid; i < 2048; i += 256) {
        int h = i >> 7, cc = i & 127;
        float m1 = sO[cc * 33 + 2 * h];
        float m2 = sO[cc * 33 + 2 * h + 1];
        g_ms1[((b * 16 + h) * 128 + r) * 128 + cc] = m1;
        g_ms2[((b * 16 + h) * 128 + r) * 128 + cc] = m2;
        s1 += m1; q1 += m1 * m1; s2 += m2; q2 += m2 * m2;
    }

    float v[4] = {s1, q1, s2, q2};
#pragma unroll
    for (int i = 0; i < 4; i++)
        for (int off = 16; off; off >>= 1) v[i] += __shfl_xor_sync(0xffffffffu, v[i], off);
    __shared__ float red[4][8];
    if (lane == 0) { red[0][warp] = v[0]; red[1][warp] = v[1]; red[2][warp] = v[2]; red[3][warp] = v[3]; }
    __syncthreads();
    if (tid == 0) {
#pragma unroll
        for (int i = 0; i < 4; i++) {
            float s = 0.f;
#pragma unroll
            for (int j = 0; j < 8; j++) s += red[i][j];
            g_part[blk * 4 + i] = s;
        }
    }
}

// ---------------- K4: std reduction (ddof=1) ----------------
__global__ void k_std() {
    __shared__ double sh[4][128];
    const int tid = threadIdx.x;  // 128
    double a0 = 0, a1 = 0, a2 = 0, a3 = 0;
    for (int i = tid; i < 1024; i += 128) {
        const float* p = g_part + i * 4;
        a0 += p[0]; a1 += p[1]; a2 += p[2]; a3 += p[3];
    }
    sh[0][tid] = a0; sh[1][tid] = a1; sh[2][tid] = a2; sh[3][tid] = a3;
    __syncthreads();
    for (int o = 64; o; o >>= 1) {
        if (tid < o) {
#pragma unroll
            for (int i = 0; i < 4; i++) sh[i][tid] += sh[i][tid + o];
        }
        __syncthreads();
    }
    if (tid == 0) {
        const double N = 2097152.0;
        double v1 = (sh[1][0] - sh[0][0] * sh[0][0] / N) / (N - 1.0);
        double v2 = (sh[3][0] - sh[2][0] * sh[2][0] / N) / (N - 1.0);
        g_stats[0] = (float)(1.0 / sqrt(v1));
        g_stats[1] = (float)(1.0 / sqrt(v2));
    }
}

// ---------------- K5: merged attention (blocks 0..255 = h1 path, 256..511 = h2 path) ----------------
#define SM_ATT (14848 * 4)
__global__ void k_attn() {
    extern __shared__ float sm[];
    const int tid = threadIdx.x;     // 256

    if (blockIdx.x < 256) {
        float* sl = sm;            // [64 r][128 c]
        float* sv = sm + 8192;     // v2 plane [128 c][16 d]
        const int blk = blockIdx.x;
        const int p = blk >> 1, rh = blk & 1;
        const float inv = g_stats[0];
        const float* mp = g_ms1 + p * 16384 + rh * 8192;
        for (int idx = tid; idx < 8192; idx += 256) sl[idx] = 10.f * fast_tanh(mp[idx] * inv);
        const float* vp = g_v2 + p * 2048;
        for (int idx = tid; idx < 2048; idx += 256) sv[idx] = vp[idx];
        __syncthreads();

        const int w = tid >> 5, lane = tid & 31;
#pragma unroll
        for (int i = 0; i < 8; i++) {
            int r = w * 8 + i;
            float* row = sl + r * 128;
            float m = fmaxf(fmaxf(row[lane], row[lane + 32]), fmaxf(row[lane + 64], row[lane + 96]));
#pragma unroll
            for (int off = 16; off; off >>= 1) m = fmaxf(m, __shfl_xor_sync(0xffffffffu, m, off));
            float s = 0.f;
#pragma unroll
            for (int t = 0; t < 4; t++) {
                int cc = lane + t * 32;
                float e = __expf(row[cc] - m);
                row[cc] = e; s += e;
            }
#pragma unroll
            for (int off = 16; off; off >>= 1) s += __shfl_xor_sync(0xffffffffu, s, off);
            float is = 1.f / s;
#pragma unroll
            for (int t = 0; t < 4; t++) row[lane + t * 32] *= is;
        }
        __syncthreads();

        const int r = tid >> 2, d0 = (tid & 3) << 2;
        float a0 = 0.f, a1 = 0.f, a2 = 0.f, a3 = 0.f;
#pragma unroll 4
        for (int cc = 0; cc < 128; cc++) {
            float wgt = sl[r * 128 + cc];
            float4 v = *(const float4*)(sv + cc * 16 + d0);
            a0 += wgt * v.x; a1 += wgt * v.y; a2 += wgt * v.z; a3 += wgt * v.w;
        }
        const int b = p >> 4, h = p & 15;
        float* out = g_attn1 + (b * 128 + rh * 64 + r) * 256 + h * 16 + d0;
        *(float4*)out = make_float4(a0, a1, a2, a3);
    } else {
        float* sl   = sm;               // [128 r][64 c]
        float* sv   = sm + 8192;        // v1 plane [128 r][16 d]
        float* pr   = sm + 10240;       // [4 seg][64 c][16 d]
        float* redm = sm + 14336;       // [4 seg][64 c]
        float* reds = sm + 14592;       // [4 seg][64 c]
        const int blk = blockIdx.x - 256;
        const int p = blk >> 1, ch = blk & 1;
        const float inv = g_stats[1];
        const float* mp = g_ms2 + p * 16384 + ch * 64;
        for (int idx = tid; idx < 8192; idx += 256)
            sl[idx] = 10.f * fast_tanh(mp[(idx >> 6) * 128 + (idx & 63)] * inv);
        const float* vp = g_v1 + p * 2048;
        for (int idx = tid; idx < 2048; idx += 256) sv[idx] = vp[idx];
        __syncthreads();

        const int c = tid & 63, seg = tid >> 6;
        float m = -1e30f;
#pragma unroll 4
        for (int i = 0; i < 32; i++) m = fmaxf(m, sl[(seg * 32 + i) * 64 + c]);
        redm[seg * 64 + c] = m;
        __syncthreads();
        m = fmaxf(fmaxf(redm[c], redm[64 + c]), fmaxf(redm[128 + c], redm[192 + c]));
        float s = 0.f;
#pragma unroll 4
        for (int i = 0; i < 32; i++) {
            int rr = seg * 32 + i;
            float e = __expf(sl[rr * 64 + c] - m);
            sl[rr * 64 + c] = e; s += e;
        }
        reds[seg * 64 + c] = s;

        float acc[16];
#pragma unroll
        for (int j = 0; j < 16; j++) acc[j] = 0.f;
#pragma unroll 2
        for (int i = 0; i < 32; i++) {
            int rr = seg * 32 + i;
            float wgt = sl[rr * 64 + c];
            const float4* v = (const float4*)(sv + rr * 16);
            float4 v0 = v[0], v1 = v[1], v2 = v[2], v3 = v[3];
            acc[0] += wgt * v0.x; acc[1] += wgt * v0.y; acc[2] += wgt * v0.z; acc[3] += wgt * v0.w;
            acc[4] += wgt * v1.x; acc[5] += wgt * v1.y; acc[6] += wgt * v1.z; acc[7] += wgt * v1.w;
            acc[8] += wgt * v2.x; acc[9] += wgt * v2.y; acc[10] += wgt * v2.z; acc[11] += wgt * v2.w;
            acc[12] += wgt * v3.x; acc[13] += wgt * v3.y; acc[14] += wgt * v3.z; acc[15] += wgt * v3.w;
        }
        float* prp = pr + (seg * 64 + c) * 16;
#pragma unroll
        for (int j = 0; j < 4; j++)
            *(float4*)(prp + j * 4) = make_float4(acc[j * 4], acc[j * 4 + 1], acc[j * 4 + 2], acc[j * 4 + 3]);
        __syncthreads();

        const int b = p >> 4, h = p & 15;
        for (int o = tid; o < 1024; o += 256) {
            int cc = o >> 4, d = o & 15;
            float v = pr[(cc) * 16 + d] + pr[(64 + cc) * 16 + d]
                    + pr[(128 + cc) * 16 + d] + pr[(192 + cc) * 16 + d];
            float stot = reds[cc] + reds[64 + cc] + reds[128 + cc] + reds[192 + cc];
            g_attn2[(b * 128 + ch * 64 + cc) * 256 + h * 16 + d] = v / stot;
        }
    }
}

// ---------------- K6: output projections (bf16-split tensor cores) ----------------
// M=2048, N=256, K=256. CTA = 64 m-rows x 64 n-cols, same warp layout as k_qkv.
#define SM_OUT (64 * 260 * 4)
__global__ void __launch_bounds__(256)
k_out(float* __restrict__ out) {
    extern __shared__ float smo[];
    float* sA = smo;   // [64][260]
    const int m0 = blockIdx.x * 64, n0 = blockIdx.y * 64;
    const bool first = (m0 < 1024);
    const float* A = first ? g_attn1 : g_attn2;
    const int wsel = first ? 0 : 1;
    float* dst = out + (first ? 0 : 262144);
    const int mm = m0 & 1023;
    const int tid = threadIdx.x;
    const int warp = tid >> 5, lane = tid & 31;
    const int g = lane >> 2, tig = lane & 3;
    const int msub = warp >> 1, nhalf = warp & 1;

    for (int idx = tid; idx < 4096; idx += 256) {
        int row = idx >> 6, k4 = (idx & 63) << 2;
        float4 v = *(const float4*)(A + (mm + row) * 256 + k4);
        *(float4*)(sA + row * 260 + k4) = v;
    }
    __syncthreads();

    const int arow0 = msub * 16 + g, arow1 = arow0 + 8;
    float acc[4][4], accL[4][4], accX[4][4];
#pragma unroll
    for (int i = 0; i < 4; i++)
#pragma unroll
        for (int j = 0; j < 4; j++) { acc[i][j] = 0.f; accL[i][j] = 0.f; accX[i][j] = 0.f; }

    const int nfr0 = (n0 >> 3) + nhalf * 4;
    const uint4* wo = gWo[wsel];
#pragma unroll 4
    for (int kk = 0; kk < 16; kk++) {
        int cb = kk * 16 + 2 * tig;
        uint32_t ah[4], al[4];
        split2(sA[arow0 * 260 + cb],     sA[arow0 * 260 + cb + 1], ah[0], al[0]);
        split2(sA[arow1 * 260 + cb],     sA[arow1 * 260 + cb + 1], ah[1], al[1]);
        split2(sA[arow0 * 260 + cb + 8], sA[arow0 * 260 + cb + 9], ah[2], al[2]);
        split2(sA[arow1 * 260 + cb + 8], sA[arow1 * 260 + cb + 9], ah[3], al[3]);
#pragma unroll
        for (int nf = 0; nf < 4; nf++) {
            uint4 bw = wo[((kk << 5) + nfr0 + nf) * 32 + lane];
            mma_bf16(acc[nf],  ah[0], ah[1], ah[2], ah[3], bw.x, bw.y);
            mma_bf16(accL[nf], al[0], al[1], al[2], al[3], bw.x, bw.y);
            mma_bf16(accX[nf], ah[0], ah[1], ah[2], ah[3], bw.z, bw.w);
        }
    }

#pragma unroll
    for (int nf = 0; nf < 4; nf++) {
        int n = n0 + nhalf * 32 + nf * 8 + 2 * tig;
        float v0 = acc[nf][0] + accL[nf][0] + accX[nf][0];
        float v1 = acc[nf][1] + accL[nf][1] + accX[nf][1];
        float v2 = acc[nf][2] + accL[nf][2] + accX[nf][2];
        float v3 = acc[nf][3] + accL[nf][3] + accX[nf][3];
        float* o0 = dst + (mm + arow0) * 256 + n;
        float* o1 = dst + (mm + arow1) * 256 + n;
        o0[0] = v0; o0[1] = v1;
        o1[0] = v2; o1[1] = v3;
    }
}

// ---------------- launch ----------------
extern "C" void kernel_launch(void* const* d_in, const int* in_sizes, int n_in,
                              void* d_out, int out_size) {
    const float* x1   = (const float*)d_in[0];
    const float* x2   = (const float*)d_in[1];
    const float* cost = (const float*)d_in[2];
    const float* Wqv1 = (const float*)d_in[3];
    const float* lin1 = (const float*)d_in[4];
    const float* lin2 = (const float*)d_in[5];
    const float* o1w  = (const float*)d_in[6];
    const float* o2w  = (const float*)d_in[7];
    float* out = (float*)d_out;

    cudaFuncSetAttribute(k_qkv,  cudaFuncAttributeMaxDynamicSharedMemorySize, SM_QKV);
    cudaFuncSetAttribute(k_mlp,  cudaFuncAttributeMaxDynamicSharedMemorySize, SM_MLP);
    cudaFuncSetAttribute(k_attn, cudaFuncAttributeMaxDynamicSharedMemorySize, SM_ATT);
    cudaFuncSetAttribute(k_out,  cudaFuncAttributeMaxDynamicSharedMemorySize, SM_OUT);

    // profiler slot 4 captures the chain-split k_qkv
    k_prep<<<288, 256>>>(lin1, lin2, Wqv1, o1w, o2w);     // 1
    k_nop<<<1, 32>>>();                                   // 2
    k_nop<<<1, 32>>>();                                   // 3
    k_qkv<<<dim3(32, 8), 256, SM_QKV>>>(x1, x2);          // 4  <- profiled
    k_mlp<<<1024, 256, SM_MLP>>>(cost);                   // 5
    k_std<<<1, 128>>>();                                  // 6
    k_attn<<<512, 256, SM_ATT>>>();                       // 7
    k_out<<<dim3(32, 4), 256, SM_OUT>>>(out);             // 8

    (void)in_sizes; (void)n_in; (void)out_size;
}

// round 16
// speedup vs baseline: 2.2930x; 1.0131x over previous
#include <cuda_runtime.h>
#include <math.h>
#include <stdint.h>

typedef unsigned long long ull;

// ---------------- scratch (device globals; no allocations allowed) ----------------
__device__ float g_qT  [1024 * 256];      // [b*128+r][e]   e = h*16+d
__device__ float g_kTT [8 * 256 * 128];   // [b][e][c]
__device__ float g_v1  [1024 * 256];      // [b][h][s][d]
__device__ float g_v2  [1024 * 256];      // [b][h][s][d]
__device__ float g_ms1 [2097152];         // [b][h][r][c]
__device__ float g_ms2 [2097152];         // [b][h][r][c]
__device__ float g_attn1[1024 * 256];     // [b*128+r][h*16+d]
__device__ float g_attn2[1024 * 256];     // [b*128+c][h*16+d]
__device__ float g_part[1024 * 4];        // per-block {s1,q1,s2,q2}
__device__ float g_stats[2];              // inv_std1, inv_std2
__device__ unsigned g_ctr;                // mlp completion counter (reset by k_prep)
// bf16 hi/lo frag-packed weights: per fragment+lane uint4 {b0hi, b1hi, b0lo, b1lo}
__device__ uint4 gW1p[128 * 32];
__device__ uint4 gW2p[128 * 32];
__device__ uint4 gWqv[1024 * 32];         // Wqv1 [256][512]: frag = kstep*64 + nfr
__device__ uint4 gWo[2][512 * 32];        // o1w/o2w [256][256]: frag = kstep*32 + nfr

// ---------------- helpers ----------------
__device__ __forceinline__ float fast_tanh(float x) {
    return 1.f - 2.f / (__expf(2.f * x) + 1.f);
}
__device__ __forceinline__ uint32_t packbf(float fu, float fl) {
    uint32_t r; asm("cvt.rn.bf16x2.f32 %0, %1, %2;" : "=r"(r) : "f"(fu), "f"(fl));
    return r;
}
__device__ __forceinline__ void split2(float x0, float x1, uint32_t& hi, uint32_t& lo) {
    hi = packbf(x1, x0);
    float h0 = __uint_as_float(hi << 16);
    float h1 = __uint_as_float(hi & 0xffff0000u);
    lo = packbf(x1 - h1, x0 - h0);
}
__device__ __forceinline__ void mma_bf16(float* c,
                                         uint32_t a0, uint32_t a1, uint32_t a2, uint32_t a3,
                                         uint32_t b0, uint32_t b1) {
    asm volatile(
        "mma.sync.aligned.m16n8k16.row.col.f32.bf16.bf16.f32 "
        "{%0,%1,%2,%3}, {%4,%5,%6,%7}, {%8,%9}, {%0,%1,%2,%3};"
        : "+f"(c[0]), "+f"(c[1]), "+f"(c[2]), "+f"(c[3])
        : "r"(a0), "r"(a1), "r"(a2), "r"(a3), "r"(b0), "r"(b1));
}

// ---------------- K0: pack W1/W2/Wqv1/o1w/o2w into bf16 hi/lo fragment uint4s ----------------
__global__ void k_prep(const float* __restrict__ w1, const float* __restrict__ w2,
                       const float* __restrict__ wqv,
                       const float* __restrict__ o1w, const float* __restrict__ o2w) {
    int idx = blockIdx.x * 256 + threadIdx.x;   // 0..73727
    if (idx == 0) g_ctr = 0;
    if (idx < 8192) {
        int sel  = idx >> 12;
        int f    = idx & 4095;
        int lane = f & 31;
        int frag = f >> 5;            // 0..127
        int g = lane >> 2, tig = lane & 3;
        float k0, k1, k8, k9;
        if (sel == 0) {
            int ks2 = frag & 1, cn = frag >> 1;
            int n = cn * 8 + g;
            int kb = ks2 * 16 + 2 * tig;
            k0 = w1[kb * 512 + n];       k1 = w1[(kb + 1) * 512 + n];
            k8 = w1[(kb + 8) * 512 + n]; k9 = w1[(kb + 9) * 512 + n];
        } else {
            int nf = frag & 3, ck = frag >> 2;
            int n = nf * 8 + g;
            int kb = ck * 16 + 2 * tig;
            k0 = w2[kb * 32 + n];        k1 = w2[(kb + 1) * 32 + n];
            k8 = w2[(kb + 8) * 32 + n];  k9 = w2[(kb + 9) * 32 + n];
        }
        uint32_t h0, l0, h1, l1;
        split2(k0, k1, h0, l0);
        split2(k8, k9, h1, l1);
        uint4 v = make_uint4(h0, h1, l0, l1);
        if (sel == 0) gW1p[frag * 32 + lane] = v;
        else          gW2p[frag * 32 + lane] = v;
    } else if (idx < 40960) {
        int f = idx - 8192;
        int lane = f & 31;
        int frag = f >> 5;            // 0..1023: kstep*64 + nfr
        int kstep = frag >> 6, nfr = frag & 63;
        int g = lane >> 2, tig = lane & 3;
        int n = nfr * 8 + g;
        int kb = kstep * 16 + 2 * tig;
        float k0 = wqv[kb * 512 + n],       k1 = wqv[(kb + 1) * 512 + n];
        float k8 = wqv[(kb + 8) * 512 + n], k9 = wqv[(kb + 9) * 512 + n];
        uint32_t h0, l0, h1, l1;
        split2(k0, k1, h0, l0);
        split2(k8, k9, h1, l1);
        gWqv[frag * 32 + lane] = make_uint4(h0, h1, l0, l1);
    } else if (idx < 73728) {
        int f = idx - 40960;          // 0..32767
        int wsel = f >> 14;           // 0 = o1w, 1 = o2w
        int ff = f & 16383;
        int lane = ff & 31;
        int frag = ff >> 5;           // 0..511: kstep*32 + nfr
        int kstep = frag >> 5, nfr = frag & 31;
        int g = lane >> 2, tig = lane & 3;
        const float* w = wsel ? o2w : o1w;
        int n = nfr * 8 + g;
        int kb = kstep * 16 + 2 * tig;
        float k0 = w[kb * 256 + n],       k1 = w[(kb + 1) * 256 + n];
        float k8 = w[(kb + 8) * 256 + n], k9 = w[(kb + 9) * 256 + n];
        uint32_t h0, l0, h1, l1;
        split2(k0, k1, h0, l0);
        split2(k8, k9, h1, l1);
        gWo[wsel][frag * 32 + lane] = make_uint4(h0, h1, l0, l1);
    }
}

// ---------------- K1: qkv projection GEMM (bf16-split tensor cores) ----------------
#define SM_QKV (64 * 260 * 4)
__global__ void __launch_bounds__(256)
k_qkv(const float* __restrict__ x1, const float* __restrict__ x2) {
    extern __shared__ float smq[];
    float* sA = smq;   // [64][260]
    const int m0 = blockIdx.x * 64, n0 = blockIdx.y * 64;
    const bool isX1 = (m0 < 1024);
    const float* src = isX1 ? x1 : x2;
    const int mm = m0 & 1023;
    const int b = mm >> 7, s0 = mm & 127;
    const int tid = threadIdx.x;
    const int warp = tid >> 5, lane = tid & 31;
    const int g = lane >> 2, tig = lane & 3;
    const int msub = warp >> 1, nhalf = warp & 1;

    for (int idx = tid; idx < 4096; idx += 256) {
        int row = idx >> 6, k4 = (idx & 63) << 2;
        float4 v = *(const float4*)(src + (b * 128 + s0 + row) * 256 + k4);
        *(float4*)(sA + row * 260 + k4) = v;
    }
    __syncthreads();

    const int arow0 = msub * 16 + g, arow1 = arow0 + 8;
    float acc[4][4], accL[4][4], accX[4][4];
#pragma unroll
    for (int i = 0; i < 4; i++)
#pragma unroll
        for (int j = 0; j < 4; j++) { acc[i][j] = 0.f; accL[i][j] = 0.f; accX[i][j] = 0.f; }

    const int nfr0 = (n0 >> 3) + nhalf * 4;
#pragma unroll 4
    for (int kk = 0; kk < 16; kk++) {
        int cb = kk * 16 + 2 * tig;
        uint32_t ah[4], al[4];
        split2(sA[arow0 * 260 + cb],     sA[arow0 * 260 + cb + 1], ah[0], al[0]);
        split2(sA[arow1 * 260 + cb],     sA[arow1 * 260 + cb + 1], ah[1], al[1]);
        split2(sA[arow0 * 260 + cb + 8], sA[arow0 * 260 + cb + 9], ah[2], al[2]);
        split2(sA[arow1 * 260 + cb + 8], sA[arow1 * 260 + cb + 9], ah[3], al[3]);
#pragma unroll
        for (int nf = 0; nf < 4; nf++) {
            uint4 bw = gWqv[((kk << 6) + nfr0 + nf) * 32 + lane];
            mma_bf16(acc[nf],  ah[0], ah[1], ah[2], ah[3], bw.x, bw.y);
            mma_bf16(accL[nf], al[0], al[1], al[2], al[3], bw.x, bw.y);
            mma_bf16(accX[nf], ah[0], ah[1], ah[2], ah[3], bw.z, bw.w);
        }
    }

#pragma unroll
    for (int nf = 0; nf < 4; nf++) {
        int n = n0 + nhalf * 32 + nf * 8 + 2 * tig;
        float v[4];
#pragma unroll
        for (int j = 0; j < 4; j++) v[j] = acc[nf][j] + accL[nf][j] + accX[nf][j];
#pragma unroll
        for (int q = 0; q < 4; q++) {
            int s = s0 + ((q >> 1) ? arow1 : arow0);
            int nn = n + (q & 1);
            float val = v[q];
            if (nn < 256) {
                if (isX1) g_qT[(b * 128 + s) * 256 + nn] = val;
                else      g_kTT[(b * 256 + nn) * 128 + s] = val;
            } else {
                int h = (nn - 256) >> 4, d = nn & 15;
                float* dst = isX1 ? g_v1 : g_v2;
                dst[((b * 16 + h) * 128 + s) * 16 + d] = val;
            }
        }
    }
}

// ---------------- K3: bf16-split MLP + folded std reduction ----------------
#define SM_MLP 81920
__global__ void __launch_bounds__(256, 2)
k_mlp(const float* __restrict__ cost) {
    extern __shared__ float smf[];
    float* sA = smf;                      // [128][36] staging; reused as sO [128][33]
    float* sq = smf + 4608;               // [256]

    const int blk = blockIdx.x;           // b*128 + r
    const int b = blk >> 7;
    const int tid = threadIdx.x;
    const int warp = tid >> 5, lane = tid & 31;
    const int g = lane >> 2, tig = lane & 3;

    sq[tid] = g_qT[(blk << 8) + tid];
    __syncthreads();

    {
        const int c = tid & 127, half = tid >> 7;
        float cv = cost[blk * 128 + c];
        const float* kb = g_kTT + b * 32768 + c;
#pragma unroll
        for (int hh = 0; hh < 8; hh++) {
            int h = half * 8 + hh;
            float a = 0.f;
#pragma unroll
            for (int d = 0; d < 16; d++)
                a += sq[h * 16 + d] * kb[(h * 16 + d) * 128];
            sA[c * 36 + 2 * h] = a * 0.25f;
            sA[c * 36 + 2 * h + 1] = cv;
        }
    }
    __syncthreads();

    const int arow0 = warp * 16 + g, arow1 = arow0 + 8;
    uint32_t Ahi[2][4], Alo[2][4];
#pragma unroll
    for (int ks2 = 0; ks2 < 2; ks2++) {
        int cb = ks2 * 16 + 2 * tig;
        split2(sA[arow0 * 36 + cb],     sA[arow0 * 36 + cb + 1], Ahi[ks2][0], Alo[ks2][0]);
        split2(sA[arow1 * 36 + cb],     sA[arow1 * 36 + cb + 1], Ahi[ks2][1], Alo[ks2][1]);
        split2(sA[arow0 * 36 + cb + 8], sA[arow0 * 36 + cb + 9], Ahi[ks2][2], Alo[ks2][2]);
        split2(sA[arow1 * 36 + cb + 8], sA[arow1 * 36 + cb + 9], Ahi[ks2][3], Alo[ks2][3]);
    }
    __syncthreads();

    float OUThh[4][4], OUTc[4][4];
#pragma unroll
    for (int i = 0; i < 4; i++)
#pragma unroll
        for (int j = 0; j < 4; j++) { OUThh[i][j] = 0.f; OUTc[i][j] = 0.f; }

    for (int chunk = 0; chunk < 8; chunk++) {
#pragma unroll
        for (int ksp = 0; ksp < 4; ksp++) {
            uint32_t ah[4], al[4];
#pragma unroll
            for (int halfn = 0; halfn < 2; halfn++) {
                int nfp = 2 * ksp + halfn;
                float hh[4] = {0.f, 0.f, 0.f, 0.f};
                float lh[4] = {0.f, 0.f, 0.f, 0.f};
                float hl[4] = {0.f, 0.f, 0.f, 0.f};
#pragma unroll
                for (int ks2 = 0; ks2 < 2; ks2++) {
                    uint4 bw = gW1p[((((chunk * 8 + nfp) * 2 + ks2)) << 5) + lane];
                    mma_bf16(hh, Ahi[ks2][0], Ahi[ks2][1], Ahi[ks2][2], Ahi[ks2][3], bw.x, bw.y);
                    mma_bf16(lh, Alo[ks2][0], Alo[ks2][1], Alo[ks2][2], Alo[ks2][3], bw.x, bw.y);
                    mma_bf16(hl, Ahi[ks2][0], Ahi[ks2][1], Ahi[ks2][2], Ahi[ks2][3], bw.z, bw.w);
                }
                float h0 = fmaxf(hh[0] + lh[0] + hl[0], 0.f);
                float h1 = fmaxf(hh[1] + lh[1] + hl[1], 0.f);
                float h2 = fmaxf(hh[2] + lh[2] + hl[2], 0.f);
                float h3 = fmaxf(hh[3] + lh[3] + hl[3], 0.f);
                split2(h0, h1, ah[2 * halfn],     al[2 * halfn]);
                split2(h2, h3, ah[2 * halfn + 1], al[2 * halfn + 1]);
            }
#pragma unroll
            for (int nf = 0; nf < 4; nf++) {
                uint4 bw = gW2p[((((chunk * 4 + ksp) * 4 + nf)) << 5) + lane];
                mma_bf16(OUThh[nf], ah[0], ah[1], ah[2], ah[3], bw.x, bw.y);
                mma_bf16(OUTc[nf],  al[0], al[1], al[2], al[3], bw.x, bw.y);
                mma_bf16(OUTc[nf],  ah[0], ah[1], ah[2], ah[3], bw.z, bw.w);
            }
        }
    }

    float* sO = smf;
#pragma unroll
    for (int nf = 0; nf < 4; nf++) {
        int col = nf * 8 + 2 * tig;
        sO[arow0 * 33 + col]     = OUThh[nf][0] + OUTc[nf][0];
        sO[arow0 * 33 + col + 1] = OUThh[nf][1] + OUTc[nf][1];
        sO[arow1 * 33 + col]     = OUThh[nf][2] + OUTc[nf][2];
        sO[arow1 * 33 + col + 1] = OUThh[nf][3] + OUTc[nf][3];
    }
    __syncthreads();

    const int r = blk & 127;
    float s1 = 0.f, q1 = 0.f, s2 = 0.f, q2 = 0.f;
    for (int i = tid; i < 2048; i += 256) {
        int h = i >> 7, cc = i & 127;
        float m1 = sO[cc * 33 + 2 * h];
        float m2 = sO[cc * 33 + 2 * h + 1];
        g_ms1[((b * 16 + h) * 128 + r) * 128 + cc] = m1;
        g_ms2[((b * 16 + h) * 128 + r) * 128 + cc] = m2;
        s1 += m1; q1 += m1 * m1; s2 += m2; q2 += m2 * m2;
    }

    float v[4] = {s1, q1, s2, q2};
#pragma unroll
    for (int i = 0; i < 4; i++)
        for (int off = 16; off; off >>= 1) v[i] += __shfl_xor_sync(0xffffffffu, v[i], off);
    __shared__ float red[4][8];
    if (lane == 0) { red[0][warp] = v[0]; red[1][warp] = v[1]; red[2][warp] = v[2]; red[3][warp] = v[3]; }
    __syncthreads();
    if (tid == 0) {
#pragma unroll
        for (int i = 0; i < 4; i++) {
            float s = 0.f;
#pragma unroll
            for (int j = 0; j < 8; j++) s += red[i][j];
            g_part[blk * 4 + i] = s;
        }
    }

    // ---- folded std reduction: last block to finish reduces g_part ----
    __shared__ unsigned slast;
    if (tid == 0) {
        __threadfence();
        slast = (atomicAdd(&g_ctr, 1u) == 1023u) ? 1u : 0u;
    }
    __syncthreads();
    if (slast) {
        __threadfence();   // acquire: make all blocks' g_part visible
        double a0 = 0, a1 = 0, a2 = 0, a3 = 0;
        for (int i = tid; i < 1024; i += 256) {
            const float* p = g_part + i * 4;
            a0 += p[0]; a1 += p[1]; a2 += p[2]; a3 += p[3];
        }
#pragma unroll
        for (int off = 16; off; off >>= 1) {
            a0 += __shfl_xor_sync(0xffffffffu, a0, off);
            a1 += __shfl_xor_sync(0xffffffffu, a1, off);
            a2 += __shfl_xor_sync(0xffffffffu, a2, off);
            a3 += __shfl_xor_sync(0xffffffffu, a3, off);
        }
        __shared__ double sh2[4][8];
        if (lane == 0) { sh2[0][warp] = a0; sh2[1][warp] = a1; sh2[2][warp] = a2; sh2[3][warp] = a3; }
        __syncthreads();
        if (tid == 0) {
            double t0 = 0, t1 = 0, t2 = 0, t3 = 0;
#pragma unroll
            for (int j = 0; j < 8; j++) { t0 += sh2[0][j]; t1 += sh2[1][j]; t2 += sh2[2][j]; t3 += sh2[3][j]; }
            const double N = 2097152.0;
            double v1 = (t1 - t0 * t0 / N) / (N - 1.0);
            double v2 = (t3 - t2 * t2 / N) / (N - 1.0);
            g_stats[0] = (float)(1.0 / sqrt(v1));
            g_stats[1] = (float)(1.0 / sqrt(v2));
        }
    }
}

// ---------------- K5: merged attention (blocks 0..255 = h1 path, 256..511 = h2 path) ----------------
#define SM_ATT (14848 * 4)
__global__ void k_attn() {
    extern __shared__ float sm[];
    const int tid = threadIdx.x;     // 256

    if (blockIdx.x < 256) {
        float* sl = sm;            // [64 r][128 c]
        float* sv = sm + 8192;     // v2 plane [128 c][16 d]
        const int blk = blockIdx.x;
        const int p = blk >> 1, rh = blk & 1;
        const float inv = g_stats[0];
        const float* mp = g_ms1 + p * 16384 + rh * 8192;
        for (int idx = tid; idx < 8192; idx += 256) sl[idx] = 10.f * fast_tanh(mp[idx] * inv);
        const float* vp = g_v2 + p * 2048;
        for (int idx = tid; idx < 2048; idx += 256) sv[idx] = vp[idx];
        __syncthreads();

        const int w = tid >> 5, lane = tid & 31;
#pragma unroll
        for (int i = 0; i < 8; i++) {
            int r = w * 8 + i;
            float* row = sl + r * 128;
            float m = fmaxf(fmaxf(row[lane], row[lane + 32]), fmaxf(row[lane + 64], row[lane + 96]));
#pragma unroll
            for (int off = 16; off; off >>= 1) m = fmaxf(m, __shfl_xor_sync(0xffffffffu, m, off));
            float s = 0.f;
#pragma unroll
            for (int t = 0; t < 4; t++) {
                int cc = lane + t * 32;
                float e = __expf(row[cc] - m);
                row[cc] = e; s += e;
            }
#pragma unroll
            for (int off = 16; off; off >>= 1) s += __shfl_xor_sync(0xffffffffu, s, off);
            float is = 1.f / s;
#pragma unroll
            for (int t = 0; t < 4; t++) row[lane + t * 32] *= is;
        }
        __syncthreads();

        const int r = tid >> 2, d0 = (tid & 3) << 2;
        float a0 = 0.f, a1 = 0.f, a2 = 0.f, a3 = 0.f;
#pragma unroll 4
        for (int cc = 0; cc < 128; cc++) {
            float wgt = sl[r * 128 + cc];
            float4 v = *(const float4*)(sv + cc * 16 + d0);
            a0 += wgt * v.x; a1 += wgt * v.y; a2 += wgt * v.z; a3 += wgt * v.w;
        }
        const int b = p >> 4, h = p & 15;
        float* out = g_attn1 + (b * 128 + rh * 64 + r) * 256 + h * 16 + d0;
        *(float4*)out = make_float4(a0, a1, a2, a3);
    } else {
        float* sl   = sm;               // [128 r][64 c]
        float* sv   = sm + 8192;        // v1 plane [128 r][16 d]
        float* pr   = sm + 10240;       // [4 seg][64 c][16 d]
        float* redm = sm + 14336;       // [4 seg][64 c]
        float* reds = sm + 14592;       // [4 seg][64 c]
        const int blk = blockIdx.x - 256;
        const int p = blk >> 1, ch = blk & 1;
        const float inv = g_stats[1];
        const float* mp = g_ms2 + p * 16384 + ch * 64;
        for (int idx = tid; idx < 8192; idx += 256)
            sl[idx] = 10.f * fast_tanh(mp[(idx >> 6) * 128 + (idx & 63)] * inv);
        const float* vp = g_v1 + p * 2048;
        for (int idx = tid; idx < 2048; idx += 256) sv[idx] = vp[idx];
        __syncthreads();

        const int c = tid & 63, seg = tid >> 6;
        float m = -1e30f;
#pragma unroll 4
        for (int i = 0; i < 32; i++) m = fmaxf(m, sl[(seg * 32 + i) * 64 + c]);
        redm[seg * 64 + c] = m;
        __syncthreads();
        m = fmaxf(fmaxf(redm[c], redm[64 + c]), fmaxf(redm[128 + c], redm[192 + c]));
        float s = 0.f;
#pragma unroll 4
        for (int i = 0; i < 32; i++) {
            int rr = seg * 32 + i;
            float e = __expf(sl[rr * 64 + c] - m);
            sl[rr * 64 + c] = e; s += e;
        }
        reds[seg * 64 + c] = s;

        float acc[16];
#pragma unroll
        for (int j = 0; j < 16; j++) acc[j] = 0.f;
#pragma unroll 2
        for (int i = 0; i < 32; i++) {
            int rr = seg * 32 + i;
            float wgt = sl[rr * 64 + c];
            const float4* v = (const float4*)(sv + rr * 16);
            float4 v0 = v[0], v1 = v[1], v2 = v[2], v3 = v[3];
            acc[0] += wgt * v0.x; acc[1] += wgt * v0.y; acc[2] += wgt * v0.z; acc[3] += wgt * v0.w;
            acc[4] += wgt * v1.x; acc[5] += wgt * v1.y; acc[6] += wgt * v1.z; acc[7] += wgt * v1.w;
            acc[8] += wgt * v2.x; acc[9] += wgt * v2.y; acc[10] += wgt * v2.z; acc[11] += wgt * v2.w;
            acc[12] += wgt * v3.x; acc[13] += wgt * v3.y; acc[14] += wgt * v3.z; acc[15] += wgt * v3.w;
        }
        float* prp = pr + (seg * 64 + c) * 16;
#pragma unroll
        for (int j = 0; j < 4; j++)
            *(float4*)(prp + j * 4) = make_float4(acc[j * 4], acc[j * 4 + 1], acc[j * 4 + 2], acc[j * 4 + 3]);
        __syncthreads();

        const int b = p >> 4, h = p & 15;
        for (int o = tid; o < 1024; o += 256) {
            int cc = o >> 4, d = o & 15;
            float v = pr[(cc) * 16 + d] + pr[(64 + cc) * 16 + d]
                    + pr[(128 + cc) * 16 + d] + pr[(192 + cc) * 16 + d];
            float stot = reds[cc] + reds[64 + cc] + reds[128 + cc] + reds[192 + cc];
            g_attn2[(b * 128 + ch * 64 + cc) * 256 + h * 16 + d] = v / stot;
        }
    }
}

// ---------------- K6: output projections (bf16-split tensor cores) ----------------
#define SM_OUT (64 * 260 * 4)
__global__ void __launch_bounds__(256)
k_out(float* __restrict__ out) {
    extern __shared__ float smo[];
    float* sA = smo;   // [64][260]
    const int m0 = blockIdx.x * 64, n0 = blockIdx.y * 64;
    const bool first = (m0 < 1024);
    const float* A = first ? g_attn1 : g_attn2;
    const int wsel = first ? 0 : 1;
    float* dst = out + (first ? 0 : 262144);
    const int mm = m0 & 1023;
    const int tid = threadIdx.x;
    const int warp = tid >> 5, lane = tid & 31;
    const int g = lane >> 2, tig = lane & 3;
    const int msub = warp >> 1, nhalf = warp & 1;

    for (int idx = tid; idx < 4096; idx += 256) {
        int row = idx >> 6, k4 = (idx & 63) << 2;
        float4 v = *(const float4*)(A + (mm + row) * 256 + k4);
        *(float4*)(sA + row * 260 + k4) = v;
    }
    __syncthreads();

    const int arow0 = msub * 16 + g, arow1 = arow0 + 8;
    float acc[4][4], accL[4][4], accX[4][4];
#pragma unroll
    for (int i = 0; i < 4; i++)
#pragma unroll
        for (int j = 0; j < 4; j++) { acc[i][j] = 0.f; accL[i][j] = 0.f; accX[i][j] = 0.f; }

    const int nfr0 = (n0 >> 3) + nhalf * 4;
    const uint4* wo = gWo[wsel];
#pragma unroll 4
    for (int kk = 0; kk < 16; kk++) {
        int cb = kk * 16 + 2 * tig;
        uint32_t ah[4], al[4];
        split2(sA[arow0 * 260 + cb],     sA[arow0 * 260 + cb + 1], ah[0], al[0]);
        split2(sA[arow1 * 260 + cb],     sA[arow1 * 260 + cb + 1], ah[1], al[1]);
        split2(sA[arow0 * 260 + cb + 8], sA[arow0 * 260 + cb + 9], ah[2], al[2]);
        split2(sA[arow1 * 260 + cb + 8], sA[arow1 * 260 + cb + 9], ah[3], al[3]);
#pragma unroll
        for (int nf = 0; nf < 4; nf++) {
            uint4 bw = wo[((kk << 5) + nfr0 + nf) * 32 + lane];
            mma_bf16(acc[nf],  ah[0], ah[1], ah[2], ah[3], bw.x, bw.y);
            mma_bf16(accL[nf], al[0], al[1], al[2], al[3], bw.x, bw.y);
            mma_bf16(accX[nf], ah[0], ah[1], ah[2], ah[3], bw.z, bw.w);
        }
    }

#pragma unroll
    for (int nf = 0; nf < 4; nf++) {
        int n = n0 + nhalf * 32 + nf * 8 + 2 * tig;
        float v0 = acc[nf][0] + accL[nf][0] + accX[nf][0];
        float v1 = acc[nf][1] + accL[nf][1] + accX[nf][1];
        float v2 = acc[nf][2] + accL[nf][2] + accX[nf][2];
        float v3 = acc[nf][3] + accL[nf][3] + accX[nf][3];
        float* o0 = dst + (mm + arow0) * 256 + n;
        float* o1 = dst + (mm + arow1) * 256 + n;
        o0[0] = v0; o0[1] = v1;
        o1[0] = v2; o1[1] = v3;
    }
}

// ---------------- launch ----------------
extern "C" void kernel_launch(void* const* d_in, const int* in_sizes, int n_in,
                              void* d_out, int out_size) {
    const float* x1   = (const float*)d_in[0];
    const float* x2   = (const float*)d_in[1];
    const float* cost = (const float*)d_in[2];
    const float* Wqv1 = (const float*)d_in[3];
    const float* lin1 = (const float*)d_in[4];
    const float* lin2 = (const float*)d_in[5];
    const float* o1w  = (const float*)d_in[6];
    const float* o2w  = (const float*)d_in[7];
    float* out = (float*)d_out;

    cudaFuncSetAttribute(k_qkv,  cudaFuncAttributeMaxDynamicSharedMemorySize, SM_QKV);
    cudaFuncSetAttribute(k_mlp,  cudaFuncAttributeMaxDynamicSharedMemorySize, SM_MLP);
    cudaFuncSetAttribute(k_attn, cudaFuncAttributeMaxDynamicSharedMemorySize, SM_ATT);
    cudaFuncSetAttribute(k_out,  cudaFuncAttributeMaxDynamicSharedMemorySize, SM_OUT);

    // 4 launches + prep; profiler slot 4 captures k_attn (first profile of it)
    k_prep<<<288, 256>>>(lin1, lin2, Wqv1, o1w, o2w);     // 1 (also resets g_ctr)
    k_qkv<<<dim3(32, 8), 256, SM_QKV>>>(x1, x2);          // 2
    k_mlp<<<1024, 256, SM_MLP>>>(cost);                   // 3 (folds std reduction)
    k_attn<<<512, 256, SM_ATT>>>();                       // 4  <- profiled
    k_out<<<dim3(32, 4), 256, SM_OUT>>>(out);             // 5

    (void)in_sizes; (void)n_in; (void)out_size;
}

// round 17
// speedup vs baseline: 2.5537x; 1.1137x over previous
#include <cuda_runtime.h>
#include <math.h>
#include <stdint.h>

typedef unsigned long long ull;

// ---------------- scratch (device globals; no allocations allowed) ----------------
__device__ float g_qT  [1024 * 256];      // [b*128+r][e]   e = h*16+d
__device__ float g_kTT [8 * 256 * 128];   // [b][e][c]
__device__ float g_v1  [1024 * 256];      // [b][h][s][d]
__device__ float g_v2  [1024 * 256];      // [b][h][s][d]
__device__ float g_ms1 [2097152];         // [b][h][r][c]
__device__ float g_ms2 [2097152];         // [b][h][r][c]
__device__ float g_attn1[1024 * 256];     // [b*128+r][h*16+d]
__device__ float g_attn2[1024 * 256];     // [b*128+c][h*16+d]
__device__ float g_part[1024 * 4];        // per-block {s1,q1,s2,q2}
__device__ float g_stats[2];              // inv_std1, inv_std2
__device__ unsigned g_ctr;                // mlp completion counter (reset by k_prep)
// bf16 hi/lo frag-packed weights: per fragment+lane uint4 {b0hi, b1hi, b0lo, b1lo}
__device__ uint4 gW1p[128 * 32];
__device__ uint4 gW2p[128 * 32];
__device__ uint4 gWqv[1024 * 32];         // Wqv1 [256][512]: frag = kstep*64 + nfr
__device__ uint4 gWo[2][512 * 32];        // o1w/o2w [256][256]: frag = kstep*32 + nfr

// ---------------- helpers ----------------
// unnormalized softmax weight of the tanh-clipped logit: exp(10*tanh(x)).
// Logits are bounded in [-10,10] so no max-subtraction is needed.
__device__ __forceinline__ float wfun(float x) {
    float E = __expf(2.f * x);
    float th = 1.f - __fdividef(2.f, E + 1.f);
    return __expf(10.f * th);
}
__device__ __forceinline__ uint32_t packbf(float fu, float fl) {
    uint32_t r; asm("cvt.rn.bf16x2.f32 %0, %1, %2;" : "=r"(r) : "f"(fu), "f"(fl));
    return r;
}
__device__ __forceinline__ void split2(float x0, float x1, uint32_t& hi, uint32_t& lo) {
    hi = packbf(x1, x0);
    float h0 = __uint_as_float(hi << 16);
    float h1 = __uint_as_float(hi & 0xffff0000u);
    lo = packbf(x1 - h1, x0 - h0);
}
__device__ __forceinline__ void mma_bf16(float* c,
                                         uint32_t a0, uint32_t a1, uint32_t a2, uint32_t a3,
                                         uint32_t b0, uint32_t b1) {
    asm volatile(
        "mma.sync.aligned.m16n8k16.row.col.f32.bf16.bf16.f32 "
        "{%0,%1,%2,%3}, {%4,%5,%6,%7}, {%8,%9}, {%0,%1,%2,%3};"
        : "+f"(c[0]), "+f"(c[1]), "+f"(c[2]), "+f"(c[3])
        : "r"(a0), "r"(a1), "r"(a2), "r"(a3), "r"(b0), "r"(b1));
}

// ---------------- K0: pack W1/W2/Wqv1/o1w/o2w into bf16 hi/lo fragment uint4s ----------------
__global__ void k_prep(const float* __restrict__ w1, const float* __restrict__ w2,
                       const float* __restrict__ wqv,
                       const float* __restrict__ o1w, const float* __restrict__ o2w) {
    int idx = blockIdx.x * 256 + threadIdx.x;   // 0..73727
    if (idx == 0) g_ctr = 0;
    if (idx < 8192) {
        int sel  = idx >> 12;
        int f    = idx & 4095;
        int lane = f & 31;
        int frag = f >> 5;            // 0..127
        int g = lane >> 2, tig = lane & 3;
        float k0, k1, k8, k9;
        if (sel == 0) {
            int ks2 = frag & 1, cn = frag >> 1;
            int n = cn * 8 + g;
            int kb = ks2 * 16 + 2 * tig;
            k0 = w1[kb * 512 + n];       k1 = w1[(kb + 1) * 512 + n];
            k8 = w1[(kb + 8) * 512 + n]; k9 = w1[(kb + 9) * 512 + n];
        } else {
            int nf = frag & 3, ck = frag >> 2;
            int n = nf * 8 + g;
            int kb = ck * 16 + 2 * tig;
            k0 = w2[kb * 32 + n];        k1 = w2[(kb + 1) * 32 + n];
            k8 = w2[(kb + 8) * 32 + n];  k9 = w2[(kb + 9) * 32 + n];
        }
        uint32_t h0, l0, h1, l1;
        split2(k0, k1, h0, l0);
        split2(k8, k9, h1, l1);
        uint4 v = make_uint4(h0, h1, l0, l1);
        if (sel == 0) gW1p[frag * 32 + lane] = v;
        else          gW2p[frag * 32 + lane] = v;
    } else if (idx < 40960) {
        int f = idx - 8192;
        int lane = f & 31;
        int frag = f >> 5;            // 0..1023: kstep*64 + nfr
        int kstep = frag >> 6, nfr = frag & 63;
        int g = lane >> 2, tig = lane & 3;
        int n = nfr * 8 + g;
        int kb = kstep * 16 + 2 * tig;
        float k0 = wqv[kb * 512 + n],       k1 = wqv[(kb + 1) * 512 + n];
        float k8 = wqv[(kb + 8) * 512 + n], k9 = wqv[(kb + 9) * 512 + n];
        uint32_t h0, l0, h1, l1;
        split2(k0, k1, h0, l0);
        split2(k8, k9, h1, l1);
        gWqv[frag * 32 + lane] = make_uint4(h0, h1, l0, l1);
    } else if (idx < 73728) {
        int f = idx - 40960;          // 0..32767
        int wsel = f >> 14;           // 0 = o1w, 1 = o2w
        int ff = f & 16383;
        int lane = ff & 31;
        int frag = ff >> 5;           // 0..511: kstep*32 + nfr
        int kstep = frag >> 5, nfr = frag & 31;
        int g = lane >> 2, tig = lane & 3;
        const float* w = wsel ? o2w : o1w;
        int n = nfr * 8 + g;
        int kb = kstep * 16 + 2 * tig;
        float k0 = w[kb * 256 + n],       k1 = w[(kb + 1) * 256 + n];
        float k8 = w[(kb + 8) * 256 + n], k9 = w[(kb + 9) * 256 + n];
        uint32_t h0, l0, h1, l1;
        split2(k0, k1, h0, l0);
        split2(k8, k9, h1, l1);
        gWo[wsel][frag * 32 + lane] = make_uint4(h0, h1, l0, l1);
    }
}

// ---------------- K1: qkv projection GEMM (bf16-split tensor cores) ----------------
#define SM_QKV (64 * 260 * 4)
__global__ void __launch_bounds__(256)
k_qkv(const float* __restrict__ x1, const float* __restrict__ x2) {
    extern __shared__ float smq[];
    float* sA = smq;   // [64][260]
    const int m0 = blockIdx.x * 64, n0 = blockIdx.y * 64;
    const bool isX1 = (m0 < 1024);
    const float* src = isX1 ? x1 : x2;
    const int mm = m0 & 1023;
    const int b = mm >> 7, s0 = mm & 127;
    const int tid = threadIdx.x;
    const int warp = tid >> 5, lane = tid & 31;
    const int g = lane >> 2, tig = lane & 3;
    const int msub = warp >> 1, nhalf = warp & 1;

    for (int idx = tid; idx < 4096; idx += 256) {
        int row = idx >> 6, k4 = (idx & 63) << 2;
        float4 v = *(const float4*)(src + (b * 128 + s0 + row) * 256 + k4);
        *(float4*)(sA + row * 260 + k4) = v;
    }
    __syncthreads();

    const int arow0 = msub * 16 + g, arow1 = arow0 + 8;
    float acc[4][4], accL[4][4], accX[4][4];
#pragma unroll
    for (int i = 0; i < 4; i++)
#pragma unroll
        for (int j = 0; j < 4; j++) { acc[i][j] = 0.f; accL[i][j] = 0.f; accX[i][j] = 0.f; }

    const int nfr0 = (n0 >> 3) + nhalf * 4;
#pragma unroll 4
    for (int kk = 0; kk < 16; kk++) {
        int cb = kk * 16 + 2 * tig;
        uint32_t ah[4], al[4];
        split2(sA[arow0 * 260 + cb],     sA[arow0 * 260 + cb + 1], ah[0], al[0]);
        split2(sA[arow1 * 260 + cb],     sA[arow1 * 260 + cb + 1], ah[1], al[1]);
        split2(sA[arow0 * 260 + cb + 8], sA[arow0 * 260 + cb + 9], ah[2], al[2]);
        split2(sA[arow1 * 260 + cb + 8], sA[arow1 * 260 + cb + 9], ah[3], al[3]);
#pragma unroll
        for (int nf = 0; nf < 4; nf++) {
            uint4 bw = gWqv[((kk << 6) + nfr0 + nf) * 32 + lane];
            mma_bf16(acc[nf],  ah[0], ah[1], ah[2], ah[3], bw.x, bw.y);
            mma_bf16(accL[nf], al[0], al[1], al[2], al[3], bw.x, bw.y);
            mma_bf16(accX[nf], ah[0], ah[1], ah[2], ah[3], bw.z, bw.w);
        }
    }

#pragma unroll
    for (int nf = 0; nf < 4; nf++) {
        int n = n0 + nhalf * 32 + nf * 8 + 2 * tig;
        float v[4];
#pragma unroll
        for (int j = 0; j < 4; j++) v[j] = acc[nf][j] + accL[nf][j] + accX[nf][j];
#pragma unroll
        for (int q = 0; q < 4; q++) {
            int s = s0 + ((q >> 1) ? arow1 : arow0);
            int nn = n + (q & 1);
            float val = v[q];
            if (nn < 256) {
                if (isX1) g_qT[(b * 128 + s) * 256 + nn] = val;
                else      g_kTT[(b * 256 + nn) * 128 + s] = val;
            } else {
                int h = (nn - 256) >> 4, d = nn & 15;
                float* dst = isX1 ? g_v1 : g_v2;
                dst[((b * 16 + h) * 128 + s) * 16 + d] = val;
            }
        }
    }
}

// ---------------- K3: bf16-split MLP + folded std reduction ----------------
#define SM_MLP 81920
__global__ void __launch_bounds__(256, 2)
k_mlp(const float* __restrict__ cost) {
    extern __shared__ float smf[];
    float* sA = smf;                      // [128][36] staging; reused as sO [128][33]
    float* sq = smf + 4608;               // [256]

    const int blk = blockIdx.x;           // b*128 + r
    const int b = blk >> 7;
    const int tid = threadIdx.x;
    const int warp = tid >> 5, lane = tid & 31;
    const int g = lane >> 2, tig = lane & 3;

    sq[tid] = g_qT[(blk << 8) + tid];
    __syncthreads();

    {
        const int c = tid & 127, half = tid >> 7;
        float cv = cost[blk * 128 + c];
        const float* kb = g_kTT + b * 32768 + c;
#pragma unroll
        for (int hh = 0; hh < 8; hh++) {
            int h = half * 8 + hh;
            float a = 0.f;
#pragma unroll
            for (int d = 0; d < 16; d++)
                a += sq[h * 16 + d] * kb[(h * 16 + d) * 128];
            sA[c * 36 + 2 * h] = a * 0.25f;
            sA[c * 36 + 2 * h + 1] = cv;
        }
    }
    __syncthreads();

    const int arow0 = warp * 16 + g, arow1 = arow0 + 8;
    uint32_t Ahi[2][4], Alo[2][4];
#pragma unroll
    for (int ks2 = 0; ks2 < 2; ks2++) {
        int cb = ks2 * 16 + 2 * tig;
        split2(sA[arow0 * 36 + cb],     sA[arow0 * 36 + cb + 1], Ahi[ks2][0], Alo[ks2][0]);
        split2(sA[arow1 * 36 + cb],     sA[arow1 * 36 + cb + 1], Ahi[ks2][1], Alo[ks2][1]);
        split2(sA[arow0 * 36 + cb + 8], sA[arow0 * 36 + cb + 9], Ahi[ks2][2], Alo[ks2][2]);
        split2(sA[arow1 * 36 + cb + 8], sA[arow1 * 36 + cb + 9], Ahi[ks2][3], Alo[ks2][3]);
    }
    __syncthreads();

    float OUThh[4][4], OUTc[4][4];
#pragma unroll
    for (int i = 0; i < 4; i++)
#pragma unroll
        for (int j = 0; j < 4; j++) { OUThh[i][j] = 0.f; OUTc[i][j] = 0.f; }

    for (int chunk = 0; chunk < 8; chunk++) {
#pragma unroll
        for (int ksp = 0; ksp < 4; ksp++) {
            uint32_t ah[4], al[4];
#pragma unroll
            for (int halfn = 0; halfn < 2; halfn++) {
                int nfp = 2 * ksp + halfn;
                float hh[4] = {0.f, 0.f, 0.f, 0.f};
                float lh[4] = {0.f, 0.f, 0.f, 0.f};
                float hl[4] = {0.f, 0.f, 0.f, 0.f};
#pragma unroll
                for (int ks2 = 0; ks2 < 2; ks2++) {
                    uint4 bw = gW1p[((((chunk * 8 + nfp) * 2 + ks2)) << 5) + lane];
                    mma_bf16(hh, Ahi[ks2][0], Ahi[ks2][1], Ahi[ks2][2], Ahi[ks2][3], bw.x, bw.y);
                    mma_bf16(lh, Alo[ks2][0], Alo[ks2][1], Alo[ks2][2], Alo[ks2][3], bw.x, bw.y);
                    mma_bf16(hl, Ahi[ks2][0], Ahi[ks2][1], Ahi[ks2][2], Ahi[ks2][3], bw.z, bw.w);
                }
                float h0 = fmaxf(hh[0] + lh[0] + hl[0], 0.f);
                float h1 = fmaxf(hh[1] + lh[1] + hl[1], 0.f);
                float h2 = fmaxf(hh[2] + lh[2] + hl[2], 0.f);
                float h3 = fmaxf(hh[3] + lh[3] + hl[3], 0.f);
                split2(h0, h1, ah[2 * halfn],     al[2 * halfn]);
                split2(h2, h3, ah[2 * halfn + 1], al[2 * halfn + 1]);
            }
#pragma unroll
            for (int nf = 0; nf < 4; nf++) {
                uint4 bw = gW2p[((((chunk * 4 + ksp) * 4 + nf)) << 5) + lane];
                mma_bf16(OUThh[nf], ah[0], ah[1], ah[2], ah[3], bw.x, bw.y);
                mma_bf16(OUTc[nf],  al[0], al[1], al[2], al[3], bw.x, bw.y);
                mma_bf16(OUTc[nf],  ah[0], ah[1], ah[2], ah[3], bw.z, bw.w);
            }
        }
    }

    float* sO = smf;
#pragma unroll
    for (int nf = 0; nf < 4; nf++) {
        int col = nf * 8 + 2 * tig;
        sO[arow0 * 33 + col]     = OUThh[nf][0] + OUTc[nf][0];
        sO[arow0 * 33 + col + 1] = OUThh[nf][1] + OUTc[nf][1];
        sO[arow1 * 33 + col]     = OUThh[nf][2] + OUTc[nf][2];
        sO[arow1 * 33 + col + 1] = OUThh[nf][3] + OUTc[nf][3];
    }
    __syncthreads();

    const int r = blk & 127;
    float s1 = 0.f, q1 = 0.f, s2 = 0.f, q2 = 0.f;
    for (int i = tid; i < 2048; i += 256) {
        int h = i >> 7, cc = i & 127;
        float m1 = sO[cc * 33 + 2 * h];
        float m2 = sO[cc * 33 + 2 * h + 1];
        g_ms1[((b * 16 + h) * 128 + r) * 128 + cc] = m1;
        g_ms2[((b * 16 + h) * 128 + r) * 128 + cc] = m2;
        s1 += m1; q1 += m1 * m1; s2 += m2; q2 += m2 * m2;
    }

    float v[4] = {s1, q1, s2, q2};
#pragma unroll
    for (int i = 0; i < 4; i++)
        for (int off = 16; off; off >>= 1) v[i] += __shfl_xor_sync(0xffffffffu, v[i], off);
    __shared__ float red[4][8];
    if (lane == 0) { red[0][warp] = v[0]; red[1][warp] = v[1]; red[2][warp] = v[2]; red[3][warp] = v[3]; }
    __syncthreads();
    if (tid == 0) {
#pragma unroll
        for (int i = 0; i < 4; i++) {
            float s = 0.f;
#pragma unroll
            for (int j = 0; j < 8; j++) s += red[i][j];
            g_part[blk * 4 + i] = s;
        }
    }

    // ---- folded std reduction: last block to finish reduces g_part ----
    __shared__ unsigned slast;
    if (tid == 0) {
        __threadfence();
        slast = (atomicAdd(&g_ctr, 1u) == 1023u) ? 1u : 0u;
    }
    __syncthreads();
    if (slast) {
        __threadfence();   // acquire: make all blocks' g_part visible
        double a0 = 0, a1 = 0, a2 = 0, a3 = 0;
        for (int i = tid; i < 1024; i += 256) {
            const float* p = g_part + i * 4;
            a0 += p[0]; a1 += p[1]; a2 += p[2]; a3 += p[3];
        }
#pragma unroll
        for (int off = 16; off; off >>= 1) {
            a0 += __shfl_xor_sync(0xffffffffu, a0, off);
            a1 += __shfl_xor_sync(0xffffffffu, a1, off);
            a2 += __shfl_xor_sync(0xffffffffu, a2, off);
            a3 += __shfl_xor_sync(0xffffffffu, a3, off);
        }
        __shared__ double sh2[4][8];
        if (lane == 0) { sh2[0][warp] = a0; sh2[1][warp] = a1; sh2[2][warp] = a2; sh2[3][warp] = a3; }
        __syncthreads();
        if (tid == 0) {
            double t0 = 0, t1 = 0, t2 = 0, t3 = 0;
#pragma unroll
            for (int j = 0; j < 8; j++) { t0 += sh2[0][j]; t1 += sh2[1][j]; t2 += sh2[2][j]; t3 += sh2[3][j]; }
            const double N = 2097152.0;
            double v1 = (t1 - t0 * t0 / N) / (N - 1.0);
            double v2 = (t3 - t2 * t2 / N) / (N - 1.0);
            g_stats[0] = (float)(1.0 / sqrt(v1));
            g_stats[1] = (float)(1.0 / sqrt(v2));
        }
    }
}

// ---------------- K5: merged attention, single-pass unnormalized-weight form ----------------
// Logits are tanh-clipped to [-10,10] so exp() needs no max subtraction.
// sl holds unnormalized weights; AV accumulates sum(w*v) and sum(w); divide once.
#define SM_ATT (14592 * 4)
__global__ void k_attn() {
    extern __shared__ float sm[];
    const int tid = threadIdx.x;     // 256

    if (blockIdx.x < 256) {
        // ---- h1: weights over c ----
        float* sl = sm;            // [64 r][128 c] unnormalized weights
        float* sv = sm + 8192;     // v2 plane [128 c][16 d]
        const int blk = blockIdx.x;
        const int p = blk >> 1, rh = blk & 1;
        const float inv = g_stats[0];
        const float* mp = g_ms1 + p * 16384 + rh * 8192;
        for (int idx = tid; idx < 8192; idx += 256) sl[idx] = wfun(mp[idx] * inv);
        const float* vp = g_v2 + p * 2048;
        for (int idx = tid; idx < 2048; idx += 256) sv[idx] = vp[idx];
        __syncthreads();

        const int r = tid >> 2, d0 = (tid & 3) << 2;
        float a0 = 0.f, a1 = 0.f, a2 = 0.f, a3 = 0.f, ws = 0.f;
#pragma unroll 4
        for (int cc = 0; cc < 128; cc++) {
            float wgt = sl[r * 128 + cc];
            float4 v = *(const float4*)(sv + cc * 16 + d0);
            a0 += wgt * v.x; a1 += wgt * v.y; a2 += wgt * v.z; a3 += wgt * v.w;
            ws += wgt;
        }
        float is = __fdividef(1.f, ws);
        const int b = p >> 4, h = p & 15;
        float* out = g_attn1 + (b * 128 + rh * 64 + r) * 256 + h * 16 + d0;
        *(float4*)out = make_float4(a0 * is, a1 * is, a2 * is, a3 * is);
    } else {
        // ---- h2: weights over r (logits transposed) ----
        float* sl   = sm;               // [128 r][64 c] unnormalized weights
        float* sv   = sm + 8192;        // v1 plane [128 r][16 d]
        float* pr   = sm + 10240;       // [4 seg][64 c][16 d]
        float* reds = sm + 14336;       // [4 seg][64 c]
        const int blk = blockIdx.x - 256;
        const int p = blk >> 1, ch = blk & 1;
        const float inv = g_stats[1];
        const float* mp = g_ms2 + p * 16384 + ch * 64;
        for (int idx = tid; idx < 8192; idx += 256)
            sl[idx] = wfun(mp[(idx >> 6) * 128 + (idx & 63)] * inv);
        const float* vp = g_v1 + p * 2048;
        for (int idx = tid; idx < 2048; idx += 256) sv[idx] = vp[idx];
        __syncthreads();

        const int c = tid & 63, seg = tid >> 6;   // seg owns rows [seg*32, seg*32+32)
        float s = 0.f;
        float acc[16];
#pragma unroll
        for (int j = 0; j < 16; j++) acc[j] = 0.f;
#pragma unroll 2
        for (int i = 0; i < 32; i++) {
            int rr = seg * 32 + i;
            float wgt = sl[rr * 64 + c];
            s += wgt;
            const float4* v = (const float4*)(sv + rr * 16);
            float4 v0 = v[0], v1 = v[1], v2 = v[2], v3 = v[3];
            acc[0] += wgt * v0.x; acc[1] += wgt * v0.y; acc[2] += wgt * v0.z; acc[3] += wgt * v0.w;
            acc[4] += wgt * v1.x; acc[5] += wgt * v1.y; acc[6] += wgt * v1.z; acc[7] += wgt * v1.w;
            acc[8] += wgt * v2.x; acc[9] += wgt * v2.y; acc[10] += wgt * v2.z; acc[11] += wgt * v2.w;
            acc[12] += wgt * v3.x; acc[13] += wgt * v3.y; acc[14] += wgt * v3.z; acc[15] += wgt * v3.w;
        }
        reds[seg * 64 + c] = s;
        float* prp = pr + (seg * 64 + c) * 16;
#pragma unroll
        for (int j = 0; j < 4; j++)
            *(float4*)(prp + j * 4) = make_float4(acc[j * 4], acc[j * 4 + 1], acc[j * 4 + 2], acc[j * 4 + 3]);
        __syncthreads();

        const int b = p >> 4, h = p & 15;
        for (int o = tid; o < 1024; o += 256) {
            int cc = o >> 4, d = o & 15;
            float v = pr[(cc) * 16 + d] + pr[(64 + cc) * 16 + d]
                    + pr[(128 + cc) * 16 + d] + pr[(192 + cc) * 16 + d];
            float stot = reds[cc] + reds[64 + cc] + reds[128 + cc] + reds[192 + cc];
            g_attn2[(b * 128 + ch * 64 + cc) * 256 + h * 16 + d] = v * __fdividef(1.f, stot);
        }
    }
}

// ---------------- K6: output projections (bf16-split tensor cores) ----------------
#define SM_OUT (64 * 260 * 4)
__global__ void __launch_bounds__(256)
k_out(float* __restrict__ out) {
    extern __shared__ float smo[];
    float* sA = smo;   // [64][260]
    const int m0 = blockIdx.x * 64, n0 = blockIdx.y * 64;
    const bool first = (m0 < 1024);
    const float* A = first ? g_attn1 : g_attn2;
    const int wsel = first ? 0 : 1;
    float* dst = out + (first ? 0 : 262144);
    const int mm = m0 & 1023;
    const int tid = threadIdx.x;
    const int warp = tid >> 5, lane = tid & 31;
    const int g = lane >> 2, tig = lane & 3;
    const int msub = warp >> 1, nhalf = warp & 1;

    for (int idx = tid; idx < 4096; idx += 256) {
        int row = idx >> 6, k4 = (idx & 63) << 2;
        float4 v = *(const float4*)(A + (mm + row) * 256 + k4);
        *(float4*)(sA + row * 260 + k4) = v;
    }
    __syncthreads();

    const int arow0 = msub * 16 + g, arow1 = arow0 + 8;
    float acc[4][4], accL[4][4], accX[4][4];
#pragma unroll
    for (int i = 0; i < 4; i++)
#pragma unroll
        for (int j = 0; j < 4; j++) { acc[i][j] = 0.f; accL[i][j] = 0.f; accX[i][j] = 0.f; }

    const int nfr0 = (n0 >> 3) + nhalf * 4;
    const uint4* wo = gWo[wsel];
#pragma unroll 4
    for (int kk = 0; kk < 16; kk++) {
        int cb = kk * 16 + 2 * tig;
        uint32_t ah[4], al[4];
        split2(sA[arow0 * 260 + cb],     sA[arow0 * 260 + cb + 1], ah[0], al[0]);
        split2(sA[arow1 * 260 + cb],     sA[arow1 * 260 + cb + 1], ah[1], al[1]);
        split2(sA[arow0 * 260 + cb + 8], sA[arow0 * 260 + cb + 9], ah[2], al[2]);
        split2(sA[arow1 * 260 + cb + 8], sA[arow1 * 260 + cb + 9], ah[3], al[3]);
#pragma unroll
        for (int nf = 0; nf < 4; nf++) {
            uint4 bw = wo[((kk << 5) + nfr0 + nf) * 32 + lane];
            mma_bf16(acc[nf],  ah[0], ah[1], ah[2], ah[3], bw.x, bw.y);
            mma_bf16(accL[nf], al[0], al[1], al[2], al[3], bw.x, bw.y);
            mma_bf16(accX[nf], ah[0], ah[1], ah[2], ah[3], bw.z, bw.w);
        }
    }

#pragma unroll
    for (int nf = 0; nf < 4; nf++) {
        int n = n0 + nhalf * 32 + nf * 8 + 2 * tig;
        float v0 = acc[nf][0] + accL[nf][0] + accX[nf][0];
        float v1 = acc[nf][1] + accL[nf][1] + accX[nf][1];
        float v2 = acc[nf][2] + accL[nf][2] + accX[nf][2];
        float v3 = acc[nf][3] + accL[nf][3] + accX[nf][3];
        float* o0 = dst + (mm + arow0) * 256 + n;
        float* o1 = dst + (mm + arow1) * 256 + n;
        o0[0] = v0; o0[1] = v1;
        o1[0] = v2; o1[1] = v3;
    }
}

// ---------------- launch ----------------
extern "C" void kernel_launch(void* const* d_in, const int* in_sizes, int n_in,
                              void* d_out, int out_size) {
    const float* x1   = (const float*)d_in[0];
    const float* x2   = (const float*)d_in[1];
    const float* cost = (const float*)d_in[2];
    const float* Wqv1 = (const float*)d_in[3];
    const float* lin1 = (const float*)d_in[4];
    const float* lin2 = (const float*)d_in[5];
    const float* o1w  = (const float*)d_in[6];
    const float* o2w  = (const float*)d_in[7];
    float* out = (float*)d_out;

    cudaFuncSetAttribute(k_qkv,  cudaFuncAttributeMaxDynamicSharedMemorySize, SM_QKV);
    cudaFuncSetAttribute(k_mlp,  cudaFuncAttributeMaxDynamicSharedMemorySize, SM_MLP);
    cudaFuncSetAttribute(k_attn, cudaFuncAttributeMaxDynamicSharedMemorySize, SM_ATT);
    cudaFuncSetAttribute(k_out,  cudaFuncAttributeMaxDynamicSharedMemorySize, SM_OUT);

    // profiler slot 4 captures the single-pass k_attn
    k_prep<<<288, 256>>>(lin1, lin2, Wqv1, o1w, o2w);     // 1 (also resets g_ctr)
    k_qkv<<<dim3(32, 8), 256, SM_QKV>>>(x1, x2);          // 2
    k_mlp<<<1024, 256, SM_MLP>>>(cost);                   // 3 (folds std reduction)
    k_attn<<<512, 256, SM_ATT>>>();                       // 4  <- profiled
    k_out<<<dim3(32, 4), 256, SM_OUT>>>(out);             // 5

    (void)in_sizes; (void)n_in; (void)out_size;
}